// round 2
// baseline (speedup 1.0000x reference)
#include <cuda_runtime.h>
#include <math.h>

// ---------------- problem constants ----------------
#define Bq   4
#define Lq   1024
#define Dq   768
#define Hq   12
#define BSq  64
#define Mq   48
#define NEq  24
#define Pq   552      // NE*(NE-1)
#define Eq   576      // P + NE self loops
#define Rq   97
#define NPq  (Bq*Pq)  // 2208

// ---------------- scratch (device globals; no allocation) ----------------
__device__ float g_entity [Bq*NEq*Dq];
__device__ float g_cur    [Bq*Hq*NEq*Lq];
__device__ float g_ca     [Bq*Pq*Lq];
__device__ float g_ci     [NPq*Dq];
__device__ float g_X1     [NPq*2*Dq];
__device__ float g_X2     [NPq*2*Dq];
__device__ float g_bh     [NPq*Dq];
__device__ float g_bt     [NPq*Dq];
__device__ int   g_mask   [NPq];
__device__ float g_Ni     [Bq*NEq*Dq];
__device__ float g_Nj     [Bq*NEq*Dq];
__device__ float g_Hs     [Bq*NEq*Dq];
__device__ float g_EfW    [NPq*Dq];
__device__ float g_f      [Bq*Eq*Dq];
__device__ float g_score  [Bq*Eq*Hq];
__device__ float g_alpha  [Bq*Eq*Hq];
__device__ float g_nout   [Bq*NEq*Dq];
__device__ float g_newci  [NPq*Dq];
__device__ float g_relpart[(size_t)Hq*NPq*Rq];
__device__ int   g_inc    [NEq*23];

// ---------------- kernels ----------------

// entity[b,n,d] = log( sum_m em[b,n,m] * exp(ctx[b, mm[b,m], d]) )
__global__ void k_entity(const float* __restrict__ ctx, const int* __restrict__ mm,
                         const float* __restrict__ em, float* __restrict__ out)
{
    int bn = blockIdx.x; int b = bn / NEq, n = bn % NEq;
    __shared__ float w_s[Mq]; __shared__ int mi_s[Mq];
    if (threadIdx.x < Mq) {
        w_s[threadIdx.x]  = em[(b*NEq + n)*Mq + threadIdx.x];
        mi_s[threadIdx.x] = mm[b*Mq + threadIdx.x];
    }
    __syncthreads();
    for (int d = threadIdx.x; d < Dq; d += blockDim.x) {
        float s = 0.f;
        #pragma unroll 4
        for (int m = 0; m < Mq; m++) {
            float w = w_s[m];
            if (w != 0.f) s += w * expf(ctx[((long)b*Lq + mi_s[m])*Dq + d]);
        }
        out[(long)bn*Dq + d] = logf(s);
    }
}

// cur[b,h,n,l] = (1/cnt) * sum_m em * attention[b,h,mm[b,m],l]
__global__ void k_cur(const float* __restrict__ att, const int* __restrict__ mm,
                      const float* __restrict__ em, float* __restrict__ cur)
{
    int id = blockIdx.x;
    int n = id % NEq; int h = (id / NEq) % Hq; int b = id / (NEq*Hq);
    __shared__ int   act_m[Mq];
    __shared__ float act_w[Mq];
    __shared__ int   nact;
    __shared__ float invc;
    if (threadIdx.x == 0) {
        int c = 0; float cnt = 0.f;
        for (int m = 0; m < Mq; m++) {
            float w = em[(b*NEq + n)*Mq + m]; cnt += w;
            if (w != 0.f) { act_m[c] = mm[b*Mq + m]; act_w[c] = w; c++; }
        }
        nact = c; invc = 1.f / (cnt + 1e-20f);
    }
    __syncthreads();
    const float* abase = att + ((long)(b*Hq + h))*Lq*Lq;
    float* obase = cur + (long)id*Lq;
    int na = nact; float iv = invc;
    for (int l = threadIdx.x; l < Lq; l += blockDim.x) {
        float s = 0.f;
        for (int a = 0; a < na; a++) s += act_w[a] * abase[(long)act_m[a]*Lq + l];
        obase[l] = s * iv;
    }
}

// ca[b,p,l] = sum_h cur[b,h,h0,l]*cur[b,h,h1,l]; normalized over l
__global__ void k_ca(const float* __restrict__ cur, const int* __restrict__ hts,
                     float* __restrict__ ca)
{
    int bp = blockIdx.x; int b = bp / Pq, p = bp % Pq;
    int h0 = hts[p], h1 = hts[Pq + p];
    const float* c0 = cur + ((long)b*Hq*NEq + h0)*Lq;
    const float* c1 = cur + ((long)b*Hq*NEq + h1)*Lq;
    float v[4]; float local = 0.f;
    #pragma unroll
    for (int q = 0; q < 4; q++) {
        int l = threadIdx.x + q*256;
        float s = 0.f;
        #pragma unroll
        for (int h = 0; h < Hq; h++)
            s += c0[(long)h*NEq*Lq + l] * c1[(long)h*NEq*Lq + l];
        v[q] = s; local += s;
    }
    __shared__ float red[256];
    red[threadIdx.x] = local; __syncthreads();
    for (int off = 128; off > 0; off >>= 1) {
        if (threadIdx.x < off) red[threadIdx.x] += red[threadIdx.x + off];
        __syncthreads();
    }
    float inv = 1.f / (red[0] + 1e-20f);
    float* o = ca + (long)bp*Lq;
    #pragma unroll
    for (int q = 0; q < 4; q++) o[threadIdx.x + q*256] = v[q]*inv;
}

// generic SGEMM: C = act(A[M,K] @ B[K,N] + bias), row-major, batched via z
__global__ void k_sgemm(const float* __restrict__ A, const float* __restrict__ Bm,
                        const float* __restrict__ bias, float* __restrict__ C,
                        int M, int K, int N, long sA, long sB, long sC, int act)
{
    A  += (long)blockIdx.z * sA;
    Bm += (long)blockIdx.z * sB;
    C  += (long)blockIdx.z * sC;
    __shared__ float As[16][64];
    __shared__ float Bs[16][64];
    int tid = threadIdx.x;
    int tx = tid & 15, ty = tid >> 4;
    int row0 = blockIdx.y * 64;
    int col0 = blockIdx.x * 64;
    float acc[4][4] = {};
    int a_r = tid >> 2;
    int a_c = (tid & 3) << 2;
    int b_k = tid >> 4;
    int b_c = (tid & 15) << 2;
    for (int k0 = 0; k0 < K; k0 += 16) {
        float4 av = make_float4(0.f, 0.f, 0.f, 0.f);
        int gr = row0 + a_r;
        if (gr < M) av = *(const float4*)(A + (long)gr*K + k0 + a_c);
        As[a_c+0][a_r] = av.x; As[a_c+1][a_r] = av.y;
        As[a_c+2][a_r] = av.z; As[a_c+3][a_r] = av.w;
        *(float4*)&Bs[b_k][b_c] = *(const float4*)(Bm + (long)(k0 + b_k)*N + col0 + b_c);
        __syncthreads();
        #pragma unroll
        for (int kk = 0; kk < 16; kk++) {
            float4 af = *(const float4*)&As[kk][ty << 2];
            float4 bf = *(const float4*)&Bs[kk][tx << 2];
            float aa[4] = {af.x, af.y, af.z, af.w};
            float bb[4] = {bf.x, bf.y, bf.z, bf.w};
            #pragma unroll
            for (int i = 0; i < 4; i++)
                #pragma unroll
                for (int j = 0; j < 4; j++)
                    acc[i][j] += aa[i]*bb[j];
        }
        __syncthreads();
    }
    #pragma unroll
    for (int i = 0; i < 4; i++) {
        int r = row0 + (ty << 2) + i;
        if (r >= M) continue;
        #pragma unroll
        for (int j = 0; j < 4; j++) {
            int c = col0 + (tx << 2) + j;
            float v = acc[i][j];
            if (bias) v += bias[c];
            if (act) v = tanhf(v);
            C[(long)r*N + c] = v;
        }
    }
}

// X1[n] = [feat[b,h0[p]] | ciX[n]], X2[n] = [feat[b,h1[p]] | ciX[n]]
__global__ void k_concat(const float* __restrict__ feat, const int* __restrict__ hts,
                         const float* __restrict__ ciX,
                         float* __restrict__ X1, float* __restrict__ X2)
{
    long idx = (long)blockIdx.x*256 + threadIdx.x;  // over NP*D
    int d = (int)(idx % Dq); long n = idx / Dq;
    int b = (int)(n / Pq), p = (int)(n % Pq);
    float cv = ciX[n*Dq + d];
    X1[n*2*Dq + d]      = feat[((long)b*NEq + hts[p])*Dq + d];
    X1[n*2*Dq + Dq + d] = cv;
    X2[n*2*Dq + d]      = feat[((long)b*NEq + hts[Pq + p])*Dq + d];
    X2[n*2*Dq + Dq + d] = cv;
}

// group bilinear, O=2: out[n,o] = sum_{h,i,j} a[n,h,i] c[n,h,j] W[h*4096+i*64+j, o]
__global__ void k_gbl_bin(const float* __restrict__ A, const float* __restrict__ C,
                          const float* __restrict__ W, const float* __restrict__ bias,
                          float* __restrict__ out, int* __restrict__ mask)
{
    int n = blockIdx.x;
    __shared__ float a_s[Dq], c_s[Dq];
    for (int d = threadIdx.x; d < Dq; d += 256) {
        a_s[d] = A[(long)n*Dq + d];
        c_s[d] = C[(long)n*Dq + d];
    }
    __syncthreads();
    float s0 = 0.f, s1 = 0.f;
    for (int hi = threadIdx.x; hi < Dq; hi += 256) {
        float ai = a_s[hi];
        const float2* w2 = (const float2*)(W + (long)hi*BSq*2);
        const float* cc = c_s + (hi & ~63);
        #pragma unroll 8
        for (int j = 0; j < BSq; j++) {
            float v = ai * cc[j];
            float2 ww = w2[j];
            s0 += v*ww.x; s1 += v*ww.y;
        }
    }
    __shared__ float r0[256], r1[256];
    r0[threadIdx.x] = s0; r1[threadIdx.x] = s1; __syncthreads();
    for (int off = 128; off > 0; off >>= 1) {
        if (threadIdx.x < off) { r0[threadIdx.x] += r0[threadIdx.x+off]; r1[threadIdx.x] += r1[threadIdx.x+off]; }
        __syncthreads();
    }
    if (threadIdx.x == 0) {
        float b0 = r0[0] + bias[0], b1 = r1[0] + bias[1];
        out[n*2]   = b0;
        out[n*2+1] = b1;
        mask[n] = (b1 > b0) ? 1 : 0;   // argmax==1 (ties -> 0)
    }
}

// incoming-edge lists per dst (same for all batches)
__global__ void k_inc(const int* __restrict__ hts, int* __restrict__ inc)
{
    if (threadIdx.x == 0 && blockIdx.x == 0) {
        int cnt[NEq];
        for (int i = 0; i < NEq; i++) cnt[i] = 0;
        for (int p = 0; p < Pq; p++) {
            int d = hts[Pq + p];
            inc[d*23 + cnt[d]++] = p;
        }
    }
}

// f[b,e,:] = Ni[b,src] + Nj[b,dst] + (e<P ? EfW[b,e] : 0) + egat_b
__global__ void k_f(const float* __restrict__ Ni, const float* __restrict__ Nj,
                    const float* __restrict__ EfW, const float* __restrict__ eb,
                    const int* __restrict__ hts, float* __restrict__ f)
{
    int be = blockIdx.x; int b = be / Eq, e = be % Eq;
    int src, dst; const float* ef = 0;
    if (e < Pq) { src = hts[e]; dst = hts[Pq + e]; ef = EfW + ((long)b*Pq + e)*Dq; }
    else        { src = dst = e - Pq; }
    const float* ni = Ni + ((long)b*NEq + src)*Dq;
    const float* nj = Nj + ((long)b*NEq + dst)*Dq;
    float* o = f + (long)be*Dq;
    for (int d = threadIdx.x; d < Dq; d += blockDim.x) {
        float v = ni[d] + nj[d] + eb[d];
        if (ef) v += ef[d];
        o[d] = v;
    }
}

// score[b,e,h] = masked( sum_i leaky_relu(f)*attn_p )
__global__ void k_score(const float* __restrict__ f, const float* __restrict__ attn_p,
                        const int* __restrict__ mask, float* __restrict__ score)
{
    int be = blockIdx.x; int b = be / Eq, e = be % Eq;
    int h = threadIdx.x >> 5, lane = threadIdx.x & 31;
    const float* fr = f + (long)be*Dq + h*BSq;
    float s = 0.f;
    #pragma unroll
    for (int i = lane; i < BSq; i += 32) {
        float x = fr[i];
        float lr = x > 0.f ? x : 0.2f*x;
        s += lr * attn_p[h*BSq + i];
    }
    #pragma unroll
    for (int off = 16; off; off >>= 1) s += __shfl_xor_sync(0xffffffffu, s, off);
    if (lane == 0) {
        int m = (e < Pq) ? mask[b*Pq + e] : 1;
        score[(long)be*Hq + h] = m ? s : -1e30f;
    }
}

// per-dst edge softmax (24 incoming per node: 23 real + self loop)
__global__ void k_soft(const float* __restrict__ score, const int* __restrict__ inc,
                       const int* __restrict__ mask, float* __restrict__ alpha)
{
    int bn = blockIdx.x; int b = bn / NEq, n = bn % NEq;
    int h = threadIdx.x >> 5, lane = threadIdx.x & 31;
    int eid = 0; float sc = -INFINITY; float m = 0.f;
    if (lane < 24) {
        eid = (lane < 23) ? inc[n*23 + lane] : (Pq + n);
        sc  = score[((long)b*Eq + eid)*Hq + h];
        m   = (eid < Pq) ? (float)mask[b*Pq + eid] : 1.f;
    }
    float mx = sc;
    #pragma unroll
    for (int off = 16; off; off >>= 1) mx = fmaxf(mx, __shfl_xor_sync(0xffffffffu, mx, off));
    float ex = (lane < 24) ? expf(sc - mx)*m : 0.f;
    float den = ex;
    #pragma unroll
    for (int off = 16; off; off >>= 1) den += __shfl_xor_sync(0xffffffffu, den, off);
    if (lane < 24) alpha[((long)b*Eq + eid)*Hq + h] = ex / (den + 1e-20f);
}

// nout[b,n,d] = sum over incoming edges alpha[e, d/64] * Hsrc[b, src(e), d]
__global__ void k_nodeout(const float* __restrict__ alpha, const float* __restrict__ Hsrc,
                          const int* __restrict__ inc, const int* __restrict__ hts,
                          float* __restrict__ out)
{
    int bn = blockIdx.x; int b = bn / NEq, n = bn % NEq;
    __shared__ int   esrc[24];
    __shared__ float eal[24*Hq];
    int t = threadIdx.x;
    if (t < 24) {
        int eid = (t < 23) ? inc[n*23 + t] : (Pq + n);
        esrc[t] = (t < 23) ? hts[eid] : n;
    }
    for (int t2 = t; t2 < 24*Hq; t2 += blockDim.x) {
        int slot = t2 / Hq, hh = t2 % Hq;
        int eid = (slot < 23) ? inc[n*23 + slot] : (Pq + n);
        eal[t2] = alpha[((long)b*Eq + eid)*Hq + hh];
    }
    __syncthreads();
    for (int d = t; d < Dq; d += blockDim.x) {
        int h = d >> 6;
        float s = 0.f;
        #pragma unroll
        for (int slot = 0; slot < 24; slot++)
            s += eal[slot*Hq + h] * Hsrc[((long)b*NEq + esrc[slot])*Dq + d];
        out[(long)bn*Dq + d] = s;
    }
}

__global__ void k_newci(const int* __restrict__ mask, const float* __restrict__ f,
                        const float* __restrict__ ci, float* __restrict__ out)
{
    long idx = (long)blockIdx.x*256 + threadIdx.x;  // NP*D
    int d = (int)(idx % Dq); long n = idx / Dq;
    int b = (int)(n / Pq), p = (int)(n % Pq);
    out[idx] = mask[n] ? f[((long)b*Eq + p)*Dq + d] : ci[idx];
}

// group bilinear, O=97, fused outer-product GEMM, split over h (partials)
// grid (46, 12), 256 threads; BM=48 rows, thread = (ty 0..7 rows x6, tx 0..31 cols x4)
__global__ void k_gbl_rel(const float* __restrict__ A, const float* __restrict__ C,
                          const float* __restrict__ W, float* __restrict__ part)
{
    __shared__ float a_s[48*64];
    __shared__ float c_s[48*64];
    __shared__ float w_s[32*128];
    int h  = blockIdx.y;
    int n0 = blockIdx.x * 48;
    int tid = threadIdx.x;
    for (int idx = tid; idx < 48*64; idx += 256) {
        int r = idx >> 6, i = idx & 63;
        a_s[idx] = A[(long)(n0 + r)*Dq + h*64 + i];
        c_s[idx] = C[(long)(n0 + r)*Dq + h*64 + i];
    }
    __syncthreads();
    int ty = tid >> 5, tx = tid & 31;
    float acc[6][4] = {};
    const float* Wh = W + (long)h*4096*Rq;
    for (int i = 0; i < 64; i++) {
        float pa[6];
        #pragma unroll
        for (int r = 0; r < 6; r++) pa[r] = a_s[(ty*6 + r)*64 + i];
        #pragma unroll
        for (int jt = 0; jt < 2; jt++) {
            __syncthreads();
            const float* Wi = Wh + (long)(i*64 + jt*32)*Rq;
            for (int idx = tid; idx < 32*128; idx += 256) {
                int j = idx >> 7, o = idx & 127;
                w_s[idx] = (o < Rq) ? Wi[(long)j*Rq + o] : 0.f;
            }
            __syncthreads();
            #pragma unroll 4
            for (int j = 0; j < 32; j++) {
                float4 w = *(const float4*)&w_s[j*128 + tx*4];
                #pragma unroll
                for (int r = 0; r < 6; r++) {
                    float av = pa[r] * c_s[(ty*6 + r)*64 + jt*32 + j];
                    acc[r][0] += av*w.x; acc[r][1] += av*w.y;
                    acc[r][2] += av*w.z; acc[r][3] += av*w.w;
                }
            }
        }
    }
    #pragma unroll
    for (int r = 0; r < 6; r++) {
        int n = n0 + ty*6 + r;
        float* pp = part + ((long)h*NPq + n)*Rq;
        #pragma unroll
        for (int q = 0; q < 4; q++) {
            int o = tx*4 + q;
            if (o < Rq) pp[o] = acc[r][q];
        }
    }
}

__global__ void k_rel_reduce(const float* __restrict__ part, const float* __restrict__ brel,
                             float* __restrict__ out)
{
    long idx = (long)blockIdx.x*256 + threadIdx.x;
    if (idx >= (long)NPq*Rq) return;
    int o = (int)(idx % Rq);
    float s = brel[o];
    #pragma unroll
    for (int h = 0; h < Hq; h++) s += part[(long)h*NPq*Rq + idx];
    out[idx] = s;
}

// ---------------- host ----------------
static void sgemm(const float* A, const float* B, const float* bias, float* C,
                  int M, int K, int N, int batch, long sA, long sB, long sC, int act)
{
    dim3 g(N/64, (M + 63)/64, batch);
    k_sgemm<<<g, 256>>>(A, B, bias, C, M, K, N, sA, sB, sC, act);
}

template <typename T>
static T* sym(const void* s) { void* p = 0; cudaGetSymbolAddress(&p, s); return (T*)p; }

extern "C" void kernel_launch(void* const* d_in, const int* in_sizes, int n_in,
                              void* d_out, int out_size)
{
    const float* ctx    = (const float*)d_in[0];
    const float* att    = (const float*)d_in[1];
    const int*   mm     = (const int*)  d_in[2];
    const float* em     = (const float*)d_in[3];
    const int*   hts    = (const int*)  d_in[4];
    const float* Whb    = (const float*)d_in[5];
    const float* bhb    = (const float*)d_in[6];
    const float* Wtb    = (const float*)d_in[7];
    const float* btb    = (const float*)d_in[8];
    const float* Wbin   = (const float*)d_in[9];
    const float* bbin   = (const float*)d_in[10];
    const float* Wrel   = (const float*)d_in[11];
    const float* brel   = (const float*)d_in[12];
    const float* Wh     = (const float*)d_in[13];
    const float* bh     = (const float*)d_in[14];
    const float* Wt     = (const float*)d_in[15];
    const float* bt     = (const float*)d_in[16];
    const float* Wnode  = (const float*)d_in[17];
    const float* Wni    = (const float*)d_in[18];
    const float* Wfij   = (const float*)d_in[19];
    const float* Wnj    = (const float*)d_in[20];
    const float* attn_p = (const float*)d_in[21];
    const float* egat_b = (const float*)d_in[22];

    float* outBin = (float*)d_out;
    float* outRel = outBin + (long)NPq*2;

    float* p_ent   = sym<float>(g_entity);
    float* p_cur   = sym<float>(g_cur);
    float* p_ca    = sym<float>(g_ca);
    float* p_ci    = sym<float>(g_ci);
    float* p_X1    = sym<float>(g_X1);
    float* p_X2    = sym<float>(g_X2);
    float* p_bh    = sym<float>(g_bh);
    float* p_bt    = sym<float>(g_bt);
    int*   p_mask  = sym<int>(g_mask);
    float* p_Ni    = sym<float>(g_Ni);
    float* p_Nj    = sym<float>(g_Nj);
    float* p_Hs    = sym<float>(g_Hs);
    float* p_EfW   = sym<float>(g_EfW);
    float* p_f     = sym<float>(g_f);
    float* p_score = sym<float>(g_score);
    float* p_alpha = sym<float>(g_alpha);
    float* p_nout  = sym<float>(g_nout);
    float* p_newci = sym<float>(g_newci);
    float* p_rpart = sym<float>(g_relpart);
    int*   p_inc   = sym<int>(g_inc);

    // ---- entity pooling + context pooling ----
    k_entity<<<Bq*NEq, 256>>>(ctx, mm, em, p_ent);
    k_cur<<<Bq*Hq*NEq, 256>>>(att, mm, em, p_cur);
    k_ca<<<Bq*Pq, 256>>>(p_cur, hts, p_ca);
    sgemm(p_ca, ctx, 0, p_ci, Pq, Lq, Dq, Bq,
          (long)Pq*Lq, (long)Lq*Dq, (long)Pq*Dq, 0);

    // ---- binary classifier ----
    k_concat<<<NPq*Dq/256, 256>>>(p_ent, hts, p_ci, p_X1, p_X2);
    sgemm(p_X1, Whb, bhb, p_bh, NPq, 2*Dq, Dq, 1, 0, 0, 0, 1);
    sgemm(p_X2, Wtb, btb, p_bt, NPq, 2*Dq, Dq, 1, 0, 0, 0, 1);
    k_gbl_bin<<<NPq, 256>>>(p_bh, p_bt, Wbin, bbin, outBin, p_mask);

    // ---- EGAT ----
    k_inc<<<1, 32>>>(hts, p_inc);
    sgemm(p_ent, Wni,   0, p_Ni, Bq*NEq, Dq, Dq, 1, 0, 0, 0, 0);
    sgemm(p_ent, Wnj,   0, p_Nj, Bq*NEq, Dq, Dq, 1, 0, 0, 0, 0);
    sgemm(p_ent, Wnode, 0, p_Hs, Bq*NEq, Dq, Dq, 1, 0, 0, 0, 0);
    sgemm(p_ci,  Wfij,  0, p_EfW, NPq,   Dq, Dq, 1, 0, 0, 0, 0);
    k_f<<<Bq*Eq, 256>>>(p_Ni, p_Nj, p_EfW, egat_b, hts, p_f);
    k_score<<<Bq*Eq, 384>>>(p_f, attn_p, p_mask, p_score);
    k_soft<<<Bq*NEq, 384>>>(p_score, p_inc, p_mask, p_alpha);
    k_nodeout<<<Bq*NEq, 256>>>(p_alpha, p_Hs, p_inc, hts, p_nout);

    // ---- relation head ----
    k_newci<<<NPq*Dq/256, 256>>>(p_mask, p_f, p_ci, p_newci);
    k_concat<<<NPq*Dq/256, 256>>>(p_nout, hts, p_newci, p_X1, p_X2);
    sgemm(p_X1, Wh, bh, p_bh, NPq, 2*Dq, Dq, 1, 0, 0, 0, 1);
    sgemm(p_X2, Wt, bt, p_bt, NPq, 2*Dq, Dq, 1, 0, 0, 0, 1);
    k_gbl_rel<<<dim3(46, 12), 256>>>(p_bh, p_bt, Wrel, p_rpart);
    k_rel_reduce<<<((long)NPq*Rq + 255)/256, 256>>>(p_rpart, brel, outRel);
}

// round 3
// speedup vs baseline: 1.2015x; 1.2015x over previous
#include <cuda_runtime.h>
#include <math.h>

// ---------------- problem constants ----------------
#define Bq   4
#define Lq   1024
#define Dq   768
#define Hq   12
#define BSq  64
#define Mq   48
#define NEq  24
#define Pq   552      // NE*(NE-1)
#define Eq   576      // P + NE self loops
#define Rq   97
#define NPq  (Bq*Pq)  // 2208

// ---------------- scratch (device globals; no allocation) ----------------
__device__ float g_entity [Bq*NEq*Dq];
__device__ float g_cur    [Bq*Hq*NEq*Lq];
__device__ float g_ca     [Bq*Pq*Lq];
__device__ float g_ci     [NPq*Dq];
__device__ float g_bh     [NPq*Dq];
__device__ float g_bt     [NPq*Dq];
__device__ int   g_mask   [NPq];
__device__ float g_Ni     [Bq*NEq*Dq];
__device__ float g_Nj     [Bq*NEq*Dq];
__device__ float g_Hs     [Bq*NEq*Dq];
__device__ float g_EfW    [NPq*Dq];
__device__ float g_f      [Bq*Eq*Dq];
__device__ float g_score  [Bq*Eq*Hq];
__device__ float g_alpha  [Bq*Eq*Hq];
__device__ float g_nout   [Bq*NEq*Dq];
__device__ float g_newci  [NPq*Dq];
__device__ float g_relpart[(size_t)Hq*NPq*Rq];
__device__ int   g_inc    [NEq*23];
__device__ float g_Wpad   [(size_t)Hq*4096*128];   // Wrel padded to 128 cols

// ---------------- small kernels (unchanged logic) ----------------

__global__ void k_entity(const float* __restrict__ ctx, const int* __restrict__ mm,
                         const float* __restrict__ em, float* __restrict__ out)
{
    int bn = blockIdx.x; int b = bn / NEq, n = bn % NEq;
    __shared__ float w_s[Mq]; __shared__ int mi_s[Mq];
    if (threadIdx.x < Mq) {
        w_s[threadIdx.x]  = em[(b*NEq + n)*Mq + threadIdx.x];
        mi_s[threadIdx.x] = mm[b*Mq + threadIdx.x];
    }
    __syncthreads();
    for (int d = threadIdx.x; d < Dq; d += blockDim.x) {
        float s = 0.f;
        #pragma unroll 4
        for (int m = 0; m < Mq; m++) {
            float w = w_s[m];
            if (w != 0.f) s += w * expf(ctx[((long)b*Lq + mi_s[m])*Dq + d]);
        }
        out[(long)bn*Dq + d] = logf(s);
    }
}

__global__ void k_cur(const float* __restrict__ att, const int* __restrict__ mm,
                      const float* __restrict__ em, float* __restrict__ cur)
{
    int id = blockIdx.x;
    int n = id % NEq; int h = (id / NEq) % Hq; int b = id / (NEq*Hq);
    __shared__ int   act_m[Mq];
    __shared__ float act_w[Mq];
    __shared__ int   nact;
    __shared__ float invc;
    if (threadIdx.x == 0) {
        int c = 0; float cnt = 0.f;
        for (int m = 0; m < Mq; m++) {
            float w = em[(b*NEq + n)*Mq + m]; cnt += w;
            if (w != 0.f) { act_m[c] = mm[b*Mq + m]; act_w[c] = w; c++; }
        }
        nact = c; invc = 1.f / (cnt + 1e-20f);
    }
    __syncthreads();
    const float* abase = att + ((long)(b*Hq + h))*Lq*Lq;
    float* obase = cur + (long)id*Lq;
    int na = nact; float iv = invc;
    for (int l = threadIdx.x; l < Lq; l += blockDim.x) {
        float s = 0.f;
        for (int a = 0; a < na; a++) s += act_w[a] * abase[(long)act_m[a]*Lq + l];
        obase[l] = s * iv;
    }
}

__global__ void k_ca(const float* __restrict__ cur, const int* __restrict__ hts,
                     float* __restrict__ ca)
{
    int bp = blockIdx.x; int b = bp / Pq, p = bp % Pq;
    int h0 = hts[p], h1 = hts[Pq + p];
    const float* c0 = cur + ((long)b*Hq*NEq + h0)*Lq;
    const float* c1 = cur + ((long)b*Hq*NEq + h1)*Lq;
    float v[4]; float local = 0.f;
    #pragma unroll
    for (int q = 0; q < 4; q++) {
        int l = threadIdx.x + q*256;
        float s = 0.f;
        #pragma unroll
        for (int h = 0; h < Hq; h++)
            s += c0[(long)h*NEq*Lq + l] * c1[(long)h*NEq*Lq + l];
        v[q] = s; local += s;
    }
    __shared__ float red[256];
    red[threadIdx.x] = local; __syncthreads();
    for (int off = 128; off > 0; off >>= 1) {
        if (threadIdx.x < off) red[threadIdx.x] += red[threadIdx.x + off];
        __syncthreads();
    }
    float inv = 1.f / (red[0] + 1e-20f);
    float* o = ca + (long)bp*Lq;
    #pragma unroll
    for (int q = 0; q < 4; q++) o[threadIdx.x + q*256] = v[q]*inv;
}

// ---------------- high-performance GEMM (128x128x8, 8x8 microtile) ----------------
// N is always 768. Per-z pointer tables; MODE CAT=1 gathers A = [feat[ent] | ciX].

struct P4 {
    const float* A[4];
    const float* B[4];
    const float* bias[4];
    float*       C[4];
    int          M[4];
};

template<int CAT>
__global__ __launch_bounds__(256, 2)
void k_gemm(P4 p, int K, int act,
            const float* __restrict__ feat, const float* __restrict__ ciX,
            const int* __restrict__ hts)
{
    __shared__ float As[2][8][132];
    __shared__ float Bs[2][8][128];
    int z = blockIdx.z;
    int M = p.M[z];
    int row0 = blockIdx.y * 128;
    if (row0 >= M) return;
    int col0 = blockIdx.x * 128;
    const float* __restrict__ Bm = p.B[z];
    const float* bias = p.bias[z];
    float* C = p.C[z];
    int tid = threadIdx.x;

    // A loader: each thread owns one row of the A tile
    int a_row = tid >> 1;
    int a_c4  = (tid & 1) << 2;
    int grow  = row0 + a_row;
    int growc = grow < M ? grow : M - 1;
    const float* asrc0;
    const float* asrc1 = 0;
    if (CAT) {
        int b = growc / Pq, pp = growc % Pq;
        asrc0 = feat + ((long)(b*NEq + hts[z*Pq + pp]))*Dq;
        asrc1 = ciX + (long)growc*Dq - Dq;       // asrc1[k] valid for k in [768,1536)
    } else {
        asrc0 = p.A[z] + (long)growc*K;
    }
    int b_k  = tid >> 5;
    int b_c4 = (tid & 31) << 2;

    int KT = K >> 3;
    // initial tile
    {
        float4 av;
        if (CAT && a_c4 >= Dq) av = *(const float4*)(asrc1 + a_c4);
        else                   av = *(const float4*)(asrc0 + a_c4);
        As[0][a_c4+0][a_row]=av.x; As[0][a_c4+1][a_row]=av.y;
        As[0][a_c4+2][a_row]=av.z; As[0][a_c4+3][a_row]=av.w;
        *(float4*)&Bs[0][b_k][b_c4] = *(const float4*)(Bm + (long)b_k*Dq + col0 + b_c4);
    }
    __syncthreads();

    int ty = tid >> 4, tx = tid & 15;
    float acc[8][8] = {};
    float4 ra, rb;
    int buf = 0;
    for (int kt = 0; kt < KT; kt++) {
        if (kt + 1 < KT) {
            int k = (kt + 1)*8 + a_c4;
            if (CAT) ra = (k >= Dq) ? *(const float4*)(asrc1 + k) : *(const float4*)(asrc0 + k);
            else     ra = *(const float4*)(asrc0 + k);
            rb = *(const float4*)(Bm + (long)((kt+1)*8 + b_k)*Dq + col0 + b_c4);
        }
        #pragma unroll
        for (int kk = 0; kk < 8; kk++) {
            float4 a0 = *(const float4*)&As[buf][kk][ty*4];
            float4 a1 = *(const float4*)&As[buf][kk][64 + ty*4];
            float4 b0 = *(const float4*)&Bs[buf][kk][tx*4];
            float4 b1 = *(const float4*)&Bs[buf][kk][64 + tx*4];
            float aa[8] = {a0.x,a0.y,a0.z,a0.w,a1.x,a1.y,a1.z,a1.w};
            float bb[8] = {b0.x,b0.y,b0.z,b0.w,b1.x,b1.y,b1.z,b1.w};
            #pragma unroll
            for (int i = 0; i < 8; i++)
                #pragma unroll
                for (int j = 0; j < 8; j++)
                    acc[i][j] += aa[i]*bb[j];
        }
        if (kt + 1 < KT) {
            int nb = buf ^ 1;
            As[nb][a_c4+0][a_row]=ra.x; As[nb][a_c4+1][a_row]=ra.y;
            As[nb][a_c4+2][a_row]=ra.z; As[nb][a_c4+3][a_row]=ra.w;
            *(float4*)&Bs[nb][b_k][b_c4] = rb;
            __syncthreads();
            buf = nb;
        }
    }

    float4 bi0 = make_float4(0.f,0.f,0.f,0.f), bi1 = bi0;
    if (bias) {
        bi0 = *(const float4*)(bias + col0 + tx*4);
        bi1 = *(const float4*)(bias + col0 + 64 + tx*4);
    }
    #pragma unroll
    for (int i = 0; i < 8; i++) {
        int r = row0 + ((i < 4) ? ty*4 + i : 64 + ty*4 + (i-4));
        if (r >= M) continue;
        float4 v0 = make_float4(acc[i][0]+bi0.x, acc[i][1]+bi0.y, acc[i][2]+bi0.z, acc[i][3]+bi0.w);
        float4 v1 = make_float4(acc[i][4]+bi1.x, acc[i][5]+bi1.y, acc[i][6]+bi1.z, acc[i][7]+bi1.w);
        if (act) {
            v0.x=tanhf(v0.x); v0.y=tanhf(v0.y); v0.z=tanhf(v0.z); v0.w=tanhf(v0.w);
            v1.x=tanhf(v1.x); v1.y=tanhf(v1.y); v1.z=tanhf(v1.z); v1.w=tanhf(v1.w);
        }
        *(float4*)(C + (long)r*Dq + col0 + tx*4)      = v0;
        *(float4*)(C + (long)r*Dq + col0 + 64 + tx*4) = v1;
    }
}

// ---------------- group bilinear binary head ----------------
__global__ void k_gbl_bin(const float* __restrict__ A, const float* __restrict__ C,
                          const float* __restrict__ W, const float* __restrict__ bias,
                          float* __restrict__ out, int* __restrict__ mask)
{
    int n = blockIdx.x;
    __shared__ float a_s[Dq], c_s[Dq];
    for (int d = threadIdx.x; d < Dq; d += 256) {
        a_s[d] = A[(long)n*Dq + d];
        c_s[d] = C[(long)n*Dq + d];
    }
    __syncthreads();
    float s0 = 0.f, s1 = 0.f;
    for (int hi = threadIdx.x; hi < Dq; hi += 256) {
        float ai = a_s[hi];
        const float2* w2 = (const float2*)(W + (long)hi*BSq*2);
        const float* cc = c_s + (hi & ~63);
        #pragma unroll 8
        for (int j = 0; j < BSq; j++) {
            float v = ai * cc[j];
            float2 ww = w2[j];
            s0 += v*ww.x; s1 += v*ww.y;
        }
    }
    __shared__ float r0[256], r1[256];
    r0[threadIdx.x] = s0; r1[threadIdx.x] = s1; __syncthreads();
    for (int off = 128; off > 0; off >>= 1) {
        if (threadIdx.x < off) { r0[threadIdx.x] += r0[threadIdx.x+off]; r1[threadIdx.x] += r1[threadIdx.x+off]; }
        __syncthreads();
    }
    if (threadIdx.x == 0) {
        float b0 = r0[0] + bias[0], b1 = r1[0] + bias[1];
        out[n*2]   = b0;
        out[n*2+1] = b1;
        mask[n] = (b1 > b0) ? 1 : 0;
    }
}

__global__ void k_inc(const int* __restrict__ hts, int* __restrict__ inc)
{
    if (threadIdx.x == 0 && blockIdx.x == 0) {
        int cnt[NEq];
        for (int i = 0; i < NEq; i++) cnt[i] = 0;
        for (int p = 0; p < Pq; p++) {
            int d = hts[Pq + p];
            inc[d*23 + cnt[d]++] = p;
        }
    }
}

__global__ void k_f(const float* __restrict__ Ni, const float* __restrict__ Nj,
                    const float* __restrict__ EfW, const float* __restrict__ eb,
                    const int* __restrict__ hts, float* __restrict__ f)
{
    int be = blockIdx.x; int b = be / Eq, e = be % Eq;
    int src, dst; const float* ef = 0;
    if (e < Pq) { src = hts[e]; dst = hts[Pq + e]; ef = EfW + ((long)b*Pq + e)*Dq; }
    else        { src = dst = e - Pq; }
    const float* ni = Ni + ((long)b*NEq + src)*Dq;
    const float* nj = Nj + ((long)b*NEq + dst)*Dq;
    float* o = f + (long)be*Dq;
    for (int d = threadIdx.x; d < Dq; d += blockDim.x) {
        float v = ni[d] + nj[d] + eb[d];
        if (ef) v += ef[d];
        o[d] = v;
    }
}

__global__ void k_score(const float* __restrict__ f, const float* __restrict__ attn_p,
                        const int* __restrict__ mask, float* __restrict__ score)
{
    int be = blockIdx.x; int b = be / Eq, e = be % Eq;
    int h = threadIdx.x >> 5, lane = threadIdx.x & 31;
    const float* fr = f + (long)be*Dq + h*BSq;
    float s = 0.f;
    #pragma unroll
    for (int i = lane; i < BSq; i += 32) {
        float x = fr[i];
        float lr = x > 0.f ? x : 0.2f*x;
        s += lr * attn_p[h*BSq + i];
    }
    #pragma unroll
    for (int off = 16; off; off >>= 1) s += __shfl_xor_sync(0xffffffffu, s, off);
    if (lane == 0) {
        int m = (e < Pq) ? mask[b*Pq + e] : 1;
        score[(long)be*Hq + h] = m ? s : -1e30f;
    }
}

__global__ void k_soft(const float* __restrict__ score, const int* __restrict__ inc,
                       const int* __restrict__ mask, float* __restrict__ alpha)
{
    int bn = blockIdx.x; int b = bn / NEq, n = bn % NEq;
    int h = threadIdx.x >> 5, lane = threadIdx.x & 31;
    int eid = 0; float sc = -INFINITY; float m = 0.f;
    if (lane < 24) {
        eid = (lane < 23) ? inc[n*23 + lane] : (Pq + n);
        sc  = score[((long)b*Eq + eid)*Hq + h];
        m   = (eid < Pq) ? (float)mask[b*Pq + eid] : 1.f;
    }
    float mx = sc;
    #pragma unroll
    for (int off = 16; off; off >>= 1) mx = fmaxf(mx, __shfl_xor_sync(0xffffffffu, mx, off));
    float ex = (lane < 24) ? expf(sc - mx)*m : 0.f;
    float den = ex;
    #pragma unroll
    for (int off = 16; off; off >>= 1) den += __shfl_xor_sync(0xffffffffu, den, off);
    if (lane < 24) alpha[((long)b*Eq + eid)*Hq + h] = ex / (den + 1e-20f);
}

__global__ void k_nodeout(const float* __restrict__ alpha, const float* __restrict__ Hsrc,
                          const int* __restrict__ inc, const int* __restrict__ hts,
                          float* __restrict__ out)
{
    int bn = blockIdx.x; int b = bn / NEq, n = bn % NEq;
    __shared__ int   esrc[24];
    __shared__ float eal[24*Hq];
    int t = threadIdx.x;
    if (t < 24) {
        int eid = (t < 23) ? inc[n*23 + t] : (Pq + n);
        esrc[t] = (t < 23) ? hts[eid] : n;
    }
    for (int t2 = t; t2 < 24*Hq; t2 += blockDim.x) {
        int slot = t2 / Hq, hh = t2 % Hq;
        int eid = (slot < 23) ? inc[n*23 + slot] : (Pq + n);
        eal[t2] = alpha[((long)b*Eq + eid)*Hq + hh];
    }
    __syncthreads();
    for (int d = t; d < Dq; d += blockDim.x) {
        int h = d >> 6;
        float s = 0.f;
        #pragma unroll
        for (int slot = 0; slot < 24; slot++)
            s += eal[slot*Hq + h] * Hsrc[((long)b*NEq + esrc[slot])*Dq + d];
        out[(long)bn*Dq + d] = s;
    }
}

__global__ void k_newci(const int* __restrict__ mask, const float* __restrict__ f,
                        const float* __restrict__ ci, float* __restrict__ out)
{
    long idx = (long)blockIdx.x*256 + threadIdx.x;
    int d = (int)(idx % Dq); long n = idx / Dq;
    int b = (int)(n / Pq), p = (int)(n % Pq);
    out[idx] = mask[n] ? f[((long)b*Eq + p)*Dq + d] : ci[idx];
}

// ---------------- Wrel padding: [49152][97] -> [12][4096][128] ----------------
__global__ void k_wpad(const float* __restrict__ W, float* __restrict__ Wp)
{
    long idx = (long)blockIdx.x*256 + threadIdx.x;   // over 12*4096*128
    int o = (int)(idx & 127);
    long row = idx >> 7;
    Wp[idx] = (o < Rq) ? W[row*Rq + o] : 0.f;
}

// ---------------- group bilinear relation head ----------------
// per (row-block of 96, head h): out96x97 += outer(a,c) @ Wpad_h, K=(i,j)=4096
__global__ __launch_bounds__(256, 2)
void k_gbl_rel(const float* __restrict__ A, const float* __restrict__ C,
               const float* __restrict__ Wp, float* __restrict__ part)
{
    extern __shared__ float dyn[];
    float (*a_s)[68] = (float(*)[68])dyn;                   // [96][68]
    float (*c_s)[68] = (float(*)[68])(dyn + 96*68);         // [96][68]
    float (*w_s)[8][128] = (float(*)[8][128])(dyn + 2*96*68);  // [2][8][128]

    int h = blockIdx.y;
    int n0 = blockIdx.x * 96;
    int tid = threadIdx.x;
    for (int idx = tid; idx < 96*16; idx += 256) {
        int r = idx >> 4, c4 = (idx & 15) << 2;
        *(float4*)&a_s[r][c4] = *(const float4*)(A + (long)(n0+r)*Dq + h*64 + c4);
        *(float4*)&c_s[r][c4] = *(const float4*)(C + (long)(n0+r)*Dq + h*64 + c4);
    }
    const float* Wh = Wp + (long)h*4096*128;
    int wk = tid >> 5, wc = (tid & 31) << 2;
    *(float4*)&w_s[0][wk][wc] = *(const float4*)(Wh + (long)wk*128 + wc);
    __syncthreads();

    int ty = tid >> 4, tx = tid & 15;
    int r0 = ty*6;
    float acc[6][8] = {};
    float4 wr;
    int buf = 0;
    for (int kt = 0; kt < 512; kt++) {
        if (kt + 1 < 512)
            wr = *(const float4*)(Wh + (long)(kt+1)*1024 + wk*128 + wc);
        int i  = kt >> 3;
        int j0 = (kt & 7) << 3;
        float af[6];
        #pragma unroll
        for (int r = 0; r < 6; r++) af[r] = a_s[r0+r][i];
        #pragma unroll
        for (int kk = 0; kk < 8; kk++) {
            float4 w0 = *(const float4*)&w_s[buf][kk][tx*4];
            float4 w1 = *(const float4*)&w_s[buf][kk][64 + tx*4];
            #pragma unroll
            for (int r = 0; r < 6; r++) {
                float av = af[r] * c_s[r0+r][j0+kk];
                acc[r][0] += av*w0.x; acc[r][1] += av*w0.y;
                acc[r][2] += av*w0.z; acc[r][3] += av*w0.w;
                acc[r][4] += av*w1.x; acc[r][5] += av*w1.y;
                acc[r][6] += av*w1.z; acc[r][7] += av*w1.w;
            }
        }
        if (kt + 1 < 512) {
            int nb = buf ^ 1;
            *(float4*)&w_s[nb][wk][wc] = wr;
            __syncthreads();
            buf = nb;
        }
    }
    #pragma unroll
    for (int r = 0; r < 6; r++) {
        long base = ((long)h*NPq + n0 + r0 + r)*Rq;
        #pragma unroll
        for (int q = 0; q < 4; q++) {
            int o0 = tx*4 + q, o1 = 64 + tx*4 + q;
            part[base + o0] = acc[r][q];
            if (o1 < Rq) part[base + o1] = acc[r][4+q];
        }
    }
}

__global__ void k_rel_reduce(const float* __restrict__ part, const float* __restrict__ brel,
                             float* __restrict__ out)
{
    long idx = (long)blockIdx.x*256 + threadIdx.x;
    if (idx >= (long)NPq*Rq) return;
    int o = (int)(idx % Rq);
    float s = brel[o];
    #pragma unroll
    for (int h = 0; h < Hq; h++) s += part[(long)h*NPq*Rq + idx];
    out[idx] = s;
}

// ---------------- host ----------------
template <typename T>
static T* sym(const void* s) { void* p = 0; cudaGetSymbolAddress(&p, s); return (T*)p; }

extern "C" void kernel_launch(void* const* d_in, const int* in_sizes, int n_in,
                              void* d_out, int out_size)
{
    const float* ctx    = (const float*)d_in[0];
    const float* att    = (const float*)d_in[1];
    const int*   mm     = (const int*)  d_in[2];
    const float* em     = (const float*)d_in[3];
    const int*   hts    = (const int*)  d_in[4];
    const float* Whb    = (const float*)d_in[5];
    const float* bhb    = (const float*)d_in[6];
    const float* Wtb    = (const float*)d_in[7];
    const float* btb    = (const float*)d_in[8];
    const float* Wbin   = (const float*)d_in[9];
    const float* bbin   = (const float*)d_in[10];
    const float* Wrel   = (const float*)d_in[11];
    const float* brel   = (const float*)d_in[12];
    const float* Wh     = (const float*)d_in[13];
    const float* bh     = (const float*)d_in[14];
    const float* Wt     = (const float*)d_in[15];
    const float* bt     = (const float*)d_in[16];
    const float* Wnode  = (const float*)d_in[17];
    const float* Wni    = (const float*)d_in[18];
    const float* Wfij   = (const float*)d_in[19];
    const float* Wnj    = (const float*)d_in[20];
    const float* attn_p = (const float*)d_in[21];
    const float* egat_b = (const float*)d_in[22];

    float* outBin = (float*)d_out;
    float* outRel = outBin + (long)NPq*2;

    float* p_ent   = sym<float>(g_entity);
    float* p_cur   = sym<float>(g_cur);
    float* p_ca    = sym<float>(g_ca);
    float* p_ci    = sym<float>(g_ci);
    float* p_bh    = sym<float>(g_bh);
    float* p_bt    = sym<float>(g_bt);
    int*   p_mask  = sym<int>(g_mask);
    float* p_Ni    = sym<float>(g_Ni);
    float* p_Nj    = sym<float>(g_Nj);
    float* p_Hs    = sym<float>(g_Hs);
    float* p_EfW   = sym<float>(g_EfW);
    float* p_f     = sym<float>(g_f);
    float* p_score = sym<float>(g_score);
    float* p_alpha = sym<float>(g_alpha);
    float* p_nout  = sym<float>(g_nout);
    float* p_newci = sym<float>(g_newci);
    float* p_rpart = sym<float>(g_relpart);
    int*   p_inc   = sym<int>(g_inc);
    float* p_Wpad  = sym<float>(g_Wpad);

    int relSmem = (2*96*68 + 2*8*128) * 4;  // 60416 bytes
    cudaFuncSetAttribute(k_gbl_rel, cudaFuncAttributeMaxDynamicSharedMemorySize, relSmem);

    // ---- entity pooling + context pooling ----
    k_entity<<<Bq*NEq, 256>>>(ctx, mm, em, p_ent);
    k_cur<<<Bq*Hq*NEq, 256>>>(att, mm, em, p_cur);
    k_ca<<<Bq*Pq, 256>>>(p_cur, hts, p_ca);
    k_wpad<<<(Hq*4096*128)/256, 256>>>(Wrel, p_Wpad);   // independent; overlaps nothing but cheap
    k_inc<<<1, 32>>>(hts, p_inc);

    // ci = ca @ ctx  (batched over B)
    {
        P4 p = {};
        for (int z = 0; z < Bq; z++) {
            p.A[z] = p_ca + (long)z*Pq*Lq;
            p.B[z] = ctx + (long)z*Lq*Dq;
            p.bias[z] = 0;
            p.C[z] = p_ci + (long)z*Pq*Dq;
            p.M[z] = Pq;
        }
        k_gemm<0><<<dim3(6, 5, 4), 256>>>(p, Lq, 0, 0, 0, 0);
    }

    // ---- binary classifier: fused concat + tanh GEMM pair ----
    {
        P4 p = {};
        p.B[0] = Whb; p.bias[0] = bhb; p.C[0] = p_bh; p.M[0] = NPq;
        p.B[1] = Wtb; p.bias[1] = btb; p.C[1] = p_bt; p.M[1] = NPq;
        k_gemm<1><<<dim3(6, 18, 2), 256>>>(p, 2*Dq, 1, p_ent, p_ci, hts);
    }
    k_gbl_bin<<<NPq, 256>>>(p_bh, p_bt, Wbin, bbin, outBin, p_mask);

    // ---- EGAT linear layers fused: EfW (M=2208) + Ni/Nj/Hs (M=96) ----
    {
        P4 p = {};
        p.A[0] = p_ci;  p.B[0] = Wfij;  p.C[0] = p_EfW; p.M[0] = NPq;
        p.A[1] = p_ent; p.B[1] = Wni;   p.C[1] = p_Ni;  p.M[1] = Bq*NEq;
        p.A[2] = p_ent; p.B[2] = Wnj;   p.C[2] = p_Nj;  p.M[2] = Bq*NEq;
        p.A[3] = p_ent; p.B[3] = Wnode; p.C[3] = p_Hs;  p.M[3] = Bq*NEq;
        k_gemm<0><<<dim3(6, 18, 4), 256>>>(p, Dq, 0, 0, 0, 0);
    }
    k_f<<<Bq*Eq, 256>>>(p_Ni, p_Nj, p_EfW, egat_b, hts, p_f);
    k_score<<<Bq*Eq, 384>>>(p_f, attn_p, p_mask, p_score);
    k_soft<<<Bq*NEq, 384>>>(p_score, p_inc, p_mask, p_alpha);
    k_nodeout<<<Bq*NEq, 256>>>(p_alpha, p_Hs, p_inc, hts, p_nout);

    // ---- relation head ----
    k_newci<<<NPq*Dq/256, 256>>>(p_mask, p_f, p_ci, p_newci);
    {
        P4 p = {};
        p.B[0] = Wh; p.bias[0] = bh; p.C[0] = p_bh; p.M[0] = NPq;
        p.B[1] = Wt; p.bias[1] = bt; p.C[1] = p_bt; p.M[1] = NPq;
        k_gemm<1><<<dim3(6, 18, 2), 256>>>(p, 2*Dq, 1, p_nout, p_newci, hts);
    }
    k_gbl_rel<<<dim3(23, 12), 256, relSmem>>>(p_bh, p_bt, p_Wpad, p_rpart);
    k_rel_reduce<<<((long)NPq*Rq + 255)/256, 256>>>(p_rpart, brel, outRel);
}

// round 4
// speedup vs baseline: 1.8683x; 1.5550x over previous
#include <cuda_runtime.h>
#include <cuda_bf16.h>
#include <math.h>

// ---------------- problem constants ----------------
#define Bq   4
#define Lq   1024
#define Dq   768
#define Hq   12
#define BSq  64
#define Mq   48
#define NEq  24
#define Pq   552      // NE*(NE-1)
#define Eq   576      // P + NE self loops
#define Rq   97
#define NPq  (Bq*Pq)  // 2208

typedef __nv_bfloat16 bf16;

// ---------------- scratch (device globals; no allocation) ----------------
__device__ float g_entity [Bq*NEq*Dq];
__device__ float g_cur    [Bq*Hq*NEq*Lq];
__device__ float g_ci     [NPq*Dq];
__device__ float g_bh     [NPq*Dq];
__device__ float g_bt     [NPq*Dq];
__device__ int   g_mask   [NPq];
__device__ float g_Ni     [Bq*NEq*Dq];
__device__ float g_Nj     [Bq*NEq*Dq];
__device__ float g_Hs     [Bq*NEq*Dq];
__device__ float g_EfW    [NPq*Dq];
__device__ float g_f      [Bq*Eq*Dq];
__device__ float g_score  [Bq*Eq*Hq];
__device__ float g_alpha  [Bq*Eq*Hq];
__device__ float g_relpart[(size_t)Hq*NPq*128];
__device__ int   g_inc    [NEq*23];

// bf16 split buffers (hi/lo)
__device__ bf16 g_enth[Bq*NEq*Dq],      g_entl[Bq*NEq*Dq];
__device__ bf16 g_cah [Bq*Pq*Lq],       g_cal [Bq*Pq*Lq];
__device__ bf16 g_cih [NPq*Dq],         g_cil [NPq*Dq];
__device__ bf16 g_nouth[Bq*NEq*Dq],     g_noutl[Bq*NEq*Dq];
__device__ bf16 g_newcih[NPq*Dq],       g_newcil[NPq*Dq];
__device__ bf16 g_ctxh[Bq*Lq*Dq],       g_ctxl[Bq*Lq*Dq];
__device__ bf16 g_Whbh[2*Dq*Dq],        g_Whbl[2*Dq*Dq];
__device__ bf16 g_Wtbh[2*Dq*Dq],        g_Wtbl[2*Dq*Dq];
__device__ bf16 g_Whh [2*Dq*Dq],        g_Whl [2*Dq*Dq];
__device__ bf16 g_Wth [2*Dq*Dq],        g_Wtl [2*Dq*Dq];
__device__ bf16 g_Wfijh[Dq*Dq],         g_Wfijl[Dq*Dq];
__device__ bf16 g_Wnih[Dq*Dq],          g_Wnil[Dq*Dq];
__device__ bf16 g_Wnjh[Dq*Dq],          g_Wnjl[Dq*Dq];
__device__ bf16 g_Wnodeh[Dq*Dq],        g_Wnodel[Dq*Dq];
__device__ bf16 g_Wpadh[(size_t)Hq*4096*128], g_Wpadl[(size_t)Hq*4096*128];
__device__ bf16 g_Ph[(size_t)Hq*NPq*4096],    g_Pl[(size_t)Hq*NPq*4096];

// ---------------- helpers ----------------
__device__ __forceinline__ void split2(float x, bf16& h, bf16& l) {
    h = __float2bfloat16(x);
    l = __float2bfloat16(x - __bfloat162float(h));
}
__device__ __forceinline__ unsigned su32(const void* p) {
    return (unsigned)__cvta_generic_to_shared(p);
}
__device__ __forceinline__ void ldmx4(unsigned* r, unsigned addr) {
    asm volatile("ldmatrix.sync.aligned.m8n8.x4.shared.b16 {%0,%1,%2,%3}, [%4];"
        : "=r"(r[0]), "=r"(r[1]), "=r"(r[2]), "=r"(r[3]) : "r"(addr));
}
__device__ __forceinline__ void ldmx4t(unsigned* r, unsigned addr) {
    asm volatile("ldmatrix.sync.aligned.m8n8.x4.trans.shared.b16 {%0,%1,%2,%3}, [%4];"
        : "=r"(r[0]), "=r"(r[1]), "=r"(r[2]), "=r"(r[3]) : "r"(addr));
}
__device__ __forceinline__ void mma16816(float* c, const unsigned* a, const unsigned* b) {
    asm volatile("mma.sync.aligned.m16n8k16.row.col.f32.bf16.bf16.f32 "
        "{%0,%1,%2,%3}, {%4,%5,%6,%7}, {%8,%9}, {%0,%1,%2,%3};"
        : "+f"(c[0]), "+f"(c[1]), "+f"(c[2]), "+f"(c[3])
        : "r"(a[0]), "r"(a[1]), "r"(a[2]), "r"(a[3]), "r"(b[0]), "r"(b[1]));
}

// ---------------- small kernels ----------------

__global__ void k_entity(const float* __restrict__ ctx, const int* __restrict__ mm,
                         const float* __restrict__ em, float* __restrict__ out,
                         bf16* __restrict__ oh, bf16* __restrict__ ol)
{
    int bn = blockIdx.x; int b = bn / NEq, n = bn % NEq;
    __shared__ float w_s[Mq]; __shared__ int mi_s[Mq];
    if (threadIdx.x < Mq) {
        w_s[threadIdx.x]  = em[(b*NEq + n)*Mq + threadIdx.x];
        mi_s[threadIdx.x] = mm[b*Mq + threadIdx.x];
    }
    __syncthreads();
    for (int d = threadIdx.x; d < Dq; d += blockDim.x) {
        float s = 0.f;
        #pragma unroll 4
        for (int m = 0; m < Mq; m++) {
            float w = w_s[m];
            if (w != 0.f) s += w * expf(ctx[((long)b*Lq + mi_s[m])*Dq + d]);
        }
        float v = logf(s);
        out[(long)bn*Dq + d] = v;
        bf16 h, l; split2(v, h, l);
        oh[(long)bn*Dq + d] = h; ol[(long)bn*Dq + d] = l;
    }
}

__global__ void k_cur(const float* __restrict__ att, const int* __restrict__ mm,
                      const float* __restrict__ em, float* __restrict__ cur)
{
    int id = blockIdx.x;
    int n = id % NEq; int h = (id / NEq) % Hq; int b = id / (NEq*Hq);
    __shared__ int   act_m[Mq];
    __shared__ float act_w[Mq];
    __shared__ int   nact;
    __shared__ float invc;
    if (threadIdx.x == 0) {
        int c = 0; float cnt = 0.f;
        for (int m = 0; m < Mq; m++) {
            float w = em[(b*NEq + n)*Mq + m]; cnt += w;
            if (w != 0.f) { act_m[c] = mm[b*Mq + m]; act_w[c] = w; c++; }
        }
        nact = c; invc = 1.f / (cnt + 1e-20f);
    }
    __syncthreads();
    const float* abase = att + ((long)(b*Hq + h))*Lq*Lq;
    float* obase = cur + (long)id*Lq;
    int na = nact; float iv = invc;
    for (int l = threadIdx.x; l < Lq; l += blockDim.x) {
        float s = 0.f;
        for (int a = 0; a < na; a++) s += act_w[a] * abase[(long)act_m[a]*Lq + l];
        obase[l] = s * iv;
    }
}

__global__ void k_ca(const float* __restrict__ cur, const int* __restrict__ hts,
                     bf16* __restrict__ cah, bf16* __restrict__ cal)
{
    int bp = blockIdx.x; int b = bp / Pq, p = bp % Pq;
    int h0 = hts[p], h1 = hts[Pq + p];
    const float* c0 = cur + ((long)b*Hq*NEq + h0)*Lq;
    const float* c1 = cur + ((long)b*Hq*NEq + h1)*Lq;
    float v[4]; float local = 0.f;
    #pragma unroll
    for (int q = 0; q < 4; q++) {
        int l = threadIdx.x + q*256;
        float s = 0.f;
        #pragma unroll
        for (int h = 0; h < Hq; h++)
            s += c0[(long)h*NEq*Lq + l] * c1[(long)h*NEq*Lq + l];
        v[q] = s; local += s;
    }
    __shared__ float red[256];
    red[threadIdx.x] = local; __syncthreads();
    for (int off = 128; off > 0; off >>= 1) {
        if (threadIdx.x < off) red[threadIdx.x] += red[threadIdx.x + off];
        __syncthreads();
    }
    float inv = 1.f / (red[0] + 1e-20f);
    #pragma unroll
    for (int q = 0; q < 4; q++) {
        long o = (long)bp*Lq + threadIdx.x + q*256;
        bf16 h, l; split2(v[q]*inv, h, l);
        cah[o] = h; cal[o] = l;
    }
}

__global__ void k_split(const float* __restrict__ src, bf16* __restrict__ hi,
                        bf16* __restrict__ lo, long n)
{
    long i = (long)blockIdx.x*256 + threadIdx.x;
    if (i >= n) return;
    bf16 h, l; split2(src[i], h, l);
    hi[i] = h; lo[i] = l;
}

// Wrel [49152][97] -> padded split [12][4096][128]
__global__ void k_wpadsplit(const float* __restrict__ W, bf16* __restrict__ Wh,
                            bf16* __restrict__ Wl)
{
    long idx = (long)blockIdx.x*256 + threadIdx.x;   // over 12*4096*128
    int o = (int)(idx & 127);
    long row = idx >> 7;
    float v = (o < Rq) ? W[row*Rq + o] : 0.f;
    bf16 h, l; split2(v, h, l);
    Wh[idx] = h; Wl[idx] = l;
}

// ---------------- mma.sync GEMM (128x128, K-chunk 32, bf16 3-term split) ----------------
// MODE 0: table (A from table). MODE 1: table + concat gather A=[feat|ciX].
// MODE 2: strided over z (rel head).
struct GemmP {
    const bf16 *Ah[4], *Al[4], *Bh[4], *Bl[4];
    const float* bias[4];
    float* C[4];
    bf16 *Chi[4], *Clo[4];
    int Mz[4];
    const bf16 *feath, *featl, *ciXh, *ciXl;
    const int* hts;
    long sA, sB, sC;
    int K, ldb, ldc, act, splitout;
};

template<int MODE>
__global__ __launch_bounds__(256)
void k_mma(GemmP p)
{
    __shared__ bf16 Ash[128][40], Asl[128][40];
    __shared__ bf16 Bsh[32][136],  Bsl[32][136];

    int z = blockIdx.z;
    const bf16 *pBh, *pBl;
    const float* pbias; float* pC;
    bf16 *pChi = 0, *pClo = 0;
    int M;
    const bf16 *tAh = 0, *tAl = 0;
    if (MODE == 2) {
        tAh = p.Ah[0] + (long)z*p.sA;  tAl = p.Al[0] + (long)z*p.sA;
        pBh = p.Bh[0] + (long)z*p.sB;  pBl = p.Bl[0] + (long)z*p.sB;
        pC  = p.C[0]  + (long)z*p.sC;
        pbias = p.bias[0]; M = p.Mz[0];
    } else {
        tAh = p.Ah[z]; tAl = p.Al[z];
        pBh = p.Bh[z]; pBl = p.Bl[z];
        pC  = p.C[z];  pbias = p.bias[z]; M = p.Mz[z];
        if (p.splitout) { pChi = p.Chi[z]; pClo = p.Clo[z]; }
    }
    int row0 = blockIdx.y * 128;
    if (row0 >= M) return;
    int col0 = blockIdx.x * 128;
    int K = p.K, ldb = p.ldb, ldc = p.ldc;
    int t = threadIdx.x;

    // A loader: thread -> (row, 16-col half)
    int arow = t >> 1;
    int ak   = (t & 1) * 16;
    int grow = row0 + arow;
    int rowc = grow < M ? grow : M - 1;
    const bf16 *srcAh0, *srcAl0, *srcAh1 = 0, *srcAl1 = 0;
    if (MODE == 1) {
        int b = rowc / Pq, pp = rowc % Pq;
        long off = ((long)(b*NEq) + p.hts[z*Pq + pp]) * Dq;
        srcAh0 = p.feath + off;              srcAl0 = p.featl + off;
        srcAh1 = p.ciXh + (long)rowc*Dq - Dq; srcAl1 = p.ciXl + (long)rowc*Dq - Dq;
    } else {
        srcAh0 = tAh + (long)rowc*K;  srcAl0 = tAl + (long)rowc*K;
    }
    // B loader: thread -> (k-row, 16-col)
    int bk = t >> 3;
    int bn = (t & 7) * 16;

    uint4 vAh0, vAh1, vAl0, vAl1, vBh0, vBh1, vBl0, vBl1;

    #define LOAD_CHUNK(kc) do {                                                     \
        int k0 = (kc)*32 + ak;                                                      \
        const bf16 *sh, *sl;                                                        \
        if (MODE == 1 && k0 >= Dq) { sh = srcAh1 + k0; sl = srcAl1 + k0; }          \
        else                       { sh = srcAh0 + k0; sl = srcAl0 + k0; }          \
        vAh0 = *(const uint4*)sh;       vAh1 = *(const uint4*)(sh + 8);             \
        vAl0 = *(const uint4*)sl;       vAl1 = *(const uint4*)(sl + 8);             \
        const bf16* bp_ = pBh + (long)((kc)*32 + bk)*ldb + col0 + bn;               \
        const bf16* bq_ = pBl + (long)((kc)*32 + bk)*ldb + col0 + bn;               \
        vBh0 = *(const uint4*)bp_;      vBh1 = *(const uint4*)(bp_ + 8);            \
        vBl0 = *(const uint4*)bq_;      vBl1 = *(const uint4*)(bq_ + 8);            \
    } while (0)

    LOAD_CHUNK(0);

    int w = t >> 5, lane = t & 31;
    int wm = w >> 1, wn = w & 1;
    float acc[2][8][4] = {};

    int KT = K >> 5;
    for (int kc = 0; kc < KT; kc++) {
        *(uint4*)&Ash[arow][ak]     = vAh0;  *(uint4*)&Ash[arow][ak + 8] = vAh1;
        *(uint4*)&Asl[arow][ak]     = vAl0;  *(uint4*)&Asl[arow][ak + 8] = vAl1;
        *(uint4*)&Bsh[bk][bn]       = vBh0;  *(uint4*)&Bsh[bk][bn + 8]   = vBh1;
        *(uint4*)&Bsl[bk][bn]       = vBl0;  *(uint4*)&Bsl[bk][bn + 8]   = vBl1;
        __syncthreads();
        if (kc + 1 < KT) LOAD_CHUNK(kc + 1);

        #pragma unroll
        for (int s = 0; s < 2; s++) {
            unsigned ah[2][4], al[2][4];
            int arw = wm*32 + (lane & 15);
            int acl = s*16 + (lane >> 4)*8;
            ldmx4(ah[0], su32(&Ash[arw][acl]));
            ldmx4(al[0], su32(&Asl[arw][acl]));
            ldmx4(ah[1], su32(&Ash[arw + 16][acl]));
            ldmx4(al[1], su32(&Asl[arw + 16][acl]));
            int brow = s*16 + ((lane >> 3) & 1)*8 + (lane & 7);
            int bcol = wn*64 + (lane >> 4)*8;
            #pragma unroll
            for (int g = 0; g < 4; g++) {
                unsigned bh_[4], bl_[4];
                ldmx4t(bh_, su32(&Bsh[brow][bcol + g*16]));
                ldmx4t(bl_, su32(&Bsl[brow][bcol + g*16]));
                #pragma unroll
                for (int mt = 0; mt < 2; mt++) {
                    mma16816(acc[mt][2*g],   ah[mt], bh_);
                    mma16816(acc[mt][2*g],   ah[mt], bl_);
                    mma16816(acc[mt][2*g],   al[mt], bh_);
                    mma16816(acc[mt][2*g+1], ah[mt], bh_ + 2);
                    mma16816(acc[mt][2*g+1], ah[mt], bl_ + 2);
                    mma16816(acc[mt][2*g+1], al[mt], bh_ + 2);
                }
            }
        }
        __syncthreads();
    }
    #undef LOAD_CHUNK

    int rg = row0 + wm*32 + (lane >> 2);
    int cb = col0 + wn*64 + (lane & 3)*2;
    #pragma unroll
    for (int mt = 0; mt < 2; mt++) {
        #pragma unroll
        for (int n8 = 0; n8 < 8; n8++) {
            int rr = rg + mt*16;
            int cc = cb + n8*8;
            float v0 = acc[mt][n8][0], v1 = acc[mt][n8][1];
            float v2 = acc[mt][n8][2], v3 = acc[mt][n8][3];
            if (pbias) {
                float b0 = pbias[cc], b1 = pbias[cc+1];
                v0 += b0; v1 += b1; v2 += b0; v3 += b1;
            }
            if (p.act) { v0 = tanhf(v0); v1 = tanhf(v1); v2 = tanhf(v2); v3 = tanhf(v3); }
            if (rr < M) {
                *(float2*)(pC + (long)rr*ldc + cc) = make_float2(v0, v1);
                if (pChi) {
                    bf16 h0,l0,h1,l1; split2(v0,h0,l0); split2(v1,h1,l1);
                    *(__nv_bfloat162*)(pChi + (long)rr*ldc + cc) = __nv_bfloat162(h0, h1);
                    *(__nv_bfloat162*)(pClo + (long)rr*ldc + cc) = __nv_bfloat162(l0, l1);
                }
            }
            if (rr + 8 < M) {
                *(float2*)(pC + (long)(rr+8)*ldc + cc) = make_float2(v2, v3);
                if (pChi) {
                    bf16 h0,l0,h1,l1; split2(v2,h0,l0); split2(v3,h1,l1);
                    *(__nv_bfloat162*)(pChi + (long)(rr+8)*ldc + cc) = __nv_bfloat162(h0, h1);
                    *(__nv_bfloat162*)(pClo + (long)(rr+8)*ldc + cc) = __nv_bfloat162(l0, l1);
                }
            }
        }
    }
}

// ---------------- group bilinear binary head (fp32) ----------------
__global__ void k_gbl_bin(const float* __restrict__ A, const float* __restrict__ C,
                          const float* __restrict__ W, const float* __restrict__ bias,
                          float* __restrict__ out, int* __restrict__ mask)
{
    int n = blockIdx.x;
    __shared__ float a_s[Dq], c_s[Dq];
    for (int d = threadIdx.x; d < Dq; d += 256) {
        a_s[d] = A[(long)n*Dq + d];
        c_s[d] = C[(long)n*Dq + d];
    }
    __syncthreads();
    float s0 = 0.f, s1 = 0.f;
    for (int hi = threadIdx.x; hi < Dq; hi += 256) {
        float ai = a_s[hi];
        const float2* w2 = (const float2*)(W + (long)hi*BSq*2);
        const float* cc = c_s + (hi & ~63);
        #pragma unroll 8
        for (int j = 0; j < BSq; j++) {
            float v = ai * cc[j];
            float2 ww = w2[j];
            s0 += v*ww.x; s1 += v*ww.y;
        }
    }
    __shared__ float r0[256], r1[256];
    r0[threadIdx.x] = s0; r1[threadIdx.x] = s1; __syncthreads();
    for (int off = 128; off > 0; off >>= 1) {
        if (threadIdx.x < off) { r0[threadIdx.x] += r0[threadIdx.x+off]; r1[threadIdx.x] += r1[threadIdx.x+off]; }
        __syncthreads();
    }
    if (threadIdx.x == 0) {
        float b0 = r0[0] + bias[0], b1 = r1[0] + bias[1];
        out[n*2]   = b0;
        out[n*2+1] = b1;
        mask[n] = (b1 > b0) ? 1 : 0;
    }
}

__global__ void k_inc(const int* __restrict__ hts, int* __restrict__ inc)
{
    if (threadIdx.x == 0 && blockIdx.x == 0) {
        int cnt[NEq];
        for (int i = 0; i < NEq; i++) cnt[i] = 0;
        for (int p = 0; p < Pq; p++) {
            int d = hts[Pq + p];
            inc[d*23 + cnt[d]++] = p;
        }
    }
}

__global__ void k_f(const float* __restrict__ Ni, const float* __restrict__ Nj,
                    const float* __restrict__ EfW, const float* __restrict__ eb,
                    const int* __restrict__ hts, float* __restrict__ f)
{
    int be = blockIdx.x; int b = be / Eq, e = be % Eq;
    int src, dst; const float* ef = 0;
    if (e < Pq) { src = hts[e]; dst = hts[Pq + e]; ef = EfW + ((long)b*Pq + e)*Dq; }
    else        { src = dst = e - Pq; }
    const float* ni = Ni + ((long)b*NEq + src)*Dq;
    const float* nj = Nj + ((long)b*NEq + dst)*Dq;
    float* o = f + (long)be*Dq;
    for (int d = threadIdx.x; d < Dq; d += blockDim.x) {
        float v = ni[d] + nj[d] + eb[d];
        if (ef) v += ef[d];
        o[d] = v;
    }
}

__global__ void k_score(const float* __restrict__ f, const float* __restrict__ attn_p,
                        const int* __restrict__ mask, float* __restrict__ score)
{
    int be = blockIdx.x; int b = be / Eq, e = be % Eq;
    int h = threadIdx.x >> 5, lane = threadIdx.x & 31;
    const float* fr = f + (long)be*Dq + h*BSq;
    float s = 0.f;
    #pragma unroll
    for (int i = lane; i < BSq; i += 32) {
        float x = fr[i];
        float lr = x > 0.f ? x : 0.2f*x;
        s += lr * attn_p[h*BSq + i];
    }
    #pragma unroll
    for (int off = 16; off; off >>= 1) s += __shfl_xor_sync(0xffffffffu, s, off);
    if (lane == 0) {
        int m = (e < Pq) ? mask[b*Pq + e] : 1;
        score[(long)be*Hq + h] = m ? s : -1e30f;
    }
}

__global__ void k_soft(const float* __restrict__ score, const int* __restrict__ inc,
                       const int* __restrict__ mask, float* __restrict__ alpha)
{
    int bn = blockIdx.x; int b = bn / NEq, n = bn % NEq;
    int h = threadIdx.x >> 5, lane = threadIdx.x & 31;
    int eid = 0; float sc = -INFINITY; float m = 0.f;
    if (lane < 24) {
        eid = (lane < 23) ? inc[n*23 + lane] : (Pq + n);
        sc  = score[((long)b*Eq + eid)*Hq + h];
        m   = (eid < Pq) ? (float)mask[b*Pq + eid] : 1.f;
    }
    float mx = sc;
    #pragma unroll
    for (int off = 16; off; off >>= 1) mx = fmaxf(mx, __shfl_xor_sync(0xffffffffu, mx, off));
    float ex = (lane < 24) ? expf(sc - mx)*m : 0.f;
    float den = ex;
    #pragma unroll
    for (int off = 16; off; off >>= 1) den += __shfl_xor_sync(0xffffffffu, den, off);
    if (lane < 24) alpha[((long)b*Eq + eid)*Hq + h] = ex / (den + 1e-20f);
}

__global__ void k_nodeout(const float* __restrict__ alpha, const float* __restrict__ Hsrc,
                          const int* __restrict__ inc, const int* __restrict__ hts,
                          bf16* __restrict__ oh, bf16* __restrict__ ol)
{
    int bn = blockIdx.x; int b = bn / NEq, n = bn % NEq;
    __shared__ int   esrc[24];
    __shared__ float eal[24*Hq];
    int t = threadIdx.x;
    if (t < 24) {
        int eid = (t < 23) ? inc[n*23 + t] : (Pq + n);
        esrc[t] = (t < 23) ? hts[eid] : n;
    }
    for (int t2 = t; t2 < 24*Hq; t2 += blockDim.x) {
        int slot = t2 / Hq, hh = t2 % Hq;
        int eid = (slot < 23) ? inc[n*23 + slot] : (Pq + n);
        eal[t2] = alpha[((long)b*Eq + eid)*Hq + hh];
    }
    __syncthreads();
    for (int d = t; d < Dq; d += blockDim.x) {
        int h = d >> 6;
        float s = 0.f;
        #pragma unroll
        for (int slot = 0; slot < 24; slot++)
            s += eal[slot*Hq + h] * Hsrc[((long)b*NEq + esrc[slot])*Dq + d];
        bf16 hh, ll; split2(s, hh, ll);
        oh[(long)bn*Dq + d] = hh; ol[(long)bn*Dq + d] = ll;
    }
}

__global__ void k_newci(const int* __restrict__ mask, const float* __restrict__ f,
                        const float* __restrict__ ci, bf16* __restrict__ oh,
                        bf16* __restrict__ ol)
{
    long idx = (long)blockIdx.x*256 + threadIdx.x;
    int d = (int)(idx % Dq); long n = idx / Dq;
    int b = (int)(n / Pq), p = (int)(n % Pq);
    float v = mask[n] ? f[((long)b*Eq + p)*Dq + d] : ci[idx];
    bf16 h, l; split2(v, h, l);
    oh[idx] = h; ol[idx] = l;
}

// P[h][n][i*64+j] = bh[n][h*64+i] * bt[n][h*64+j], split bf16
__global__ void k_outer(const float* __restrict__ bh, const float* __restrict__ bt,
                        bf16* __restrict__ Ph, bf16* __restrict__ Pl)
{
    int blk = blockIdx.x;              // h*NP + n
    int h = blk / NPq, n = blk % NPq;
    __shared__ float a_s[64], c_s[64];
    int t = threadIdx.x;
    if (t < 64)                a_s[t]      = bh[(long)n*Dq + h*64 + t];
    else if (t < 128)          c_s[t - 64] = bt[(long)n*Dq + h*64 + (t - 64)];
    __syncthreads();
    long base = ((long)h*NPq + n)*4096;
    for (int idx = t; idx < 4096; idx += 128) {
        float v = a_s[idx >> 6] * c_s[idx & 63];
        bf16 hh, ll; split2(v, hh, ll);
        Ph[base + idx] = hh; Pl[base + idx] = ll;
    }
}

__global__ void k_rel_reduce(const float* __restrict__ part, const float* __restrict__ brel,
                             float* __restrict__ out)
{
    long idx = (long)blockIdx.x*256 + threadIdx.x;
    if (idx >= (long)NPq*Rq) return;
    int o = (int)(idx % Rq);
    long n = idx / Rq;
    float s = brel[o];
    #pragma unroll
    for (int h = 0; h < Hq; h++) s += part[((long)h*NPq + n)*128 + o];
    out[idx] = s;
}

// ---------------- host ----------------
template <typename T>
static T* sym(const void* s) { void* p = 0; cudaGetSymbolAddress(&p, s); return (T*)p; }

static void splitw(const float* src, bf16* hi, bf16* lo, long n)
{
    k_split<<<(int)((n + 255)/256), 256>>>(src, hi, lo, n);
}

extern "C" void kernel_launch(void* const* d_in, const int* in_sizes, int n_in,
                              void* d_out, int out_size)
{
    const float* ctx    = (const float*)d_in[0];
    const float* att    = (const float*)d_in[1];
    const int*   mm     = (const int*)  d_in[2];
    const float* em     = (const float*)d_in[3];
    const int*   hts    = (const int*)  d_in[4];
    const float* Whb    = (const float*)d_in[5];
    const float* bhb    = (const float*)d_in[6];
    const float* Wtb    = (const float*)d_in[7];
    const float* btb    = (const float*)d_in[8];
    const float* Wbin   = (const float*)d_in[9];
    const float* bbin   = (const float*)d_in[10];
    const float* Wrel   = (const float*)d_in[11];
    const float* brel   = (const float*)d_in[12];
    const float* Wh     = (const float*)d_in[13];
    const float* bh     = (const float*)d_in[14];
    const float* Wt     = (const float*)d_in[15];
    const float* bt     = (const float*)d_in[16];
    const float* Wnode  = (const float*)d_in[17];
    const float* Wni    = (const float*)d_in[18];
    const float* Wfij   = (const float*)d_in[19];
    const float* Wnj    = (const float*)d_in[20];
    const float* attn_p = (const float*)d_in[21];
    const float* egat_b = (const float*)d_in[22];

    float* outBin = (float*)d_out;
    float* outRel = outBin + (long)NPq*2;

    float* p_ent   = sym<float>(g_entity);
    float* p_cur   = sym<float>(g_cur);
    float* p_ci    = sym<float>(g_ci);
    float* p_bh    = sym<float>(g_bh);
    float* p_bt    = sym<float>(g_bt);
    int*   p_mask  = sym<int>(g_mask);
    float* p_Ni    = sym<float>(g_Ni);
    float* p_Nj    = sym<float>(g_Nj);
    float* p_Hs    = sym<float>(g_Hs);
    float* p_EfW   = sym<float>(g_EfW);
    float* p_f     = sym<float>(g_f);
    float* p_score = sym<float>(g_score);
    float* p_alpha = sym<float>(g_alpha);
    float* p_rpart = sym<float>(g_relpart);
    int*   p_inc   = sym<int>(g_inc);

    bf16 *enth = sym<bf16>(g_enth), *entl = sym<bf16>(g_entl);
    bf16 *cah  = sym<bf16>(g_cah),  *cal  = sym<bf16>(g_cal);
    bf16 *cih  = sym<bf16>(g_cih),  *cil  = sym<bf16>(g_cil);
    bf16 *nouth= sym<bf16>(g_nouth),*noutl= sym<bf16>(g_noutl);
    bf16 *nch  = sym<bf16>(g_newcih),*ncl = sym<bf16>(g_newcil);
    bf16 *ctxh = sym<bf16>(g_ctxh), *ctxl = sym<bf16>(g_ctxl);
    bf16 *Whbh = sym<bf16>(g_Whbh), *Whbl = sym<bf16>(g_Whbl);
    bf16 *Wtbh = sym<bf16>(g_Wtbh), *Wtbl = sym<bf16>(g_Wtbl);
    bf16 *Whh  = sym<bf16>(g_Whh),  *Whl  = sym<bf16>(g_Whl);
    bf16 *Wth  = sym<bf16>(g_Wth),  *Wtl  = sym<bf16>(g_Wtl);
    bf16 *Wfijh= sym<bf16>(g_Wfijh),*Wfijl= sym<bf16>(g_Wfijl);
    bf16 *Wnih = sym<bf16>(g_Wnih), *Wnil = sym<bf16>(g_Wnil);
    bf16 *Wnjh = sym<bf16>(g_Wnjh), *Wnjl = sym<bf16>(g_Wnjl);
    bf16 *Wnodeh=sym<bf16>(g_Wnodeh),*Wnodel=sym<bf16>(g_Wnodel);
    bf16 *Wpadh= sym<bf16>(g_Wpadh),*Wpadl= sym<bf16>(g_Wpadl);
    bf16 *Ph   = sym<bf16>(g_Ph),   *Pl   = sym<bf16>(g_Pl);

    // ---- pooling + weight conversion ----
    k_entity<<<Bq*NEq, 256>>>(ctx, mm, em, p_ent, enth, entl);
    k_cur<<<Bq*Hq*NEq, 256>>>(att, mm, em, p_cur);
    k_ca<<<Bq*Pq, 256>>>(p_cur, hts, cah, cal);
    splitw(ctx,   ctxh,  ctxl,  (long)Bq*Lq*Dq);
    splitw(Whb,   Whbh,  Whbl,  (long)2*Dq*Dq);
    splitw(Wtb,   Wtbh,  Wtbl,  (long)2*Dq*Dq);
    splitw(Wh,    Whh,   Whl,   (long)2*Dq*Dq);
    splitw(Wt,    Wth,   Wtl,   (long)2*Dq*Dq);
    splitw(Wfij,  Wfijh, Wfijl, (long)Dq*Dq);
    splitw(Wni,   Wnih,  Wnil,  (long)Dq*Dq);
    splitw(Wnj,   Wnjh,  Wnjl,  (long)Dq*Dq);
    splitw(Wnode, Wnodeh,Wnodel,(long)Dq*Dq);
    k_wpadsplit<<<(int)(((long)Hq*4096*128)/256), 256>>>(Wrel, Wpadh, Wpadl);
    k_inc<<<1, 32>>>(hts, p_inc);

    // ---- ci = ca @ ctx (batched over B), split output ----
    {
        GemmP g = {};
        for (int z = 0; z < Bq; z++) {
            g.Ah[z] = cah + (long)z*Pq*Lq;  g.Al[z] = cal + (long)z*Pq*Lq;
            g.Bh[z] = ctxh + (long)z*Lq*Dq; g.Bl[z] = ctxl + (long)z*Lq*Dq;
            g.C[z]  = p_ci + (long)z*Pq*Dq;
            g.Chi[z]= cih  + (long)z*Pq*Dq; g.Clo[z]= cil + (long)z*Pq*Dq;
            g.Mz[z] = Pq;
        }
        g.K = Lq; g.ldb = Dq; g.ldc = Dq; g.act = 0; g.splitout = 1;
        k_mma<0><<<dim3(6, 5, 4), 256>>>(g);
    }

    // ---- binary classifier pair (fused concat gather) ----
    {
        GemmP g = {};
        g.Bh[0] = Whbh; g.Bl[0] = Whbl; g.bias[0] = bhb; g.C[0] = p_bh; g.Mz[0] = NPq;
        g.Bh[1] = Wtbh; g.Bl[1] = Wtbl; g.bias[1] = btb; g.C[1] = p_bt; g.Mz[1] = NPq;
        g.feath = enth; g.featl = entl; g.ciXh = cih; g.ciXl = cil; g.hts = hts;
        g.K = 2*Dq; g.ldb = Dq; g.ldc = Dq; g.act = 1;
        k_mma<1><<<dim3(6, 18, 2), 256>>>(g);
    }
    k_gbl_bin<<<NPq, 256>>>(p_bh, p_bt, Wbin, bbin, outBin, p_mask);

    // ---- EGAT linear layers: EfW (M=2208) + Ni/Nj/Hs (M=96) ----
    {
        GemmP g = {};
        g.Ah[0] = cih;  g.Al[0] = cil;  g.Bh[0] = Wfijh;  g.Bl[0] = Wfijl;  g.C[0] = p_EfW; g.Mz[0] = NPq;
        g.Ah[1] = enth; g.Al[1] = entl; g.Bh[1] = Wnih;   g.Bl[1] = Wnil;   g.C[1] = p_Ni;  g.Mz[1] = Bq*NEq;
        g.Ah[2] = enth; g.Al[2] = entl; g.Bh[2] = Wnjh;   g.Bl[2] = Wnjl;   g.C[2] = p_Nj;  g.Mz[2] = Bq*NEq;
        g.Ah[3] = enth; g.Al[3] = entl; g.Bh[3] = Wnodeh; g.Bl[3] = Wnodel; g.C[3] = p_Hs;  g.Mz[3] = Bq*NEq;
        g.K = Dq; g.ldb = Dq; g.ldc = Dq;
        k_mma<0><<<dim3(6, 18, 4), 256>>>(g);
    }
    k_f<<<Bq*Eq, 256>>>(p_Ni, p_Nj, p_EfW, egat_b, hts, p_f);
    k_score<<<Bq*Eq, 384>>>(p_f, attn_p, p_mask, p_score);
    k_soft<<<Bq*NEq, 384>>>(p_score, p_inc, p_mask, p_alpha);
    k_nodeout<<<Bq*NEq, 256>>>(p_alpha, p_Hs, p_inc, hts, nouth, noutl);

    // ---- relation head ----
    k_newci<<<NPq*Dq/256, 256>>>(p_mask, p_f, p_ci, nch, ncl);
    {
        GemmP g = {};
        g.Bh[0] = Whh; g.Bl[0] = Whl; g.bias[0] = bh; g.C[0] = p_bh; g.Mz[0] = NPq;
        g.Bh[1] = Wth; g.Bl[1] = Wtl; g.bias[1] = bt; g.C[1] = p_bt; g.Mz[1] = NPq;
        g.feath = nouth; g.featl = noutl; g.ciXh = nch; g.ciXl = ncl; g.hts = hts;
        g.K = 2*Dq; g.ldb = Dq; g.ldc = Dq; g.act = 1;
        k_mma<1><<<dim3(6, 18, 2), 256>>>(g);
    }
    k_outer<<<Hq*NPq, 128>>>(p_bh, p_bt, Ph, Pl);
    {
        GemmP g = {};
        g.Ah[0] = Ph; g.Al[0] = Pl; g.Bh[0] = Wpadh; g.Bl[0] = Wpadl;
        g.C[0] = p_rpart; g.Mz[0] = NPq;
        g.sA = (long)NPq*4096; g.sB = (long)4096*128; g.sC = (long)NPq*128;
        g.K = 4096; g.ldb = 128; g.ldc = 128;
        k_mma<2><<<dim3(1, 18, Hq), 256>>>(g);
    }
    k_rel_reduce<<<((long)NPq*Rq + 255)/256, 256>>>(p_rpart, brel, outRel);
}

// round 5
// speedup vs baseline: 1.8723x; 1.0021x over previous
#include <cuda_runtime.h>
#include <cuda_bf16.h>
#include <math.h>

// ---------------- problem constants ----------------
#define Bq   4
#define Lq   1024
#define Dq   768
#define Hq   12
#define BSq  64
#define Mq   48
#define NEq  24
#define Pq   552      // NE*(NE-1)
#define Eq   576      // P + NE self loops
#define Rq   97
#define NPq  (Bq*Pq)  // 2208

typedef __nv_bfloat16 bf16;

// ---------------- scratch (device globals; no allocation) ----------------
__device__ float g_entity [Bq*NEq*Dq];
__device__ float g_cur    [Bq*Hq*NEq*Lq];
__device__ float g_ci     [NPq*Dq];
__device__ float g_bh     [NPq*Dq];
__device__ float g_bt     [NPq*Dq];
__device__ int   g_mask   [NPq];
__device__ float g_Ni     [Bq*NEq*Dq];
__device__ float g_Nj     [Bq*NEq*Dq];
__device__ float g_Hs     [Bq*NEq*Dq];
__device__ float g_EfW    [NPq*Dq];
__device__ float g_f      [Bq*Eq*Dq];
__device__ float g_score  [Bq*Eq*Hq];
__device__ float g_alpha  [Bq*Eq*Hq];
__device__ float g_relpart[(size_t)Hq*NPq*128];
__device__ int   g_inc    [NEq*23];

// bf16 split buffers (hi/lo)
__device__ bf16 g_enth[Bq*NEq*Dq],      g_entl[Bq*NEq*Dq];
__device__ bf16 g_cah [Bq*Pq*Lq],       g_cal [Bq*Pq*Lq];
__device__ bf16 g_cih [NPq*Dq],         g_cil [NPq*Dq];
__device__ bf16 g_nouth[Bq*NEq*Dq],     g_noutl[Bq*NEq*Dq];
__device__ bf16 g_newcih[NPq*Dq],       g_newcil[NPq*Dq];
__device__ bf16 g_ctxh[Bq*Lq*Dq],       g_ctxl[Bq*Lq*Dq];
__device__ bf16 g_Whbh[2*Dq*Dq],        g_Whbl[2*Dq*Dq];
__device__ bf16 g_Wtbh[2*Dq*Dq],        g_Wtbl[2*Dq*Dq];
__device__ bf16 g_Whh [2*Dq*Dq],        g_Whl [2*Dq*Dq];
__device__ bf16 g_Wth [2*Dq*Dq],        g_Wtl [2*Dq*Dq];
__device__ bf16 g_Wfijh[Dq*Dq],         g_Wfijl[Dq*Dq];
__device__ bf16 g_Wnih[Dq*Dq],          g_Wnil[Dq*Dq];
__device__ bf16 g_Wnjh[Dq*Dq],          g_Wnjl[Dq*Dq];
__device__ bf16 g_Wnodeh[Dq*Dq],        g_Wnodel[Dq*Dq];
__device__ bf16 g_Wpadh[(size_t)Hq*4096*128], g_Wpadl[(size_t)Hq*4096*128];
__device__ bf16 g_Ph[(size_t)Hq*NPq*4096],    g_Pl[(size_t)Hq*NPq*4096];

// ---------------- helpers ----------------
__device__ __forceinline__ void split2(float x, bf16& h, bf16& l) {
    h = __float2bfloat16(x);
    l = __float2bfloat16(x - __bfloat162float(h));
}
__device__ __forceinline__ unsigned su32(const void* p) {
    return (unsigned)__cvta_generic_to_shared(p);
}
__device__ __forceinline__ void ldmx4(unsigned* r, unsigned addr) {
    asm volatile("ldmatrix.sync.aligned.m8n8.x4.shared.b16 {%0,%1,%2,%3}, [%4];"
        : "=r"(r[0]), "=r"(r[1]), "=r"(r[2]), "=r"(r[3]) : "r"(addr));
}
__device__ __forceinline__ void ldmx4t(unsigned* r, unsigned addr) {
    asm volatile("ldmatrix.sync.aligned.m8n8.x4.trans.shared.b16 {%0,%1,%2,%3}, [%4];"
        : "=r"(r[0]), "=r"(r[1]), "=r"(r[2]), "=r"(r[3]) : "r"(addr));
}
__device__ __forceinline__ void mma16816(float* c, const unsigned* a, const unsigned* b) {
    asm volatile("mma.sync.aligned.m16n8k16.row.col.f32.bf16.bf16.f32 "
        "{%0,%1,%2,%3}, {%4,%5,%6,%7}, {%8,%9}, {%0,%1,%2,%3};"
        : "+f"(c[0]), "+f"(c[1]), "+f"(c[2]), "+f"(c[3])
        : "r"(a[0]), "r"(a[1]), "r"(a[2]), "r"(a[3]), "r"(b[0]), "r"(b[1]));
}

// ---------------- small kernels ----------------

__global__ void k_entity(const float* __restrict__ ctx, const int* __restrict__ mm,
                         const float* __restrict__ em, float* __restrict__ out,
                         bf16* __restrict__ oh, bf16* __restrict__ ol)
{
    int bn = blockIdx.x; int b = bn / NEq, n = bn % NEq;
    __shared__ float w_s[Mq]; __shared__ int mi_s[Mq];
    if (threadIdx.x < Mq) {
        w_s[threadIdx.x]  = em[(b*NEq + n)*Mq + threadIdx.x];
        mi_s[threadIdx.x] = mm[b*Mq + threadIdx.x];
    }
    __syncthreads();
    for (int d = threadIdx.x; d < Dq; d += blockDim.x) {
        float s = 0.f;
        #pragma unroll 4
        for (int m = 0; m < Mq; m++) {
            float w = w_s[m];
            if (w != 0.f) s += w * expf(ctx[((long)b*Lq + mi_s[m])*Dq + d]);
        }
        float v = logf(s);
        out[(long)bn*Dq + d] = v;
        bf16 h, l; split2(v, h, l);
        oh[(long)bn*Dq + d] = h; ol[(long)bn*Dq + d] = l;
    }
}

__global__ void k_cur(const float* __restrict__ att, const int* __restrict__ mm,
                      const float* __restrict__ em, float* __restrict__ cur)
{
    int id = blockIdx.x;
    int n = id % NEq; int h = (id / NEq) % Hq; int b = id / (NEq*Hq);
    __shared__ int   act_m[Mq];
    __shared__ float act_w[Mq];
    __shared__ int   nact;
    __shared__ float invc;
    if (threadIdx.x == 0) {
        int c = 0; float cnt = 0.f;
        for (int m = 0; m < Mq; m++) {
            float w = em[(b*NEq + n)*Mq + m]; cnt += w;
            if (w != 0.f) { act_m[c] = mm[b*Mq + m]; act_w[c] = w; c++; }
        }
        nact = c; invc = 1.f / (cnt + 1e-20f);
    }
    __syncthreads();
    const float* abase = att + ((long)(b*Hq + h))*Lq*Lq;
    float* obase = cur + (long)id*Lq;
    int na = nact; float iv = invc;
    for (int l = threadIdx.x; l < Lq; l += blockDim.x) {
        float s = 0.f;
        for (int a = 0; a < na; a++) s += act_w[a] * abase[(long)act_m[a]*Lq + l];
        obase[l] = s * iv;
    }
}

__global__ void k_ca(const float* __restrict__ cur, const int* __restrict__ hts,
                     bf16* __restrict__ cah, bf16* __restrict__ cal)
{
    int bp = blockIdx.x; int b = bp / Pq, p = bp % Pq;
    int h0 = hts[p], h1 = hts[Pq + p];
    const float* c0 = cur + ((long)b*Hq*NEq + h0)*Lq;
    const float* c1 = cur + ((long)b*Hq*NEq + h1)*Lq;
    float v[4]; float local = 0.f;
    #pragma unroll
    for (int q = 0; q < 4; q++) {
        int l = threadIdx.x + q*256;
        float s = 0.f;
        #pragma unroll
        for (int h = 0; h < Hq; h++)
            s += c0[(long)h*NEq*Lq + l] * c1[(long)h*NEq*Lq + l];
        v[q] = s; local += s;
    }
    __shared__ float red[256];
    red[threadIdx.x] = local; __syncthreads();
    for (int off = 128; off > 0; off >>= 1) {
        if (threadIdx.x < off) red[threadIdx.x] += red[threadIdx.x + off];
        __syncthreads();
    }
    float inv = 1.f / (red[0] + 1e-20f);
    #pragma unroll
    for (int q = 0; q < 4; q++) {
        long o = (long)bp*Lq + threadIdx.x + q*256;
        bf16 h, l; split2(v[q]*inv, h, l);
        cah[o] = h; cal[o] = l;
    }
}

__global__ void k_split(const float* __restrict__ src, bf16* __restrict__ hi,
                        bf16* __restrict__ lo, long n)
{
    long i = (long)blockIdx.x*256 + threadIdx.x;
    if (i >= n) return;
    bf16 h, l; split2(src[i], h, l);
    hi[i] = h; lo[i] = l;
}

// Wrel [49152][97] -> padded split [12][4096][128]
__global__ void k_wpadsplit(const float* __restrict__ W, bf16* __restrict__ Wh,
                            bf16* __restrict__ Wl)
{
    long idx = (long)blockIdx.x*256 + threadIdx.x;   // over 12*4096*128
    int o = (int)(idx & 127);
    long row = idx >> 7;
    float v = (o < Rq) ? W[row*Rq + o] : 0.f;
    bf16 h, l; split2(v, h, l);
    Wh[idx] = h; Wl[idx] = l;
}

// ---------------- mma.sync GEMM (128x128, K-chunk 32, bf16 3-term split) ----------------
// MODE 0: table (A from table). MODE 1: table + concat gather A=[feat|ciX].
// MODE 2: strided over z (rel head).
struct GemmP {
    const bf16 *Ah[4], *Al[4], *Bh[4], *Bl[4];
    const float* bias[4];
    float* C[4];
    bf16 *Chi[4], *Clo[4];
    int Mz[4];
    const bf16 *feath, *featl, *ciXh, *ciXl;
    const int* hts;
    long sA, sB, sC;
    int K, ldb, ldc, act, splitout;
};

template<int MODE>
__global__ __launch_bounds__(256)
void k_mma(GemmP p)
{
    __shared__ bf16 Ash[128][40], Asl[128][40];
    __shared__ bf16 Bsh[32][136],  Bsl[32][136];

    int z = blockIdx.z;
    const bf16 *pBh, *pBl;
    const float* pbias; float* pC;
    bf16 *pChi = 0, *pClo = 0;
    int M;
    const bf16 *tAh = 0, *tAl = 0;
    if (MODE == 2) {
        tAh = p.Ah[0] + (long)z*p.sA;  tAl = p.Al[0] + (long)z*p.sA;
        pBh = p.Bh[0] + (long)z*p.sB;  pBl = p.Bl[0] + (long)z*p.sB;
        pC  = p.C[0]  + (long)z*p.sC;
        pbias = p.bias[0]; M = p.Mz[0];
    } else {
        tAh = p.Ah[z]; tAl = p.Al[z];
        pBh = p.Bh[z]; pBl = p.Bl[z];
        pC  = p.C[z];  pbias = p.bias[z]; M = p.Mz[z];
        if (p.splitout) { pChi = p.Chi[z]; pClo = p.Clo[z]; }
    }
    int row0 = blockIdx.y * 128;
    if (row0 >= M) return;
    int col0 = blockIdx.x * 128;
    int K = p.K, ldb = p.ldb, ldc = p.ldc;
    int t = threadIdx.x;

    // A loader: thread -> (row, 16-col half)
    int arow = t >> 1;
    int ak   = (t & 1) * 16;
    int grow = row0 + arow;
    int rowc = grow < M ? grow : M - 1;
    const bf16 *srcAh0, *srcAl0, *srcAh1 = 0, *srcAl1 = 0;
    if (MODE == 1) {
        int b = rowc / Pq, pp = rowc % Pq;
        long off = ((long)(b*NEq) + p.hts[z*Pq + pp]) * Dq;
        srcAh0 = p.feath + off;              srcAl0 = p.featl + off;
        srcAh1 = p.ciXh + (long)rowc*Dq - Dq; srcAl1 = p.ciXl + (long)rowc*Dq - Dq;
    } else {
        srcAh0 = tAh + (long)rowc*K;  srcAl0 = tAl + (long)rowc*K;
    }
    // B loader: thread -> (k-row, 16-col)
    int bk = t >> 3;
    int bn = (t & 7) * 16;

    uint4 vAh0, vAh1, vAl0, vAl1, vBh0, vBh1, vBl0, vBl1;

    #define LOAD_CHUNK(kc) do {                                                     \
        int k0 = (kc)*32 + ak;                                                      \
        const bf16 *sh, *sl;                                                        \
        if (MODE == 1 && k0 >= Dq) { sh = srcAh1 + k0; sl = srcAl1 + k0; }          \
        else                       { sh = srcAh0 + k0; sl = srcAl0 + k0; }          \
        vAh0 = *(const uint4*)sh;       vAh1 = *(const uint4*)(sh + 8);             \
        vAl0 = *(const uint4*)sl;       vAl1 = *(const uint4*)(sl + 8);             \
        const bf16* bp_ = pBh + (long)((kc)*32 + bk)*ldb + col0 + bn;               \
        const bf16* bq_ = pBl + (long)((kc)*32 + bk)*ldb + col0 + bn;               \
        vBh0 = *(const uint4*)bp_;      vBh1 = *(const uint4*)(bp_ + 8);            \
        vBl0 = *(const uint4*)bq_;      vBl1 = *(const uint4*)(bq_ + 8);            \
    } while (0)

    LOAD_CHUNK(0);

    int w = t >> 5, lane = t & 31;
    int wm = w >> 1, wn = w & 1;
    float acc[2][8][4] = {};

    int KT = K >> 5;
    for (int kc = 0; kc < KT; kc++) {
        *(uint4*)&Ash[arow][ak]     = vAh0;  *(uint4*)&Ash[arow][ak + 8] = vAh1;
        *(uint4*)&Asl[arow][ak]     = vAl0;  *(uint4*)&Asl[arow][ak + 8] = vAl1;
        *(uint4*)&Bsh[bk][bn]       = vBh0;  *(uint4*)&Bsh[bk][bn + 8]   = vBh1;
        *(uint4*)&Bsl[bk][bn]       = vBl0;  *(uint4*)&Bsl[bk][bn + 8]   = vBl1;
        __syncthreads();
        if (kc + 1 < KT) LOAD_CHUNK(kc + 1);

        #pragma unroll
        for (int s = 0; s < 2; s++) {
            unsigned ah[2][4], al[2][4];
            int arw = wm*32 + (lane & 15);
            int acl = s*16 + (lane >> 4)*8;
            ldmx4(ah[0], su32(&Ash[arw][acl]));
            ldmx4(al[0], su32(&Asl[arw][acl]));
            ldmx4(ah[1], su32(&Ash[arw + 16][acl]));
            ldmx4(al[1], su32(&Asl[arw + 16][acl]));
            int brow = s*16 + ((lane >> 3) & 1)*8 + (lane & 7);
            int bcol = wn*64 + (lane >> 4)*8;
            #pragma unroll
            for (int g = 0; g < 4; g++) {
                unsigned bh_[4], bl_[4];
                ldmx4t(bh_, su32(&Bsh[brow][bcol + g*16]));
                ldmx4t(bl_, su32(&Bsl[brow][bcol + g*16]));
                #pragma unroll
                for (int mt = 0; mt < 2; mt++) {
                    mma16816(acc[mt][2*g],   ah[mt], bh_);
                    mma16816(acc[mt][2*g],   ah[mt], bl_);
                    mma16816(acc[mt][2*g],   al[mt], bh_);
                    mma16816(acc[mt][2*g+1], ah[mt], bh_ + 2);
                    mma16816(acc[mt][2*g+1], ah[mt], bl_ + 2);
                    mma16816(acc[mt][2*g+1], al[mt], bh_ + 2);
                }
            }
        }
        __syncthreads();
    }
    #undef LOAD_CHUNK

    int rg = row0 + wm*32 + (lane >> 2);
    int cb = col0 + wn*64 + (lane & 3)*2;
    #pragma unroll
    for (int mt = 0; mt < 2; mt++) {
        #pragma unroll
        for (int n8 = 0; n8 < 8; n8++) {
            int rr = rg + mt*16;
            int cc = cb + n8*8;
            float v0 = acc[mt][n8][0], v1 = acc[mt][n8][1];
            float v2 = acc[mt][n8][2], v3 = acc[mt][n8][3];
            if (pbias) {
                float b0 = pbias[cc], b1 = pbias[cc+1];
                v0 += b0; v1 += b1; v2 += b0; v3 += b1;
            }
            if (p.act) { v0 = tanhf(v0); v1 = tanhf(v1); v2 = tanhf(v2); v3 = tanhf(v3); }
            if (rr < M) {
                *(float2*)(pC + (long)rr*ldc + cc) = make_float2(v0, v1);
                if (pChi) {
                    bf16 h0,l0,h1,l1; split2(v0,h0,l0); split2(v1,h1,l1);
                    *(__nv_bfloat162*)(pChi + (long)rr*ldc + cc) = __nv_bfloat162(h0, h1);
                    *(__nv_bfloat162*)(pClo + (long)rr*ldc + cc) = __nv_bfloat162(l0, l1);
                }
            }
            if (rr + 8 < M) {
                *(float2*)(pC + (long)(rr+8)*ldc + cc) = make_float2(v2, v3);
                if (pChi) {
                    bf16 h0,l0,h1,l1; split2(v2,h0,l0); split2(v3,h1,l1);
                    *(__nv_bfloat162*)(pChi + (long)(rr+8)*ldc + cc) = __nv_bfloat162(h0, h1);
                    *(__nv_bfloat162*)(pClo + (long)(rr+8)*ldc + cc) = __nv_bfloat162(l0, l1);
                }
            }
        }
    }
}

// ---------------- group bilinear binary head (fp32) ----------------
__global__ void k_gbl_bin(const float* __restrict__ A, const float* __restrict__ C,
                          const float* __restrict__ W, const float* __restrict__ bias,
                          float* __restrict__ out, int* __restrict__ mask)
{
    int n = blockIdx.x;
    __shared__ float a_s[Dq], c_s[Dq];
    for (int d = threadIdx.x; d < Dq; d += 256) {
        a_s[d] = A[(long)n*Dq + d];
        c_s[d] = C[(long)n*Dq + d];
    }
    __syncthreads();
    float s0 = 0.f, s1 = 0.f;
    for (int hi = threadIdx.x; hi < Dq; hi += 256) {
        float ai = a_s[hi];
        const float2* w2 = (const float2*)(W + (long)hi*BSq*2);
        const float* cc = c_s + (hi & ~63);
        #pragma unroll 8
        for (int j = 0; j < BSq; j++) {
            float v = ai * cc[j];
            float2 ww = w2[j];
            s0 += v*ww.x; s1 += v*ww.y;
        }
    }
    __shared__ float r0[256], r1[256];
    r0[threadIdx.x] = s0; r1[threadIdx.x] = s1; __syncthreads();
    for (int off = 128; off > 0; off >>= 1) {
        if (threadIdx.x < off) { r0[threadIdx.x] += r0[threadIdx.x+off]; r1[threadIdx.x] += r1[threadIdx.x+off]; }
        __syncthreads();
    }
    if (threadIdx.x == 0) {
        float b0 = r0[0] + bias[0], b1 = r1[0] + bias[1];
        out[n*2]   = b0;
        out[n*2+1] = b1;
        mask[n] = (b1 > b0) ? 1 : 0;
    }
}

__global__ void k_inc(const int* __restrict__ hts, int* __restrict__ inc)
{
    if (threadIdx.x == 0 && blockIdx.x == 0) {
        int cnt[NEq];
        for (int i = 0; i < NEq; i++) cnt[i] = 0;
        for (int p = 0; p < Pq; p++) {
            int d = hts[Pq + p];
            inc[d*23 + cnt[d]++] = p;
        }
    }
}

__global__ void k_f(const float* __restrict__ Ni, const float* __restrict__ Nj,
                    const float* __restrict__ EfW, const float* __restrict__ eb,
                    const int* __restrict__ hts, float* __restrict__ f)
{
    int be = blockIdx.x; int b = be / Eq, e = be % Eq;
    int src, dst; const float* ef = 0;
    if (e < Pq) { src = hts[e]; dst = hts[Pq + e]; ef = EfW + ((long)b*Pq + e)*Dq; }
    else        { src = dst = e - Pq; }
    const float* ni = Ni + ((long)b*NEq + src)*Dq;
    const float* nj = Nj + ((long)b*NEq + dst)*Dq;
    float* o = f + (long)be*Dq;
    for (int d = threadIdx.x; d < Dq; d += blockDim.x) {
        float v = ni[d] + nj[d] + eb[d];
        if (ef) v += ef[d];
        o[d] = v;
    }
}

__global__ void k_score(const float* __restrict__ f, const float* __restrict__ attn_p,
                        const int* __restrict__ mask, float* __restrict__ score)
{
    int be = blockIdx.x; int b = be / Eq, e = be % Eq;
    int h = threadIdx.x >> 5, lane = threadIdx.x & 31;
    const float* fr = f + (long)be*Dq + h*BSq;
    float s = 0.f;
    #pragma unroll
    for (int i = lane; i < BSq; i += 32) {
        float x = fr[i];
        float lr = x > 0.f ? x : 0.2f*x;
        s += lr * attn_p[h*BSq + i];
    }
    #pragma unroll
    for (int off = 16; off; off >>= 1) s += __shfl_xor_sync(0xffffffffu, s, off);
    if (lane == 0) {
        int m = (e < Pq) ? mask[b*Pq + e] : 1;
        score[(long)be*Hq + h] = m ? s : -1e30f;
    }
}

__global__ void k_soft(const float* __restrict__ score, const int* __restrict__ inc,
                       const int* __restrict__ mask, float* __restrict__ alpha)
{
    int bn = blockIdx.x; int b = bn / NEq, n = bn % NEq;
    int h = threadIdx.x >> 5, lane = threadIdx.x & 31;
    int eid = 0; float sc = -INFINITY; float m = 0.f;
    if (lane < 24) {
        eid = (lane < 23) ? inc[n*23 + lane] : (Pq + n);
        sc  = score[((long)b*Eq + eid)*Hq + h];
        m   = (eid < Pq) ? (float)mask[b*Pq + eid] : 1.f;
    }
    float mx = sc;
    #pragma unroll
    for (int off = 16; off; off >>= 1) mx = fmaxf(mx, __shfl_xor_sync(0xffffffffu, mx, off));
    float ex = (lane < 24) ? expf(sc - mx)*m : 0.f;
    float den = ex;
    #pragma unroll
    for (int off = 16; off; off >>= 1) den += __shfl_xor_sync(0xffffffffu, den, off);
    if (lane < 24) alpha[((long)b*Eq + eid)*Hq + h] = ex / (den + 1e-20f);
}

__global__ void k_nodeout(const float* __restrict__ alpha, const float* __restrict__ Hsrc,
                          const int* __restrict__ inc, const int* __restrict__ hts,
                          bf16* __restrict__ oh, bf16* __restrict__ ol)
{
    int bn = blockIdx.x; int b = bn / NEq, n = bn % NEq;
    __shared__ int   esrc[24];
    __shared__ float eal[24*Hq];
    int t = threadIdx.x;
    if (t < 24) {
        int eid = (t < 23) ? inc[n*23 + t] : (Pq + n);
        esrc[t] = (t < 23) ? hts[eid] : n;
    }
    for (int t2 = t; t2 < 24*Hq; t2 += blockDim.x) {
        int slot = t2 / Hq, hh = t2 % Hq;
        int eid = (slot < 23) ? inc[n*23 + slot] : (Pq + n);
        eal[t2] = alpha[((long)b*Eq + eid)*Hq + hh];
    }
    __syncthreads();
    for (int d = t; d < Dq; d += blockDim.x) {
        int h = d >> 6;
        float s = 0.f;
        #pragma unroll
        for (int slot = 0; slot < 24; slot++)
            s += eal[slot*Hq + h] * Hsrc[((long)b*NEq + esrc[slot])*Dq + d];
        bf16 hh, ll; split2(s, hh, ll);
        oh[(long)bn*Dq + d] = hh; ol[(long)bn*Dq + d] = ll;
    }
}

__global__ void k_newci(const int* __restrict__ mask, const float* __restrict__ f,
                        const float* __restrict__ ci, bf16* __restrict__ oh,
                        bf16* __restrict__ ol)
{
    long idx = (long)blockIdx.x*256 + threadIdx.x;
    int d = (int)(idx % Dq); long n = idx / Dq;
    int b = (int)(n / Pq), p = (int)(n % Pq);
    float v = mask[n] ? f[((long)b*Eq + p)*Dq + d] : ci[idx];
    bf16 h, l; split2(v, h, l);
    oh[idx] = h; ol[idx] = l;
}

// P[h][n][i*64+j] = bh[n][h*64+i] * bt[n][h*64+j], split bf16
__global__ void k_outer(const float* __restrict__ bh, const float* __restrict__ bt,
                        bf16* __restrict__ Ph, bf16* __restrict__ Pl)
{
    int blk = blockIdx.x;              // h*NP + n
    int h = blk / NPq, n = blk % NPq;
    __shared__ float a_s[64], c_s[64];
    int t = threadIdx.x;
    if (t < 64)                a_s[t]      = bh[(long)n*Dq + h*64 + t];
    else if (t < 128)          c_s[t - 64] = bt[(long)n*Dq + h*64 + (t - 64)];
    __syncthreads();
    long base = ((long)h*NPq + n)*4096;
    for (int idx = t; idx < 4096; idx += 128) {
        float v = a_s[idx >> 6] * c_s[idx & 63];
        bf16 hh, ll; split2(v, hh, ll);
        Ph[base + idx] = hh; Pl[base + idx] = ll;
    }
}

__global__ void k_rel_reduce(const float* __restrict__ part, const float* __restrict__ brel,
                             float* __restrict__ out)
{
    long idx = (long)blockIdx.x*256 + threadIdx.x;
    if (idx >= (long)NPq*Rq) return;
    int o = (int)(idx % Rq);
    long n = idx / Rq;
    float s = brel[o];
    #pragma unroll
    for (int h = 0; h < Hq; h++) s += part[((long)h*NPq + n)*128 + o];
    out[idx] = s;
}

// ---------------- host ----------------
template <typename T>
static T* sym(const void* s) { void* p = 0; cudaGetSymbolAddress(&p, s); return (T*)p; }

static void splitw(const float* src, bf16* hi, bf16* lo, long n)
{
    k_split<<<(int)((n + 255)/256), 256>>>(src, hi, lo, n);
}

extern "C" void kernel_launch(void* const* d_in, const int* in_sizes, int n_in,
                              void* d_out, int out_size)
{
    const float* ctx    = (const float*)d_in[0];
    const float* att    = (const float*)d_in[1];
    const int*   mm     = (const int*)  d_in[2];
    const float* em     = (const float*)d_in[3];
    const int*   hts    = (const int*)  d_in[4];
    const float* Whb    = (const float*)d_in[5];
    const float* bhb    = (const float*)d_in[6];
    const float* Wtb    = (const float*)d_in[7];
    const float* btb    = (const float*)d_in[8];
    const float* Wbin   = (const float*)d_in[9];
    const float* bbin   = (const float*)d_in[10];
    const float* Wrel   = (const float*)d_in[11];
    const float* brel   = (const float*)d_in[12];
    const float* Wh     = (const float*)d_in[13];
    const float* bh     = (const float*)d_in[14];
    const float* Wt     = (const float*)d_in[15];
    const float* bt     = (const float*)d_in[16];
    const float* Wnode  = (const float*)d_in[17];
    const float* Wni    = (const float*)d_in[18];
    const float* Wfij   = (const float*)d_in[19];
    const float* Wnj    = (const float*)d_in[20];
    const float* attn_p = (const float*)d_in[21];
    const float* egat_b = (const float*)d_in[22];

    float* outBin = (float*)d_out;
    float* outRel = outBin + (long)NPq*2;

    float* p_ent   = sym<float>(g_entity);
    float* p_cur   = sym<float>(g_cur);
    float* p_ci    = sym<float>(g_ci);
    float* p_bh    = sym<float>(g_bh);
    float* p_bt    = sym<float>(g_bt);
    int*   p_mask  = sym<int>(g_mask);
    float* p_Ni    = sym<float>(g_Ni);
    float* p_Nj    = sym<float>(g_Nj);
    float* p_Hs    = sym<float>(g_Hs);
    float* p_EfW   = sym<float>(g_EfW);
    float* p_f     = sym<float>(g_f);
    float* p_score = sym<float>(g_score);
    float* p_alpha = sym<float>(g_alpha);
    float* p_rpart = sym<float>(g_relpart);
    int*   p_inc   = sym<int>(g_inc);

    bf16 *enth = sym<bf16>(g_enth), *entl = sym<bf16>(g_entl);
    bf16 *cah  = sym<bf16>(g_cah),  *cal  = sym<bf16>(g_cal);
    bf16 *cih  = sym<bf16>(g_cih),  *cil  = sym<bf16>(g_cil);
    bf16 *nouth= sym<bf16>(g_nouth),*noutl= sym<bf16>(g_noutl);
    bf16 *nch  = sym<bf16>(g_newcih),*ncl = sym<bf16>(g_newcil);
    bf16 *ctxh = sym<bf16>(g_ctxh), *ctxl = sym<bf16>(g_ctxl);
    bf16 *Whbh = sym<bf16>(g_Whbh), *Whbl = sym<bf16>(g_Whbl);
    bf16 *Wtbh = sym<bf16>(g_Wtbh), *Wtbl = sym<bf16>(g_Wtbl);
    bf16 *Whh  = sym<bf16>(g_Whh),  *Whl  = sym<bf16>(g_Whl);
    bf16 *Wth  = sym<bf16>(g_Wth),  *Wtl  = sym<bf16>(g_Wtl);
    bf16 *Wfijh= sym<bf16>(g_Wfijh),*Wfijl= sym<bf16>(g_Wfijl);
    bf16 *Wnih = sym<bf16>(g_Wnih), *Wnil = sym<bf16>(g_Wnil);
    bf16 *Wnjh = sym<bf16>(g_Wnjh), *Wnjl = sym<bf16>(g_Wnjl);
    bf16 *Wnodeh=sym<bf16>(g_Wnodeh),*Wnodel=sym<bf16>(g_Wnodel);
    bf16 *Wpadh= sym<bf16>(g_Wpadh),*Wpadl= sym<bf16>(g_Wpadl);
    bf16 *Ph   = sym<bf16>(g_Ph),   *Pl   = sym<bf16>(g_Pl);

    // ---- pooling + weight conversion ----
    k_entity<<<Bq*NEq, 256>>>(ctx, mm, em, p_ent, enth, entl);
    k_cur<<<Bq*Hq*NEq, 256>>>(att, mm, em, p_cur);
    k_ca<<<Bq*Pq, 256>>>(p_cur, hts, cah, cal);
    splitw(ctx,   ctxh,  ctxl,  (long)Bq*Lq*Dq);
    splitw(Whb,   Whbh,  Whbl,  (long)2*Dq*Dq);
    splitw(Wtb,   Wtbh,  Wtbl,  (long)2*Dq*Dq);
    splitw(Wh,    Whh,   Whl,   (long)2*Dq*Dq);
    splitw(Wt,    Wth,   Wtl,   (long)2*Dq*Dq);
    splitw(Wfij,  Wfijh, Wfijl, (long)Dq*Dq);
    splitw(Wni,   Wnih,  Wnil,  (long)Dq*Dq);
    splitw(Wnj,   Wnjh,  Wnjl,  (long)Dq*Dq);
    splitw(Wnode, Wnodeh,Wnodel,(long)Dq*Dq);
    k_wpadsplit<<<(int)(((long)Hq*4096*128)/256), 256>>>(Wrel, Wpadh, Wpadl);
    k_inc<<<1, 32>>>(hts, p_inc);

    // ---- ci = ca @ ctx (batched over B), split output ----
    {
        GemmP g = {};
        for (int z = 0; z < Bq; z++) {
            g.Ah[z] = cah + (long)z*Pq*Lq;  g.Al[z] = cal + (long)z*Pq*Lq;
            g.Bh[z] = ctxh + (long)z*Lq*Dq; g.Bl[z] = ctxl + (long)z*Lq*Dq;
            g.C[z]  = p_ci + (long)z*Pq*Dq;
            g.Chi[z]= cih  + (long)z*Pq*Dq; g.Clo[z]= cil + (long)z*Pq*Dq;
            g.Mz[z] = Pq;
        }
        g.K = Lq; g.ldb = Dq; g.ldc = Dq; g.act = 0; g.splitout = 1;
        k_mma<0><<<dim3(6, 5, 4), 256>>>(g);
    }

    // ---- binary classifier pair (fused concat gather) ----
    {
        GemmP g = {};
        g.Bh[0] = Whbh; g.Bl[0] = Whbl; g.bias[0] = bhb; g.C[0] = p_bh; g.Mz[0] = NPq;
        g.Bh[1] = Wtbh; g.Bl[1] = Wtbl; g.bias[1] = btb; g.C[1] = p_bt; g.Mz[1] = NPq;
        g.feath = enth; g.featl = entl; g.ciXh = cih; g.ciXl = cil; g.hts = hts;
        g.K = 2*Dq; g.ldb = Dq; g.ldc = Dq; g.act = 1;
        k_mma<1><<<dim3(6, 18, 2), 256>>>(g);
    }
    k_gbl_bin<<<NPq, 256>>>(p_bh, p_bt, Wbin, bbin, outBin, p_mask);

    // ---- EGAT linear layers: EfW (M=2208) + Ni/Nj/Hs (M=96) ----
    {
        GemmP g = {};
        g.Ah[0] = cih;  g.Al[0] = cil;  g.Bh[0] = Wfijh;  g.Bl[0] = Wfijl;  g.C[0] = p_EfW; g.Mz[0] = NPq;
        g.Ah[1] = enth; g.Al[1] = entl; g.Bh[1] = Wnih;   g.Bl[1] = Wnil;   g.C[1] = p_Ni;  g.Mz[1] = Bq*NEq;
        g.Ah[2] = enth; g.Al[2] = entl; g.Bh[2] = Wnjh;   g.Bl[2] = Wnjl;   g.C[2] = p_Nj;  g.Mz[2] = Bq*NEq;
        g.Ah[3] = enth; g.Al[3] = entl; g.Bh[3] = Wnodeh; g.Bl[3] = Wnodel; g.C[3] = p_Hs;  g.Mz[3] = Bq*NEq;
        g.K = Dq; g.ldb = Dq; g.ldc = Dq;
        k_mma<0><<<dim3(6, 18, 4), 256>>>(g);
    }
    k_f<<<Bq*Eq, 256>>>(p_Ni, p_Nj, p_EfW, egat_b, hts, p_f);
    k_score<<<Bq*Eq, 384>>>(p_f, attn_p, p_mask, p_score);
    k_soft<<<Bq*NEq, 384>>>(p_score, p_inc, p_mask, p_alpha);
    k_nodeout<<<Bq*NEq, 256>>>(p_alpha, p_Hs, p_inc, hts, nouth, noutl);

    // ---- relation head ----
    k_newci<<<NPq*Dq/256, 256>>>(p_mask, p_f, p_ci, nch, ncl);
    {
        GemmP g = {};
        g.Bh[0] = Whh; g.Bl[0] = Whl; g.bias[0] = bh; g.C[0] = p_bh; g.Mz[0] = NPq;
        g.Bh[1] = Wth; g.Bl[1] = Wtl; g.bias[1] = bt; g.C[1] = p_bt; g.Mz[1] = NPq;
        g.feath = nouth; g.featl = noutl; g.ciXh = nch; g.ciXl = ncl; g.hts = hts;
        g.K = 2*Dq; g.ldb = Dq; g.ldc = Dq; g.act = 1;
        k_mma<1><<<dim3(6, 18, 2), 256>>>(g);
    }
    k_outer<<<Hq*NPq, 128>>>(p_bh, p_bt, Ph, Pl);
    {
        GemmP g = {};
        g.Ah[0] = Ph; g.Al[0] = Pl; g.Bh[0] = Wpadh; g.Bl[0] = Wpadl;
        g.C[0] = p_rpart; g.Mz[0] = NPq;
        g.sA = (long)NPq*4096; g.sB = (long)4096*128; g.sC = (long)NPq*128;
        g.K = 4096; g.ldb = 128; g.ldc = 128;
        k_mma<2><<<dim3(1, 18, Hq), 256>>>(g);
    }
    k_rel_reduce<<<((long)NPq*Rq + 255)/256, 256>>>(p_rpart, brel, outRel);
}

// round 6
// speedup vs baseline: 2.4011x; 1.2824x over previous
#include <cuda_runtime.h>
#include <cuda_bf16.h>
#include <math.h>

#define Bq   4
#define Lq   1024
#define Dq   768
#define Hq   12
#define BSq  64
#define Mq   48
#define NEq  24
#define Pq   552
#define Eq   576
#define Rq   97
#define NPq  2208

typedef __nv_bfloat16 bf16;

// ---------------- scratch ----------------
__device__ float g_cur    [Bq*Hq*NEq*Lq];
__device__ float g_ci     [NPq*Dq];
__device__ float g_bh     [NPq*Dq];
__device__ float g_bt     [NPq*Dq];
__device__ int   g_mask   [NPq];
__device__ float g_Ni     [Bq*NEq*Dq];
__device__ float g_Nj     [Bq*NEq*Dq];
__device__ float g_Hs     [Bq*NEq*Dq];
__device__ float g_EfW    [NPq*Dq];
__device__ float g_f      [Bq*Eq*Dq];
__device__ float g_score  [Bq*Eq*Hq];
__device__ float g_alpha  [Bq*Eq*Hq];
__device__ float g_relpart[(size_t)Hq*NPq*128];
__device__ int   g_inc    [NEq*23];
__device__ float g_Ebh[96*Dq], g_Ebt[96*Dq], g_Erh[96*Dq], g_Ert[96*Dq];

__device__ bf16 g_enth[Bq*NEq*Dq],   g_entl[Bq*NEq*Dq];
__device__ bf16 g_cah [Bq*Pq*Lq],    g_cal [Bq*Pq*Lq];
__device__ bf16 g_cih [NPq*Dq],      g_cil [NPq*Dq];
__device__ bf16 g_nouth[Bq*NEq*Dq],  g_noutl[Bq*NEq*Dq];
__device__ bf16 g_nch[NPq*Dq],       g_ncl[NPq*Dq];
__device__ bf16 g_ctxh[Bq*Lq*Dq],    g_ctxl[Bq*Lq*Dq];
__device__ bf16 g_Whbh[2*Dq*Dq],     g_Whbl[2*Dq*Dq];
__device__ bf16 g_Wtbh[2*Dq*Dq],     g_Wtbl[2*Dq*Dq];
__device__ bf16 g_Whh [2*Dq*Dq],     g_Whl [2*Dq*Dq];
__device__ bf16 g_Wth [2*Dq*Dq],     g_Wtl [2*Dq*Dq];
__device__ bf16 g_Wfijh[Dq*Dq],      g_Wfijl[Dq*Dq];
__device__ bf16 g_Wnih[Dq*Dq],       g_Wnil[Dq*Dq];
__device__ bf16 g_Wnjh[Dq*Dq],       g_Wnjl[Dq*Dq];
__device__ bf16 g_Wnodeh[Dq*Dq],     g_Wnodel[Dq*Dq];
__device__ bf16 g_Wpadh[(size_t)Hq*4096*128], g_Wpadl[(size_t)Hq*4096*128];

// ---------------- helpers ----------------
__device__ __forceinline__ void split2(float x, bf16& h, bf16& l) {
    h = __float2bfloat16(x);
    l = __float2bfloat16(x - __bfloat162float(h));
}
__device__ __forceinline__ unsigned su32(const void* p) {
    return (unsigned)__cvta_generic_to_shared(p);
}
__device__ __forceinline__ void ldmx4(unsigned* r, unsigned a) {
    asm volatile("ldmatrix.sync.aligned.m8n8.x4.shared.b16 {%0,%1,%2,%3}, [%4];"
        : "=r"(r[0]), "=r"(r[1]), "=r"(r[2]), "=r"(r[3]) : "r"(a));
}
__device__ __forceinline__ void ldmx4t(unsigned* r, unsigned a) {
    asm volatile("ldmatrix.sync.aligned.m8n8.x4.trans.shared.b16 {%0,%1,%2,%3}, [%4];"
        : "=r"(r[0]), "=r"(r[1]), "=r"(r[2]), "=r"(r[3]) : "r"(a));
}
__device__ __forceinline__ void mma16816(float* c, const unsigned* a, const unsigned* b) {
    asm volatile("mma.sync.aligned.m16n8k16.row.col.f32.bf16.bf16.f32 "
        "{%0,%1,%2,%3}, {%4,%5,%6,%7}, {%8,%9}, {%0,%1,%2,%3};"
        : "+f"(c[0]), "+f"(c[1]), "+f"(c[2]), "+f"(c[3])
        : "r"(a[0]), "r"(a[1]), "r"(a[2]), "r"(a[3]), "r"(b[0]), "r"(b[1]));
}
__device__ __forceinline__ uint4 pack8(const bf16* x) {
    uint4 u;
    u.x = ((unsigned)__bfloat16_as_ushort(x[1]) << 16) | __bfloat16_as_ushort(x[0]);
    u.y = ((unsigned)__bfloat16_as_ushort(x[3]) << 16) | __bfloat16_as_ushort(x[2]);
    u.z = ((unsigned)__bfloat16_as_ushort(x[5]) << 16) | __bfloat16_as_ushort(x[4]);
    u.w = ((unsigned)__bfloat16_as_ushort(x[7]) << 16) | __bfloat16_as_ushort(x[6]);
    return u;
}

// ---------------- small kernels ----------------
__global__ void k_entity(const float* __restrict__ ctx, const int* __restrict__ mm,
                         const float* __restrict__ em,
                         bf16* __restrict__ oh, bf16* __restrict__ ol)
{
    int bn = blockIdx.x; int b = bn / NEq, n = bn % NEq;
    __shared__ float w_s[Mq]; __shared__ int mi_s[Mq];
    if (threadIdx.x < Mq) {
        w_s[threadIdx.x]  = em[(b*NEq + n)*Mq + threadIdx.x];
        mi_s[threadIdx.x] = mm[b*Mq + threadIdx.x];
    }
    __syncthreads();
    for (int d = threadIdx.x; d < Dq; d += blockDim.x) {
        float s = 0.f;
        #pragma unroll 4
        for (int m = 0; m < Mq; m++) {
            float w = w_s[m];
            if (w != 0.f) s += w * expf(ctx[((long)b*Lq + mi_s[m])*Dq + d]);
        }
        float v = logf(s);
        bf16 h, l; split2(v, h, l);
        oh[(long)bn*Dq + d] = h; ol[(long)bn*Dq + d] = l;
    }
}

__global__ void k_cur(const float* __restrict__ att, const int* __restrict__ mm,
                      const float* __restrict__ em, float* __restrict__ cur)
{
    int id = blockIdx.x;
    int n = id % NEq; int h = (id / NEq) % Hq; int b = id / (NEq*Hq);
    __shared__ int   act_m[Mq];
    __shared__ float act_w[Mq];
    __shared__ int   nact;
    __shared__ float invc;
    if (threadIdx.x == 0) {
        int c = 0; float cnt = 0.f;
        for (int m = 0; m < Mq; m++) {
            float w = em[(b*NEq + n)*Mq + m]; cnt += w;
            if (w != 0.f) { act_m[c] = mm[b*Mq + m]; act_w[c] = w; c++; }
        }
        nact = c; invc = 1.f / (cnt + 1e-20f);
    }
    __syncthreads();
    const float* abase = att + ((long)(b*Hq + h))*Lq*Lq;
    float* obase = cur + (long)id*Lq;
    int na = nact; float iv = invc;
    for (int l = threadIdx.x; l < Lq; l += blockDim.x) {
        float s = 0.f;
        for (int a = 0; a < na; a++) s += act_w[a] * abase[(long)act_m[a]*Lq + l];
        obase[l] = s * iv;
    }
}

__global__ void k_ca(const float* __restrict__ cur, const int* __restrict__ hts,
                     bf16* __restrict__ cah, bf16* __restrict__ cal)
{
    int bp = blockIdx.x; int b = bp / Pq, p = bp % Pq;
    int h0 = hts[p], h1 = hts[Pq + p];
    const float* c0 = cur + ((long)b*Hq*NEq + h0)*Lq;
    const float* c1 = cur + ((long)b*Hq*NEq + h1)*Lq;
    float v[4]; float local = 0.f;
    #pragma unroll
    for (int q = 0; q < 4; q++) {
        int l = threadIdx.x + q*256;
        float s = 0.f;
        #pragma unroll
        for (int h = 0; h < Hq; h++)
            s += c0[(long)h*NEq*Lq + l] * c1[(long)h*NEq*Lq + l];
        v[q] = s; local += s;
    }
    __shared__ float red[256];
    red[threadIdx.x] = local; __syncthreads();
    for (int off = 128; off > 0; off >>= 1) {
        if (threadIdx.x < off) red[threadIdx.x] += red[threadIdx.x + off];
        __syncthreads();
    }
    float inv = 1.f / (red[0] + 1e-20f);
    #pragma unroll
    for (int q = 0; q < 4; q++) {
        long o = (long)bp*Lq + threadIdx.x + q*256;
        bf16 h, l; split2(v[q]*inv, h, l);
        cah[o] = h; cal[o] = l;
    }
}

__global__ void k_split(const float* __restrict__ src, bf16* __restrict__ hi,
                        bf16* __restrict__ lo, long n)
{
    long i = (long)blockIdx.x*256 + threadIdx.x;
    if (i >= n) return;
    bf16 h, l; split2(src[i], h, l);
    hi[i] = h; lo[i] = l;
}

__global__ void k_wpadsplit(const float* __restrict__ W, bf16* __restrict__ Wh,
                            bf16* __restrict__ Wl)
{
    long idx = (long)blockIdx.x*256 + threadIdx.x;
    int o = (int)(idx & 127);
    long row = idx >> 7;
    float v = (o < Rq) ? W[row*Rq + o] : 0.f;
    bf16 h, l; split2(v, h, l);
    Wh[idx] = h; Wl[idx] = l;
}

// ---------------- mma.sync GEMM ----------------
// MODE 0: A from table. MODE 3: A generated = outer(bh,bt) per head z, B strided.
// MODE 4: A from table, epilogue adds gathered per-row fp32 addend Eadd[z][hts-row].
struct GemmP {
    const bf16 *Ah[4], *Al[4], *Bh[4], *Bl[4];
    const float* bias[4];
    float* C[4];
    bf16 *Chi[4], *Clo[4];
    const float* Eadd[4];
    int Mz[4];
    const int* hts;
    const float *bhp, *btp;
    long sB, sC;
    int K, ldb, ldc, act, splitout;
};

template<int MODE>
__global__ __launch_bounds__(256)
void k_mma(GemmP p)
{
    __shared__ bf16 Ash[128][40], Asl[128][40];
    __shared__ bf16 Bsh[32][136],  Bsl[32][136];
    extern __shared__ float dynf[];     // MODE 3: bhF[128*68], btF[128*68]
    float* bhF = dynf;
    float* btF = dynf + 128*68;

    int z = blockIdx.z;
    const bf16 *pBh, *pBl;
    const float* pbias = 0; float* pC;
    bf16 *pChi = 0, *pClo = 0;
    int M;
    const bf16 *tAh = 0, *tAl = 0;
    if (MODE == 3) {
        pBh = p.Bh[0] + (long)z*p.sB;  pBl = p.Bl[0] + (long)z*p.sB;
        pC  = p.C[0]  + (long)z*p.sC;
        M = p.Mz[0];
    } else {
        tAh = p.Ah[z]; tAl = p.Al[z];
        pBh = p.Bh[z]; pBl = p.Bl[z];
        pC  = p.C[z];  pbias = p.bias[z]; M = p.Mz[z];
        if (p.splitout) { pChi = p.Chi[z]; pClo = p.Clo[z]; }
    }
    int row0 = blockIdx.y * 128;
    if (row0 >= M) return;
    int col0 = blockIdx.x * 128;
    int K = p.K, ldb = p.ldb, ldc = p.ldc;
    int t = threadIdx.x;

    int arow = t >> 1;
    int ak   = (t & 1) * 16;
    int grow = row0 + arow;
    int rowc = grow < M ? grow : M - 1;
    const bf16 *srcAh0 = 0, *srcAl0 = 0;
    if (MODE != 3) {
        srcAh0 = tAh + (long)rowc*K;  srcAl0 = tAl + (long)rowc*K;
    }
    int bk = t >> 3;
    int bn = (t & 7) * 16;

    if (MODE == 3) {
        for (int idx = t; idx < 128*16; idx += 256) {
            int r = idx >> 4, q = (idx & 15) * 4;
            int rr = row0 + r; if (rr >= M) rr = M - 1;
            *(float4*)&bhF[r*68 + q] = *(const float4*)(p.bhp + (long)rr*Dq + z*64 + q);
            *(float4*)&btF[r*68 + q] = *(const float4*)(p.btp + (long)rr*Dq + z*64 + q);
        }
        __syncthreads();
    }

    uint4 vAh0, vAh1, vAl0, vAl1, vBh0, vBh1, vBl0, vBl1;

    #define LOAD_CHUNK(kc) do {                                                     \
        if (MODE == 3) {                                                            \
            int i_ = (kc) >> 1, j0_ = ((kc) & 1) * 32;                              \
            float a_ = bhF[arow*68 + i_];                                           \
            bf16 hh_[16], ll_[16];                                                  \
            _Pragma("unroll")                                                       \
            for (int q = 0; q < 16; q++) {                                          \
                float v_ = a_ * btF[arow*68 + j0_ + ak + q];                        \
                split2(v_, hh_[q], ll_[q]);                                         \
            }                                                                       \
            vAh0 = pack8(hh_); vAh1 = pack8(hh_ + 8);                               \
            vAl0 = pack8(ll_); vAl1 = pack8(ll_ + 8);                               \
        } else {                                                                    \
            const bf16 *sh = srcAh0 + (kc)*32 + ak, *sl = srcAl0 + (kc)*32 + ak;    \
            vAh0 = *(const uint4*)sh;  vAh1 = *(const uint4*)(sh + 8);              \
            vAl0 = *(const uint4*)sl;  vAl1 = *(const uint4*)(sl + 8);              \
        }                                                                           \
        const bf16* bp_ = pBh + (long)((kc)*32 + bk)*ldb + col0 + bn;               \
        const bf16* bq_ = pBl + (long)((kc)*32 + bk)*ldb + col0 + bn;               \
        vBh0 = *(const uint4*)bp_;  vBh1 = *(const uint4*)(bp_ + 8);                \
        vBl0 = *(const uint4*)bq_;  vBl1 = *(const uint4*)(bq_ + 8);                \
    } while (0)

    LOAD_CHUNK(0);

    int w = t >> 5, lane = t & 31;
    int wm = w >> 1, wn = w & 1;
    float acc[2][8][4] = {};

    int KT = K >> 5;
    for (int kc = 0; kc < KT; kc++) {
        *(uint4*)&Ash[arow][ak]     = vAh0;  *(uint4*)&Ash[arow][ak + 8] = vAh1;
        *(uint4*)&Asl[arow][ak]     = vAl0;  *(uint4*)&Asl[arow][ak + 8] = vAl1;
        *(uint4*)&Bsh[bk][bn]       = vBh0;  *(uint4*)&Bsh[bk][bn + 8]   = vBh1;
        *(uint4*)&Bsl[bk][bn]       = vBl0;  *(uint4*)&Bsl[bk][bn + 8]   = vBl1;
        __syncthreads();
        if (kc + 1 < KT) LOAD_CHUNK(kc + 1);

        #pragma unroll
        for (int s = 0; s < 2; s++) {
            unsigned ah[2][4], al[2][4];
            int arw = wm*32 + (lane & 15);
            int acl = s*16 + (lane >> 4)*8;
            ldmx4(ah[0], su32(&Ash[arw][acl]));
            ldmx4(al[0], su32(&Asl[arw][acl]));
            ldmx4(ah[1], su32(&Ash[arw + 16][acl]));
            ldmx4(al[1], su32(&Asl[arw + 16][acl]));
            int brow = s*16 + ((lane >> 3) & 1)*8 + (lane & 7);
            int bcol = wn*64 + (lane >> 4)*8;
            #pragma unroll
            for (int g = 0; g < 4; g++) {
                unsigned bh_[4], bl_[4];
                ldmx4t(bh_, su32(&Bsh[brow][bcol + g*16]));
                ldmx4t(bl_, su32(&Bsl[brow][bcol + g*16]));
                #pragma unroll
                for (int mt = 0; mt < 2; mt++) {
                    mma16816(acc[mt][2*g],   ah[mt], bh_);
                    mma16816(acc[mt][2*g],   ah[mt], bl_);
                    mma16816(acc[mt][2*g],   al[mt], bh_);
                    mma16816(acc[mt][2*g+1], ah[mt], bh_ + 2);
                    mma16816(acc[mt][2*g+1], ah[mt], bl_ + 2);
                    mma16816(acc[mt][2*g+1], al[mt], bh_ + 2);
                }
            }
        }
        __syncthreads();
    }
    #undef LOAD_CHUNK

    int rg = row0 + wm*32 + (lane >> 2);
    int cb = col0 + wn*64 + (lane & 3)*2;
    const float* ea[2][2] = {};
    if (MODE == 4) {
        #pragma unroll
        for (int mt = 0; mt < 2; mt++)
            #pragma unroll
            for (int hf = 0; hf < 2; hf++) {
                int rr = rg + mt*16 + hf*8;
                if (rr < M) {
                    int b = rr / Pq, pp = rr % Pq;
                    ea[mt][hf] = p.Eadd[z] + ((long)(b*NEq) + p.hts[z*Pq + pp])*Dq;
                }
            }
    }
    #pragma unroll
    for (int mt = 0; mt < 2; mt++) {
        #pragma unroll
        for (int n8 = 0; n8 < 8; n8++) {
            int rr = rg + mt*16;
            int cc = cb + n8*8;
            float v0 = acc[mt][n8][0], v1 = acc[mt][n8][1];
            float v2 = acc[mt][n8][2], v3 = acc[mt][n8][3];
            if (MODE == 4) {
                if (ea[mt][0]) { v0 += ea[mt][0][cc]; v1 += ea[mt][0][cc+1]; }
                if (ea[mt][1]) { v2 += ea[mt][1][cc]; v3 += ea[mt][1][cc+1]; }
            }
            if (pbias) {
                float b0 = pbias[cc], b1 = pbias[cc+1];
                v0 += b0; v1 += b1; v2 += b0; v3 += b1;
            }
            if (p.act) { v0 = tanhf(v0); v1 = tanhf(v1); v2 = tanhf(v2); v3 = tanhf(v3); }
            if (rr < M) {
                *(float2*)(pC + (long)rr*ldc + cc) = make_float2(v0, v1);
                if (pChi) {
                    bf16 h0,l0,h1,l1; split2(v0,h0,l0); split2(v1,h1,l1);
                    *(__nv_bfloat162*)(pChi + (long)rr*ldc + cc) = __nv_bfloat162(h0, h1);
                    *(__nv_bfloat162*)(pClo + (long)rr*ldc + cc) = __nv_bfloat162(l0, l1);
                }
            }
            if (rr + 8 < M) {
                *(float2*)(pC + (long)(rr+8)*ldc + cc) = make_float2(v2, v3);
                if (pChi) {
                    bf16 h0,l0,h1,l1; split2(v2,h0,l0); split2(v3,h1,l1);
                    *(__nv_bfloat162*)(pChi + (long)(rr+8)*ldc + cc) = __nv_bfloat162(h0, h1);
                    *(__nv_bfloat162*)(pClo + (long)(rr+8)*ldc + cc) = __nv_bfloat162(l0, l1);
                }
            }
        }
    }
}

// ---------------- binary head: 16 rows per block ----------------
__global__ void k_gbl_bin16(const float* __restrict__ A, const float* __restrict__ C,
                            const float* __restrict__ W, const float* __restrict__ bias,
                            float* __restrict__ out, int* __restrict__ mask)
{
    extern __shared__ float sm[];           // a[16][772] + c[16][772]
    float* a_s = sm;
    float* c_s = sm + 16*772;
    int n0 = blockIdx.x * 16;
    int t = threadIdx.x;
    for (int idx = t; idx < 16*192; idx += 256) {
        int r = idx / 192, q = (idx % 192) * 4;
        *(float4*)&a_s[r*772 + q] = *(const float4*)(A + (long)(n0 + r)*Dq + q);
        *(float4*)&c_s[r*772 + q] = *(const float4*)(C + (long)(n0 + r)*Dq + q);
    }
    __syncthreads();
    int nl = t & 15, grp = t >> 4;
    float s0 = 0.f, s1 = 0.f;
    for (int s = 0; s < 48; s++) {
        int hi = grp*48 + s;
        float ai = a_s[nl*772 + hi];
        const float2* w2 = (const float2*)(W + (long)hi*BSq*2);
        const float* cc = c_s + nl*772 + (hi & ~63);
        #pragma unroll 8
        for (int j = 0; j < BSq; j++) {
            float v = ai * cc[j];
            float2 ww = w2[j];
            s0 += v*ww.x; s1 += v*ww.y;
        }
    }
    __shared__ float r0[16][17], r1[16][17];
    r0[grp][nl] = s0; r1[grp][nl] = s1;
    __syncthreads();
    if (t < 16) {
        float b0 = bias[0], b1 = bias[1];
        #pragma unroll
        for (int g = 0; g < 16; g++) { b0 += r0[g][t]; b1 += r1[g][t]; }
        int n = n0 + t;
        out[n*2] = b0; out[n*2+1] = b1;
        mask[n] = (b1 > b0) ? 1 : 0;
    }
}

__global__ void k_inc(const int* __restrict__ hts, int* __restrict__ inc)
{
    if (threadIdx.x == 0 && blockIdx.x == 0) {
        int cnt[NEq];
        for (int i = 0; i < NEq; i++) cnt[i] = 0;
        for (int p = 0; p < Pq; p++) {
            int d = hts[Pq + p];
            inc[d*23 + cnt[d]++] = p;
        }
    }
}

__global__ void k_f(const float* __restrict__ Ni, const float* __restrict__ Nj,
                    const float* __restrict__ EfW, const float* __restrict__ eb,
                    const int* __restrict__ hts, float* __restrict__ f)
{
    int be = blockIdx.x; int b = be / Eq, e = be % Eq;
    int src, dst; const float* ef = 0;
    if (e < Pq) { src = hts[e]; dst = hts[Pq + e]; ef = EfW + ((long)b*Pq + e)*Dq; }
    else        { src = dst = e - Pq; }
    const float* ni = Ni + ((long)b*NEq + src)*Dq;
    const float* nj = Nj + ((long)b*NEq + dst)*Dq;
    float* o = f + (long)be*Dq;
    for (int d = threadIdx.x; d < Dq; d += blockDim.x) {
        float v = ni[d] + nj[d] + eb[d];
        if (ef) v += ef[d];
        o[d] = v;
    }
}

__global__ void k_score(const float* __restrict__ f, const float* __restrict__ attn_p,
                        const int* __restrict__ mask, float* __restrict__ score)
{
    int be = blockIdx.x; int b = be / Eq, e = be % Eq;
    int h = threadIdx.x >> 5, lane = threadIdx.x & 31;
    const float* fr = f + (long)be*Dq + h*BSq;
    float s = 0.f;
    #pragma unroll
    for (int i = lane; i < BSq; i += 32) {
        float x = fr[i];
        float lr = x > 0.f ? x : 0.2f*x;
        s += lr * attn_p[h*BSq + i];
    }
    #pragma unroll
    for (int off = 16; off; off >>= 1) s += __shfl_xor_sync(0xffffffffu, s, off);
    if (lane == 0) {
        int m = (e < Pq) ? mask[b*Pq + e] : 1;
        score[(long)be*Hq + h] = m ? s : -1e30f;
    }
}

__global__ void k_soft(const float* __restrict__ score, const int* __restrict__ inc,
                       const int* __restrict__ mask, float* __restrict__ alpha)
{
    int bn = blockIdx.x; int b = bn / NEq, n = bn % NEq;
    int h = threadIdx.x >> 5, lane = threadIdx.x & 31;
    int eid = 0; float sc = -INFINITY; float m = 0.f;
    if (lane < 24) {
        eid = (lane < 23) ? inc[n*23 + lane] : (Pq + n);
        sc  = score[((long)b*Eq + eid)*Hq + h];
        m   = (eid < Pq) ? (float)mask[b*Pq + eid] : 1.f;
    }
    float mx = sc;
    #pragma unroll
    for (int off = 16; off; off >>= 1) mx = fmaxf(mx, __shfl_xor_sync(0xffffffffu, mx, off));
    float ex = (lane < 24) ? expf(sc - mx)*m : 0.f;
    float den = ex;
    #pragma unroll
    for (int off = 16; off; off >>= 1) den += __shfl_xor_sync(0xffffffffu, den, off);
    if (lane < 24) alpha[((long)b*Eq + eid)*Hq + h] = ex / (den + 1e-20f);
}

__global__ void k_nodeout(const float* __restrict__ alpha, const float* __restrict__ Hsrc,
                          const int* __restrict__ inc, const int* __restrict__ hts,
                          bf16* __restrict__ oh, bf16* __restrict__ ol)
{
    int bn = blockIdx.x; int b = bn / NEq, n = bn % NEq;
    __shared__ int   esrc[24];
    __shared__ float eal[24*Hq];
    int t = threadIdx.x;
    if (t < 24) {
        int eid = (t < 23) ? inc[n*23 + t] : (Pq + n);
        esrc[t] = (t < 23) ? hts[eid] : n;
    }
    for (int t2 = t; t2 < 24*Hq; t2 += blockDim.x) {
        int slot = t2 / Hq, hh = t2 % Hq;
        int eid = (slot < 23) ? inc[n*23 + slot] : (Pq + n);
        eal[t2] = alpha[((long)b*Eq + eid)*Hq + hh];
    }
    __syncthreads();
    for (int d = t; d < Dq; d += blockDim.x) {
        int h = d >> 6;
        float s = 0.f;
        #pragma unroll
        for (int slot = 0; slot < 24; slot++)
            s += eal[slot*Hq + h] * Hsrc[((long)b*NEq + esrc[slot])*Dq + d];
        bf16 hh, ll; split2(s, hh, ll);
        oh[(long)bn*Dq + d] = hh; ol[(long)bn*Dq + d] = ll;
    }
}

__global__ void k_newci(const int* __restrict__ mask, const float* __restrict__ f,
                        const float* __restrict__ ci, bf16* __restrict__ oh,
                        bf16* __restrict__ ol)
{
    long idx = (long)blockIdx.x*256 + threadIdx.x;
    int d = (int)(idx % Dq); long n = idx / Dq;
    int b = (int)(n / Pq), p = (int)(n % Pq);
    float v = mask[n] ? f[((long)b*Eq + p)*Dq + d] : ci[idx];
    bf16 h, l; split2(v, h, l);
    oh[idx] = h; ol[idx] = l;
}

__global__ void k_rel_reduce(const float* __restrict__ part, const float* __restrict__ brel,
                             float* __restrict__ out)
{
    long idx = (long)blockIdx.x*256 + threadIdx.x;
    if (idx >= (long)NPq*Rq) return;
    int o = (int)(idx % Rq);
    long n = idx / Rq;
    float s = brel[o];
    #pragma unroll
    for (int h = 0; h < Hq; h++) s += part[((long)h*NPq + n)*128 + o];
    out[idx] = s;
}

// ---------------- host ----------------
template <typename T>
static T* sym(const void* s) { void* p = 0; cudaGetSymbolAddress(&p, s); return (T*)p; }

static void splitw(const float* src, bf16* hi, bf16* lo, long n)
{
    k_split<<<(int)((n + 255)/256), 256>>>(src, hi, lo, n);
}

extern "C" void kernel_launch(void* const* d_in, const int* in_sizes, int n_in,
                              void* d_out, int out_size)
{
    const float* ctx    = (const float*)d_in[0];
    const float* att    = (const float*)d_in[1];
    const int*   mm     = (const int*)  d_in[2];
    const float* em     = (const float*)d_in[3];
    const int*   hts    = (const int*)  d_in[4];
    const float* Whb    = (const float*)d_in[5];
    const float* bhb    = (const float*)d_in[6];
    const float* Wtb    = (const float*)d_in[7];
    const float* btb    = (const float*)d_in[8];
    const float* Wbin   = (const float*)d_in[9];
    const float* bbin   = (const float*)d_in[10];
    const float* Wrel   = (const float*)d_in[11];
    const float* brel   = (const float*)d_in[12];
    const float* Wh     = (const float*)d_in[13];
    const float* bh     = (const float*)d_in[14];
    const float* Wt     = (const float*)d_in[15];
    const float* bt     = (const float*)d_in[16];
    const float* Wnode  = (const float*)d_in[17];
    const float* Wni    = (const float*)d_in[18];
    const float* Wfij   = (const float*)d_in[19];
    const float* Wnj    = (const float*)d_in[20];
    const float* attn_p = (const float*)d_in[21];
    const float* egat_b = (const float*)d_in[22];

    float* outBin = (float*)d_out;
    float* outRel = outBin + (long)NPq*2;

    float* p_cur   = sym<float>(g_cur);
    float* p_ci    = sym<float>(g_ci);
    float* p_bh    = sym<float>(g_bh);
    float* p_bt    = sym<float>(g_bt);
    int*   p_mask  = sym<int>(g_mask);
    float* p_Ni    = sym<float>(g_Ni);
    float* p_Nj    = sym<float>(g_Nj);
    float* p_Hs    = sym<float>(g_Hs);
    float* p_EfW   = sym<float>(g_EfW);
    float* p_f     = sym<float>(g_f);
    float* p_score = sym<float>(g_score);
    float* p_alpha = sym<float>(g_alpha);
    float* p_rpart = sym<float>(g_relpart);
    int*   p_inc   = sym<int>(g_inc);
    float* p_Ebh   = sym<float>(g_Ebh);
    float* p_Ebt   = sym<float>(g_Ebt);
    float* p_Erh   = sym<float>(g_Erh);
    float* p_Ert   = sym<float>(g_Ert);

    bf16 *enth = sym<bf16>(g_enth), *entl = sym<bf16>(g_entl);
    bf16 *cah  = sym<bf16>(g_cah),  *cal  = sym<bf16>(g_cal);
    bf16 *cih  = sym<bf16>(g_cih),  *cil  = sym<bf16>(g_cil);
    bf16 *nouth= sym<bf16>(g_nouth),*noutl= sym<bf16>(g_noutl);
    bf16 *nch  = sym<bf16>(g_nch),  *ncl  = sym<bf16>(g_ncl);
    bf16 *ctxh = sym<bf16>(g_ctxh), *ctxl = sym<bf16>(g_ctxl);
    bf16 *Whbh = sym<bf16>(g_Whbh), *Whbl = sym<bf16>(g_Whbl);
    bf16 *Wtbh = sym<bf16>(g_Wtbh), *Wtbl = sym<bf16>(g_Wtbl);
    bf16 *Whh  = sym<bf16>(g_Whh),  *Whl  = sym<bf16>(g_Whl);
    bf16 *Wth  = sym<bf16>(g_Wth),  *Wtl  = sym<bf16>(g_Wtl);
    bf16 *Wfijh= sym<bf16>(g_Wfijh),*Wfijl= sym<bf16>(g_Wfijl);
    bf16 *Wnih = sym<bf16>(g_Wnih), *Wnil = sym<bf16>(g_Wnil);
    bf16 *Wnjh = sym<bf16>(g_Wnjh), *Wnjl = sym<bf16>(g_Wnjl);
    bf16 *Wnodeh=sym<bf16>(g_Wnodeh),*Wnodel=sym<bf16>(g_Wnodel);
    bf16 *Wpadh= sym<bf16>(g_Wpadh),*Wpadl= sym<bf16>(g_Wpadl);

    cudaFuncSetAttribute(k_mma<3>, cudaFuncAttributeMaxDynamicSharedMemorySize, 2*128*68*4);
    cudaFuncSetAttribute(k_gbl_bin16, cudaFuncAttributeMaxDynamicSharedMemorySize, 2*16*772*4);

    // ---- pooling + conversions ----
    k_entity<<<Bq*NEq, 256>>>(ctx, mm, em, enth, entl);
    k_cur<<<Bq*Hq*NEq, 256>>>(att, mm, em, p_cur);
    k_ca<<<Bq*Pq, 256>>>(p_cur, hts, cah, cal);
    splitw(ctx,   ctxh,  ctxl,  (long)Bq*Lq*Dq);
    splitw(Whb,   Whbh,  Whbl,  (long)2*Dq*Dq);
    splitw(Wtb,   Wtbh,  Wtbl,  (long)2*Dq*Dq);
    splitw(Wh,    Whh,   Whl,   (long)2*Dq*Dq);
    splitw(Wt,    Wth,   Wtl,   (long)2*Dq*Dq);
    splitw(Wfij,  Wfijh, Wfijl, (long)Dq*Dq);
    splitw(Wni,   Wnih,  Wnil,  (long)Dq*Dq);
    splitw(Wnj,   Wnjh,  Wnjl,  (long)Dq*Dq);
    splitw(Wnode, Wnodeh,Wnodel,(long)Dq*Dq);
    k_wpadsplit<<<(int)(((long)Hq*4096*128)/256), 256>>>(Wrel, Wpadh, Wpadl);
    k_inc<<<1, 32>>>(hts, p_inc);

    // ---- ci = ca @ ctx (batched over B), split output ----
    {
        GemmP g = {};
        for (int z = 0; z < Bq; z++) {
            g.Ah[z] = cah + (long)z*Pq*Lq;  g.Al[z] = cal + (long)z*Pq*Lq;
            g.Bh[z] = ctxh + (long)z*Lq*Dq; g.Bl[z] = ctxl + (long)z*Lq*Dq;
            g.C[z]  = p_ci + (long)z*Pq*Dq;
            g.Chi[z]= cih  + (long)z*Pq*Dq; g.Clo[z]= cil + (long)z*Pq*Dq;
            g.Mz[z] = Pq;
        }
        g.K = Lq; g.ldb = Dq; g.ldc = Dq; g.splitout = 1;
        k_mma<0><<<dim3(6, 5, 4), 256>>>(g);
    }

    // ---- Ebin = ent96 @ W_top ----
    {
        GemmP g = {};
        g.Ah[0] = enth; g.Al[0] = entl; g.Bh[0] = Whbh; g.Bl[0] = Whbl; g.C[0] = p_Ebh; g.Mz[0] = Bq*NEq;
        g.Ah[1] = enth; g.Al[1] = entl; g.Bh[1] = Wtbh; g.Bl[1] = Wtbl; g.C[1] = p_Ebt; g.Mz[1] = Bq*NEq;
        g.K = Dq; g.ldb = Dq; g.ldc = Dq;
        k_mma<0><<<dim3(6, 1, 2), 256>>>(g);
    }

    // ---- bin pair: tanh(ci @ W_bot + Ebin[ent] + bias) ----
    {
        GemmP g = {};
        g.Ah[0] = cih; g.Al[0] = cil; g.Bh[0] = Whbh + (long)Dq*Dq; g.Bl[0] = Whbl + (long)Dq*Dq;
        g.bias[0] = bhb; g.C[0] = p_bh; g.Eadd[0] = p_Ebh; g.Mz[0] = NPq;
        g.Ah[1] = cih; g.Al[1] = cil; g.Bh[1] = Wtbh + (long)Dq*Dq; g.Bl[1] = Wtbl + (long)Dq*Dq;
        g.bias[1] = btb; g.C[1] = p_bt; g.Eadd[1] = p_Ebt; g.Mz[1] = NPq;
        g.hts = hts; g.K = Dq; g.ldb = Dq; g.ldc = Dq; g.act = 1;
        k_mma<4><<<dim3(6, 18, 2), 256>>>(g);
    }
    k_gbl_bin16<<<NPq/16, 256, 2*16*772*4>>>(p_bh, p_bt, Wbin, bbin, outBin, p_mask);

    // ---- EGAT linear layers ----
    {
        GemmP g = {};
        g.Ah[0] = cih;  g.Al[0] = cil;  g.Bh[0] = Wfijh;  g.Bl[0] = Wfijl;  g.C[0] = p_EfW; g.Mz[0] = NPq;
        g.Ah[1] = enth; g.Al[1] = entl; g.Bh[1] = Wnih;   g.Bl[1] = Wnil;   g.C[1] = p_Ni;  g.Mz[1] = Bq*NEq;
        g.Ah[2] = enth; g.Al[2] = entl; g.Bh[2] = Wnjh;   g.Bl[2] = Wnjl;   g.C[2] = p_Nj;  g.Mz[2] = Bq*NEq;
        g.Ah[3] = enth; g.Al[3] = entl; g.Bh[3] = Wnodeh; g.Bl[3] = Wnodel; g.C[3] = p_Hs;  g.Mz[3] = Bq*NEq;
        g.K = Dq; g.ldb = Dq; g.ldc = Dq;
        k_mma<0><<<dim3(6, 18, 4), 256>>>(g);
    }
    k_f<<<Bq*Eq, 256>>>(p_Ni, p_Nj, p_EfW, egat_b, hts, p_f);
    k_score<<<Bq*Eq, 384>>>(p_f, attn_p, p_mask, p_score);
    k_soft<<<Bq*NEq, 384>>>(p_score, p_inc, p_mask, p_alpha);
    k_nodeout<<<Bq*NEq, 256>>>(p_alpha, p_Hs, p_inc, hts, nouth, noutl);

    // ---- relation head ----
    k_newci<<<NPq*Dq/256, 256>>>(p_mask, p_f, p_ci, nch, ncl);
    {
        GemmP g = {};
        g.Ah[0] = nouth; g.Al[0] = noutl; g.Bh[0] = Whh; g.Bl[0] = Whl; g.C[0] = p_Erh; g.Mz[0] = Bq*NEq;
        g.Ah[1] = nouth; g.Al[1] = noutl; g.Bh[1] = Wth; g.Bl[1] = Wtl; g.C[1] = p_Ert; g.Mz[1] = Bq*NEq;
        g.K = Dq; g.ldb = Dq; g.ldc = Dq;
        k_mma<0><<<dim3(6, 1, 2), 256>>>(g);
    }
    {
        GemmP g = {};
        g.Ah[0] = nch; g.Al[0] = ncl; g.Bh[0] = Whh + (long)Dq*Dq; g.Bl[0] = Whl + (long)Dq*Dq;
        g.bias[0] = bh; g.C[0] = p_bh; g.Eadd[0] = p_Erh; g.Mz[0] = NPq;
        g.Ah[1] = nch; g.Al[1] = ncl; g.Bh[1] = Wth + (long)Dq*Dq; g.Bl[1] = Wtl + (long)Dq*Dq;
        g.bias[1] = bt; g.C[1] = p_bt; g.Eadd[1] = p_Ert; g.Mz[1] = NPq;
        g.hts = hts; g.K = Dq; g.ldb = Dq; g.ldc = Dq; g.act = 1;
        k_mma<4><<<dim3(6, 18, 2), 256>>>(g);
    }
    {
        GemmP g = {};
        g.Bh[0] = Wpadh; g.Bl[0] = Wpadl;
        g.C[0] = p_rpart; g.Mz[0] = NPq;
        g.bhp = p_bh; g.btp = p_bt;
        g.sB = (long)4096*128; g.sC = (long)NPq*128;
        g.K = 4096; g.ldb = 128; g.ldc = 128;
        k_mma<3><<<dim3(1, 18, Hq), 256, 2*128*68*4>>>(g);
    }
    k_rel_reduce<<<((long)NPq*Rq + 255)/256, 256>>>(p_rpart, brel, outRel);
}

// round 8
// speedup vs baseline: 2.6284x; 1.0947x over previous
#include <cuda_runtime.h>
#include <cuda_bf16.h>
#include <math.h>

#define Bq   4
#define Lq   1024
#define Dq   768
#define Hq   12
#define BSq  64
#define Mq   48
#define NEq  24
#define Pq   552
#define Eq   576
#define Rq   97
#define NPq  2208

typedef __nv_bfloat16 bf16;

// ---------------- scratch ----------------
__device__ float g_cur    [Bq*Hq*NEq*Lq];
__device__ float g_ci     [NPq*Dq];
__device__ float g_bh     [NPq*Dq];
__device__ float g_bt     [NPq*Dq];
__device__ int   g_mask   [NPq];
__device__ float g_Ni     [Bq*NEq*Dq];
__device__ float g_Nj     [Bq*NEq*Dq];
__device__ float g_Hs     [Bq*NEq*Dq];
__device__ float g_EfW    [NPq*Dq];
__device__ float g_f      [Bq*Eq*Dq];
__device__ float g_score  [Bq*Eq*Hq];
__device__ float g_alpha  [Bq*Eq*Hq];
__device__ float g_relpart[(size_t)24*NPq*128];
__device__ int   g_inc    [NEq*23];
__device__ float g_Ebh[96*Dq], g_Ebt[96*Dq], g_Erh[96*Dq], g_Ert[96*Dq];

__device__ bf16 g_enth[Bq*NEq*Dq],   g_entl[Bq*NEq*Dq];
__device__ bf16 g_cah [Bq*Pq*Lq],    g_cal [Bq*Pq*Lq];
__device__ bf16 g_cih [NPq*Dq],      g_cil [NPq*Dq];
__device__ bf16 g_nouth[Bq*NEq*Dq],  g_noutl[Bq*NEq*Dq];
__device__ bf16 g_nch[NPq*Dq],       g_ncl[NPq*Dq];
__device__ bf16 g_ctxh[Bq*Lq*Dq],    g_ctxl[Bq*Lq*Dq];
__device__ bf16 g_Whbh[2*Dq*Dq],     g_Whbl[2*Dq*Dq];
__device__ bf16 g_Wtbh[2*Dq*Dq],     g_Wtbl[2*Dq*Dq];
__device__ bf16 g_Whh [2*Dq*Dq],     g_Whl [2*Dq*Dq];
__device__ bf16 g_Wth [2*Dq*Dq],     g_Wtl [2*Dq*Dq];
__device__ bf16 g_Wfijh[Dq*Dq],      g_Wfijl[Dq*Dq];
__device__ bf16 g_Wnih[Dq*Dq],       g_Wnil[Dq*Dq];
__device__ bf16 g_Wnjh[Dq*Dq],       g_Wnjl[Dq*Dq];
__device__ bf16 g_Wnodeh[Dq*Dq],     g_Wnodel[Dq*Dq];
__device__ bf16 g_Wpadh[(size_t)Hq*4096*128], g_Wpadl[(size_t)Hq*4096*128];

// ---------------- helpers ----------------
__device__ __forceinline__ void split2(float x, bf16& h, bf16& l) {
    h = __float2bfloat16(x);
    l = __float2bfloat16(x - __bfloat162float(h));
}
__device__ __forceinline__ unsigned su32(const void* p) {
    return (unsigned)__cvta_generic_to_shared(p);
}
__device__ __forceinline__ void ldmx4(unsigned* r, unsigned a) {
    asm volatile("ldmatrix.sync.aligned.m8n8.x4.shared.b16 {%0,%1,%2,%3}, [%4];"
        : "=r"(r[0]), "=r"(r[1]), "=r"(r[2]), "=r"(r[3]) : "r"(a));
}
__device__ __forceinline__ void ldmx4t(unsigned* r, unsigned a) {
    asm volatile("ldmatrix.sync.aligned.m8n8.x4.trans.shared.b16 {%0,%1,%2,%3}, [%4];"
        : "=r"(r[0]), "=r"(r[1]), "=r"(r[2]), "=r"(r[3]) : "r"(a));
}
__device__ __forceinline__ void mma16816(float* c, const unsigned* a, const unsigned* b) {
    asm volatile("mma.sync.aligned.m16n8k16.row.col.f32.bf16.bf16.f32 "
        "{%0,%1,%2,%3}, {%4,%5,%6,%7}, {%8,%9}, {%0,%1,%2,%3};"
        : "+f"(c[0]), "+f"(c[1]), "+f"(c[2]), "+f"(c[3])
        : "r"(a[0]), "r"(a[1]), "r"(a[2]), "r"(a[3]), "r"(b[0]), "r"(b[1]));
}
__device__ __forceinline__ uint4 pack8(const bf16* x) {
    uint4 u;
    u.x = ((unsigned)__bfloat16_as_ushort(x[1]) << 16) | __bfloat16_as_ushort(x[0]);
    u.y = ((unsigned)__bfloat16_as_ushort(x[3]) << 16) | __bfloat16_as_ushort(x[2]);
    u.z = ((unsigned)__bfloat16_as_ushort(x[5]) << 16) | __bfloat16_as_ushort(x[4]);
    u.w = ((unsigned)__bfloat16_as_ushort(x[7]) << 16) | __bfloat16_as_ushort(x[6]);
    return u;
}

// ---------------- small kernels ----------------
__global__ void k_entity(const float* __restrict__ ctx, const int* __restrict__ mm,
                         const float* __restrict__ em,
                         bf16* __restrict__ oh, bf16* __restrict__ ol)
{
    int bn = blockIdx.x; int b = bn / NEq, n = bn % NEq;
    __shared__ float w_s[Mq]; __shared__ int mi_s[Mq];
    if (threadIdx.x < Mq) {
        w_s[threadIdx.x]  = em[(b*NEq + n)*Mq + threadIdx.x];
        mi_s[threadIdx.x] = mm[b*Mq + threadIdx.x];
    }
    __syncthreads();
    for (int d = threadIdx.x; d < Dq; d += blockDim.x) {
        float s = 0.f;
        #pragma unroll 4
        for (int m = 0; m < Mq; m++) {
            float w = w_s[m];
            if (w != 0.f) s += w * expf(ctx[((long)b*Lq + mi_s[m])*Dq + d]);
        }
        float v = logf(s);
        bf16 h, l; split2(v, h, l);
        oh[(long)bn*Dq + d] = h; ol[(long)bn*Dq + d] = l;
    }
}

__global__ void k_cur(const float* __restrict__ att, const int* __restrict__ mm,
                      const float* __restrict__ em, float* __restrict__ cur)
{
    int id = blockIdx.x;
    int n = id % NEq; int h = (id / NEq) % Hq; int b = id / (NEq*Hq);
    __shared__ int   act_m[Mq];
    __shared__ float act_w[Mq];
    __shared__ int   nact;
    __shared__ float invc;
    if (threadIdx.x == 0) {
        int c = 0; float cnt = 0.f;
        for (int m = 0; m < Mq; m++) {
            float w = em[(b*NEq + n)*Mq + m]; cnt += w;
            if (w != 0.f) { act_m[c] = mm[b*Mq + m]; act_w[c] = w; c++; }
        }
        nact = c; invc = 1.f / (cnt + 1e-20f);
    }
    __syncthreads();
    const float* abase = att + ((long)(b*Hq + h))*Lq*Lq;
    float* obase = cur + (long)id*Lq;
    int na = nact; float iv = invc;
    for (int l = threadIdx.x; l < Lq; l += blockDim.x) {
        float s = 0.f;
        for (int a = 0; a < na; a++) s += act_w[a] * abase[(long)act_m[a]*Lq + l];
        obase[l] = s * iv;
    }
}

__global__ void k_ca(const float* __restrict__ cur, const int* __restrict__ hts,
                     bf16* __restrict__ cah, bf16* __restrict__ cal)
{
    int bp = blockIdx.x; int b = bp / Pq, p = bp % Pq;
    int h0 = hts[p], h1 = hts[Pq + p];
    const float* c0 = cur + ((long)b*Hq*NEq + h0)*Lq;
    const float* c1 = cur + ((long)b*Hq*NEq + h1)*Lq;
    float v[4]; float local = 0.f;
    #pragma unroll
    for (int q = 0; q < 4; q++) {
        int l = threadIdx.x + q*256;
        float s = 0.f;
        #pragma unroll
        for (int h = 0; h < Hq; h++)
            s += c0[(long)h*NEq*Lq + l] * c1[(long)h*NEq*Lq + l];
        v[q] = s; local += s;
    }
    __shared__ float red[256];
    red[threadIdx.x] = local; __syncthreads();
    for (int off = 128; off > 0; off >>= 1) {
        if (threadIdx.x < off) red[threadIdx.x] += red[threadIdx.x + off];
        __syncthreads();
    }
    float inv = 1.f / (red[0] + 1e-20f);
    #pragma unroll
    for (int q = 0; q < 4; q++) {
        long o = (long)bp*Lq + threadIdx.x + q*256;
        bf16 h, l; split2(v[q]*inv, h, l);
        cah[o] = h; cal[o] = l;
    }
}

__global__ void k_split(const float* __restrict__ src, bf16* __restrict__ hi,
                        bf16* __restrict__ lo, long n)
{
    long i = (long)blockIdx.x*256 + threadIdx.x;
    if (i >= n) return;
    bf16 h, l; split2(src[i], h, l);
    hi[i] = h; lo[i] = l;
}

// Wrel [49152][97] -> padded split [12][4096][128]
__global__ void k_wpadsplit(const float* __restrict__ W, bf16* __restrict__ Wh,
                            bf16* __restrict__ Wl)
{
    long idx = (long)blockIdx.x*256 + threadIdx.x;
    int o = (int)(idx & 127);
    long row = idx >> 7;
    float v = (o < Rq) ? W[row*Rq + o] : 0.f;
    bf16 h, l; split2(v, h, l);
    Wh[idx] = h; Wl[idx] = l;
}

// ---------------- mma.sync GEMM ----------------
// MODE 0: A from table. MODE 3: A generated = outer(bh,bt), z = head*2+ksplit.
// MODE 4: A from table, epilogue adds gathered per-row fp32 addend Eadd[z][hts-row].
struct GemmP {
    const bf16 *Ah[4], *Al[4], *Bh[4], *Bl[4];
    const float* bias[4];
    float* C[4];
    bf16 *Chi[4], *Clo[4];
    const float* Eadd[4];
    int Mz[4];
    const int* hts;
    const float *bhp, *btp;
    long sB, sC;
    int K, ldb, ldc, act, splitout;
};

template<int MODE>
__global__ __launch_bounds__(256)
void k_mma(GemmP p)
{
    __shared__ bf16 Ash[128][40], Asl[128][40];
    __shared__ bf16 Bsh[32][136],  Bsl[32][136];
    extern __shared__ float dynf[];     // MODE 3: bhF[128*68], btF[128*68]
    float* bhF = dynf;
    float* btF = dynf + 128*68;

    int z = blockIdx.z;
    const bf16 *pBh, *pBl;
    const float* pbias = 0; float* pC;
    bf16 *pChi = 0, *pClo = 0;
    int M;
    const bf16 *tAh = 0, *tAl = 0;
    int h3 = 0, kcb = 0;
    if (MODE == 3) {
        h3 = z >> 1;
        kcb = (z & 1) * 64;                 // K-split: 64 of 128 32-wide chunks
        pBh = p.Bh[0] + (long)h3*p.sB;  pBl = p.Bl[0] + (long)h3*p.sB;
        pC  = p.C[0]  + (long)z*p.sC;
        M = p.Mz[0];
    } else {
        tAh = p.Ah[z]; tAl = p.Al[z];
        pBh = p.Bh[z]; pBl = p.Bl[z];
        pC  = p.C[z];  pbias = p.bias[z]; M = p.Mz[z];
        if (p.splitout) { pChi = p.Chi[z]; pClo = p.Clo[z]; }
    }
    int row0 = blockIdx.y * 128;
    if (row0 >= M) return;
    int col0 = blockIdx.x * 128;
    int K = p.K, ldb = p.ldb, ldc = p.ldc;
    int t = threadIdx.x;

    int arow = t >> 1;
    int ak   = (t & 1) * 16;
    int grow = row0 + arow;
    int rowc = grow < M ? grow : M - 1;
    const bf16 *srcAh0 = 0, *srcAl0 = 0;
    if (MODE != 3) {
        srcAh0 = tAh + (long)rowc*K;  srcAl0 = tAl + (long)rowc*K;
    }
    int bk = t >> 3;
    int bn = (t & 7) * 16;

    if (MODE == 3) {
        for (int idx = t; idx < 128*16; idx += 256) {
            int r = idx >> 4, q = (idx & 15) * 4;
            int rr = row0 + r; if (rr >= M) rr = M - 1;
            *(float4*)&bhF[r*68 + q] = *(const float4*)(p.bhp + (long)rr*Dq + h3*64 + q);
            *(float4*)&btF[r*68 + q] = *(const float4*)(p.btp + (long)rr*Dq + h3*64 + q);
        }
        __syncthreads();
    }

    uint4 vAh0, vAh1, vAl0, vAl1, vBh0, vBh1, vBl0, vBl1;

    #define LOAD_CHUNK(kc) do {                                                     \
        if (MODE == 3) {                                                            \
            int kk_ = (kc) + kcb;                                                   \
            int i_ = kk_ >> 1, j0_ = (kk_ & 1) * 32;                                \
            float a_ = bhF[arow*68 + i_];                                           \
            bf16 hh_[16], ll_[16];                                                  \
            _Pragma("unroll")                                                       \
            for (int q = 0; q < 16; q++) {                                          \
                float v_ = a_ * btF[arow*68 + j0_ + ak + q];                        \
                split2(v_, hh_[q], ll_[q]);                                         \
            }                                                                       \
            vAh0 = pack8(hh_); vAh1 = pack8(hh_ + 8);                               \
            vAl0 = pack8(ll_); vAl1 = pack8(ll_ + 8);                               \
        } else {                                                                    \
            const bf16 *sh = srcAh0 + (kc)*32 + ak, *sl = srcAl0 + (kc)*32 + ak;    \
            vAh0 = *(const uint4*)sh;  vAh1 = *(const uint4*)(sh + 8);              \
            vAl0 = *(const uint4*)sl;  vAl1 = *(const uint4*)(sl + 8);              \
        }                                                                           \
        const bf16* bp_ = pBh + (long)(((kc) + kcb)*32 + bk)*ldb + col0 + bn;       \
        const bf16* bq_ = pBl + (long)(((kc) + kcb)*32 + bk)*ldb + col0 + bn;       \
        vBh0 = *(const uint4*)bp_;  vBh1 = *(const uint4*)(bp_ + 8);                \
        vBl0 = *(const uint4*)bq_;  vBl1 = *(const uint4*)(bq_ + 8);                \
    } while (0)

    LOAD_CHUNK(0);

    int w = t >> 5, lane = t & 31;
    // SMSP-balanced warp->tile map: each SMSP (w%4) gets one wn=0 and one wn=1 warp
    int wm = (w >> 1) & 3;
    int wn = (w & 1) ^ ((w >> 2) & 1);
    float acc[2][8][4] = {};

    int KT = K >> 5;
    for (int kc = 0; kc < KT; kc++) {
        *(uint4*)&Ash[arow][ak]     = vAh0;  *(uint4*)&Ash[arow][ak + 8] = vAh1;
        *(uint4*)&Asl[arow][ak]     = vAl0;  *(uint4*)&Asl[arow][ak + 8] = vAl1;
        *(uint4*)&Bsh[bk][bn]       = vBh0;  *(uint4*)&Bsh[bk][bn + 8]   = vBh1;
        *(uint4*)&Bsl[bk][bn]       = vBl0;  *(uint4*)&Bsl[bk][bn + 8]   = vBl1;
        __syncthreads();
        if (kc + 1 < KT) LOAD_CHUNK(kc + 1);

        #pragma unroll
        for (int s = 0; s < 2; s++) {
            unsigned ah[2][4], al[2][4];
            int arw = wm*32 + (lane & 15);
            int acl = s*16 + (lane >> 4)*8;
            ldmx4(ah[0], su32(&Ash[arw][acl]));
            ldmx4(al[0], su32(&Asl[arw][acl]));
            ldmx4(ah[1], su32(&Ash[arw + 16][acl]));
            ldmx4(al[1], su32(&Asl[arw + 16][acl]));
            int brow = s*16 + ((lane >> 3) & 1)*8 + (lane & 7);
            int bcol = wn*64 + (lane >> 4)*8;
            #pragma unroll
            for (int g = 0; g < 4; g++) {
                // N-pad trim: rel head only needs cols < 112 (97 real + pad to 112)
                if (MODE == 3 && wn == 1 && g == 3) continue;
                unsigned bh_[4], bl_[4];
                ldmx4t(bh_, su32(&Bsh[brow][bcol + g*16]));
                ldmx4t(bl_, su32(&Bsl[brow][bcol + g*16]));
                #pragma unroll
                for (int mt = 0; mt < 2; mt++) {
                    mma16816(acc[mt][2*g],   ah[mt], bh_);
                    mma16816(acc[mt][2*g],   ah[mt], bl_);
                    mma16816(acc[mt][2*g],   al[mt], bh_);
                    mma16816(acc[mt][2*g+1], ah[mt], bh_ + 2);
                    mma16816(acc[mt][2*g+1], ah[mt], bl_ + 2);
                    mma16816(acc[mt][2*g+1], al[mt], bh_ + 2);
                }
            }
        }
        __syncthreads();
    }
    #undef LOAD_CHUNK

    int rg = row0 + wm*32 + (lane >> 2);
    int cb = col0 + wn*64 + (lane & 3)*2;
    const float* ea[2][2] = {};
    if (MODE == 4) {
        #pragma unroll
        for (int mt = 0; mt < 2; mt++)
            #pragma unroll
            for (int hf = 0; hf < 2; hf++) {
                int rr = rg + mt*16 + hf*8;
                if (rr < M) {
                    int b = rr / Pq, pp = rr % Pq;
                    ea[mt][hf] = p.Eadd[z] + ((long)(b*NEq) + p.hts[z*Pq + pp])*Dq;
                }
            }
    }
    #pragma unroll
    for (int mt = 0; mt < 2; mt++) {
        #pragma unroll
        for (int n8 = 0; n8 < 8; n8++) {
            int rr = rg + mt*16;
            int cc = cb + n8*8;
            float v0 = acc[mt][n8][0], v1 = acc[mt][n8][1];
            float v2 = acc[mt][n8][2], v3 = acc[mt][n8][3];
            if (MODE == 4) {
                if (ea[mt][0]) { v0 += ea[mt][0][cc]; v1 += ea[mt][0][cc+1]; }
                if (ea[mt][1]) { v2 += ea[mt][1][cc]; v3 += ea[mt][1][cc+1]; }
            }
            if (pbias) {
                float b0 = pbias[cc], b1 = pbias[cc+1];
                v0 += b0; v1 += b1; v2 += b0; v3 += b1;
            }
            if (p.act) { v0 = tanhf(v0); v1 = tanhf(v1); v2 = tanhf(v2); v3 = tanhf(v3); }
            if (rr < M) {
                *(float2*)(pC + (long)rr*ldc + cc) = make_float2(v0, v1);
                if (pChi) {
                    bf16 h0,l0,h1,l1; split2(v0,h0,l0); split2(v1,h1,l1);
                    *(__nv_bfloat162*)(pChi + (long)rr*ldc + cc) = __nv_bfloat162(h0, h1);
                    *(__nv_bfloat162*)(pClo + (long)rr*ldc + cc) = __nv_bfloat162(l0, l1);
                }
            }
            if (rr + 8 < M) {
                *(float2*)(pC + (long)(rr+8)*ldc + cc) = make_float2(v2, v3);
                if (pChi) {
                    bf16 h0,l0,h1,l1; split2(v2,h0,l0); split2(v3,h1,l1);
                    *(__nv_bfloat162*)(pChi + (long)(rr+8)*ldc + cc) = __nv_bfloat162(h0, h1);
                    *(__nv_bfloat162*)(pClo + (long)(rr+8)*ldc + cc) = __nv_bfloat162(l0, l1);
                }
            }
        }
    }
}

// ---------------- binary head: 16 rows per block ----------------
__global__ void k_gbl_bin16(const float* __restrict__ A, const float* __restrict__ C,
                            const float* __restrict__ W, const float* __restrict__ bias,
                            float* __restrict__ out, int* __restrict__ mask)
{
    extern __shared__ float sm[];
    float* a_s = sm;
    float* c_s = sm + 16*772;
    int n0 = blockIdx.x * 16;
    int t = threadIdx.x;
    for (int idx = t; idx < 16*192; idx += 256) {
        int r = idx / 192, q = (idx % 192) * 4;
        *(float4*)&a_s[r*772 + q] = *(const float4*)(A + (long)(n0 + r)*Dq + q);
        *(float4*)&c_s[r*772 + q] = *(const float4*)(C + (long)(n0 + r)*Dq + q);
    }
    __syncthreads();
    int nl = t & 15, grp = t >> 4;
    float s0 = 0.f, s1 = 0.f;
    for (int s = 0; s < 48; s++) {
        int hi = grp*48 + s;
        float ai = a_s[nl*772 + hi];
        const float2* w2 = (const float2*)(W + (long)hi*BSq*2);
        const float* cc = c_s + nl*772 + (hi & ~63);
        #pragma unroll 8
        for (int j = 0; j < BSq; j++) {
            float v = ai * cc[j];
            float2 ww = w2[j];
            s0 += v*ww.x; s1 += v*ww.y;
        }
    }
    __shared__ float r0[16][17], r1[16][17];
    r0[grp][nl] = s0; r1[grp][nl] = s1;
    __syncthreads();
    if (t < 16) {
        float b0 = bias[0], b1 = bias[1];
        #pragma unroll
        for (int g = 0; g < 16; g++) { b0 += r0[g][t]; b1 += r1[g][t]; }
        int n = n0 + t;
        out[n*2] = b0; out[n*2+1] = b1;
        mask[n] = (b1 > b0) ? 1 : 0;
    }
}

__global__ void k_inc(const int* __restrict__ hts, int* __restrict__ inc)
{
    if (threadIdx.x == 0 && blockIdx.x == 0) {
        int cnt[NEq];
        for (int i = 0; i < NEq; i++) cnt[i] = 0;
        for (int p = 0; p < Pq; p++) {
            int d = hts[Pq + p];
            inc[d*23 + cnt[d]++] = p;
        }
    }
}

__global__ void k_f(const float* __restrict__ Ni, const float* __restrict__ Nj,
                    const float* __restrict__ EfW, const float* __restrict__ eb,
                    const int* __restrict__ hts, float* __restrict__ f)
{
    int be = blockIdx.x; int b = be / Eq, e = be % Eq;
    int src, dst; const float* ef = 0;
    if (e < Pq) { src = hts[e]; dst = hts[Pq + e]; ef = EfW + ((long)b*Pq + e)*Dq; }
    else        { src = dst = e - Pq; }
    const float* ni = Ni + ((long)b*NEq + src)*Dq;
    const float* nj = Nj + ((long)b*NEq + dst)*Dq;
    float* o = f + (long)be*Dq;
    for (int d = threadIdx.x; d < Dq; d += blockDim.x) {
        float v = ni[d] + nj[d] + eb[d];
        if (ef) v += ef[d];
        o[d] = v;
    }
}

__global__ void k_score(const float* __restrict__ f, const float* __restrict__ attn_p,
                        const int* __restrict__ mask, float* __restrict__ score)
{
    int be = blockIdx.x; int b = be / Eq, e = be % Eq;
    int h = threadIdx.x >> 5, lane = threadIdx.x & 31;
    const float* fr = f + (long)be*Dq + h*BSq;
    float s = 0.f;
    #pragma unroll
    for (int i = lane; i < BSq; i += 32) {
        float x = fr[i];
        float lr = x > 0.f ? x : 0.2f*x;
        s += lr * attn_p[h*BSq + i];
    }
    #pragma unroll
    for (int off = 16; off; off >>= 1) s += __shfl_xor_sync(0xffffffffu, s, off);
    if (lane == 0) {
        int m = (e < Pq) ? mask[b*Pq + e] : 1;
        score[(long)be*Hq + h] = m ? s : -1e30f;
    }
}

__global__ void k_soft(const float* __restrict__ score, const int* __restrict__ inc,
                       const int* __restrict__ mask, float* __restrict__ alpha)
{
    int bn = blockIdx.x; int b = bn / NEq, n = bn % NEq;
    int h = threadIdx.x >> 5, lane = threadIdx.x & 31;
    int eid = 0; float sc = -INFINITY; float m = 0.f;
    if (lane < 24) {
        eid = (lane < 23) ? inc[n*23 + lane] : (Pq + n);
        sc  = score[((long)b*Eq + eid)*Hq + h];
        m   = (eid < Pq) ? (float)mask[b*Pq + eid] : 1.f;
    }
    float mx = sc;
    #pragma unroll
    for (int off = 16; off; off >>= 1) mx = fmaxf(mx, __shfl_xor_sync(0xffffffffu, mx, off));
    float ex = (lane < 24) ? expf(sc - mx)*m : 0.f;
    float den = ex;
    #pragma unroll
    for (int off = 16; off; off >>= 1) den += __shfl_xor_sync(0xffffffffu, den, off);
    if (lane < 24) alpha[((long)b*Eq + eid)*Hq + h] = ex / (den + 1e-20f);
}

__global__ void k_nodeout(const float* __restrict__ alpha, const float* __restrict__ Hsrc,
                          const int* __restrict__ inc, const int* __restrict__ hts,
                          bf16* __restrict__ oh, bf16* __restrict__ ol)
{
    int bn = blockIdx.x; int b = bn / NEq, n = bn % NEq;
    __shared__ int   esrc[24];
    __shared__ float eal[24*Hq];
    int t = threadIdx.x;
    if (t < 24) {
        int eid = (t < 23) ? inc[n*23 + t] : (Pq + n);
        esrc[t] = (t < 23) ? hts[eid] : n;
    }
    for (int t2 = t; t2 < 24*Hq; t2 += blockDim.x) {
        int slot = t2 / Hq, hh = t2 % Hq;
        int eid = (slot < 23) ? inc[n*23 + slot] : (Pq + n);
        eal[t2] = alpha[((long)b*Eq + eid)*Hq + hh];
    }
    __syncthreads();
    for (int d = t; d < Dq; d += blockDim.x) {
        int h = d >> 6;
        float s = 0.f;
        #pragma unroll
        for (int slot = 0; slot < 24; slot++)
            s += eal[slot*Hq + h] * Hsrc[((long)b*NEq + esrc[slot])*Dq + d];
        bf16 hh, ll; split2(s, hh, ll);
        oh[(long)bn*Dq + d] = hh; ol[(long)bn*Dq + d] = ll;
    }
}

__global__ void k_newci(const int* __restrict__ mask, const float* __restrict__ f,
                        const float* __restrict__ ci, bf16* __restrict__ oh,
                        bf16* __restrict__ ol)
{
    long idx = (long)blockIdx.x*256 + threadIdx.x;
    int d = (int)(idx % Dq); long n = idx / Dq;
    int b = (int)(n / Pq), p = (int)(n % Pq);
    float v = mask[n] ? f[((long)b*Eq + p)*Dq + d] : ci[idx];
    bf16 h, l; split2(v, h, l);
    oh[idx] = h; ol[idx] = l;
}

__global__ void k_rel_reduce(const float* __restrict__ part, const float* __restrict__ brel,
                             float* __restrict__ out)
{
    long idx = (long)blockIdx.x*256 + threadIdx.x;
    if (idx >= (long)NPq*Rq) return;
    int o = (int)(idx % Rq);
    long n = idx / Rq;
    float s = brel[o];
    #pragma unroll
    for (int h = 0; h < 24; h++) s += part[((long)h*NPq + n)*128 + o];
    out[idx] = s;
}

// ---------------- host ----------------
template <typename T>
static T* sym(const void* s) { void* p = 0; cudaGetSymbolAddress(&p, s); return (T*)p; }

static void splitw(const float* src, bf16* hi, bf16* lo, long n)
{
    k_split<<<(int)((n + 255)/256), 256>>>(src, hi, lo, n);
}

extern "C" void kernel_launch(void* const* d_in, const int* in_sizes, int n_in,
                              void* d_out, int out_size)
{
    const float* ctx    = (const float*)d_in[0];
    const float* att    = (const float*)d_in[1];
    const int*   mm     = (const int*)  d_in[2];
    const float* em     = (const float*)d_in[3];
    const int*   hts    = (const int*)  d_in[4];
    const float* Whb    = (const float*)d_in[5];
    const float* bhb    = (const float*)d_in[6];
    const float* Wtb    = (const float*)d_in[7];
    const float* btb    = (const float*)d_in[8];
    const float* Wbin   = (const float*)d_in[9];
    const float* bbin   = (const float*)d_in[10];
    const float* Wrel   = (const float*)d_in[11];
    const float* brel   = (const float*)d_in[12];
    const float* Wh     = (const float*)d_in[13];
    const float* bh     = (const float*)d_in[14];
    const float* Wt     = (const float*)d_in[15];
    const float* bt     = (const float*)d_in[16];
    const float* Wnode  = (const float*)d_in[17];
    const float* Wni    = (const float*)d_in[18];
    const float* Wfij   = (const float*)d_in[19];
    const float* Wnj    = (const float*)d_in[20];
    const float* attn_p = (const float*)d_in[21];
    const float* egat_b = (const float*)d_in[22];

    float* outBin = (float*)d_out;
    float* outRel = outBin + (long)NPq*2;

    float* p_cur   = sym<float>(g_cur);
    float* p_ci    = sym<float>(g_ci);
    float* p_bh    = sym<float>(g_bh);
    float* p_bt    = sym<float>(g_bt);
    int*   p_mask  = sym<int>(g_mask);
    float* p_Ni    = sym<float>(g_Ni);
    float* p_Nj    = sym<float>(g_Nj);
    float* p_Hs    = sym<float>(g_Hs);
    float* p_EfW   = sym<float>(g_EfW);
    float* p_f     = sym<float>(g_f);
    float* p_score = sym<float>(g_score);
    float* p_alpha = sym<float>(g_alpha);
    float* p_rpart = sym<float>(g_relpart);
    int*   p_inc   = sym<int>(g_inc);
    float* p_Ebh   = sym<float>(g_Ebh);
    float* p_Ebt   = sym<float>(g_Ebt);
    float* p_Erh   = sym<float>(g_Erh);
    float* p_Ert   = sym<float>(g_Ert);

    bf16 *enth = sym<bf16>(g_enth), *entl = sym<bf16>(g_entl);
    bf16 *cah  = sym<bf16>(g_cah),  *cal  = sym<bf16>(g_cal);
    bf16 *cih  = sym<bf16>(g_cih),  *cil  = sym<bf16>(g_cil);
    bf16 *nouth= sym<bf16>(g_nouth),*noutl= sym<bf16>(g_noutl);
    bf16 *nch  = sym<bf16>(g_nch),  *ncl  = sym<bf16>(g_ncl);
    bf16 *ctxh = sym<bf16>(g_ctxh), *ctxl = sym<bf16>(g_ctxl);
    bf16 *Whbh = sym<bf16>(g_Whbh), *Whbl = sym<bf16>(g_Whbl);
    bf16 *Wtbh = sym<bf16>(g_Wtbh), *Wtbl = sym<bf16>(g_Wtbl);
    bf16 *Whh  = sym<bf16>(g_Whh),  *Whl  = sym<bf16>(g_Whl);
    bf16 *Wth  = sym<bf16>(g_Wth),  *Wtl  = sym<bf16>(g_Wtl);
    bf16 *Wfijh= sym<bf16>(g_Wfijh),*Wfijl= sym<bf16>(g_Wfijl);
    bf16 *Wnih = sym<bf16>(g_Wnih), *Wnil = sym<bf16>(g_Wnil);
    bf16 *Wnjh = sym<bf16>(g_Wnjh), *Wnjl = sym<bf16>(g_Wnjl);
    bf16 *Wnodeh=sym<bf16>(g_Wnodeh),*Wnodel=sym<bf16>(g_Wnodel);
    bf16 *Wpadh= sym<bf16>(g_Wpadh), *Wpadl= sym<bf16>(g_Wpadl);

    cudaFuncSetAttribute(k_mma<3>, cudaFuncAttributeMaxDynamicSharedMemorySize, 2*128*68*4);
    cudaFuncSetAttribute(k_gbl_bin16, cudaFuncAttributeMaxDynamicSharedMemorySize, 2*16*772*4);

    // ---- pooling + conversions ----
    k_entity<<<Bq*NEq, 256>>>(ctx, mm, em, enth, entl);
    k_cur<<<Bq*Hq*NEq, 256>>>(att, mm, em, p_cur);
    k_ca<<<Bq*Pq, 256>>>(p_cur, hts, cah, cal);
    splitw(ctx,   ctxh,  ctxl,  (long)Bq*Lq*Dq);
    splitw(Whb,   Whbh,  Whbl,  (long)2*Dq*Dq);
    splitw(Wtb,   Wtbh,  Wtbl,  (long)2*Dq*Dq);
    splitw(Wh,    Whh,   Whl,   (long)2*Dq*Dq);
    splitw(Wt,    Wth,   Wtl,   (long)2*Dq*Dq);
    splitw(Wfij,  Wfijh, Wfijl, (long)Dq*Dq);
    splitw(Wni,   Wnih,  Wnil,  (long)Dq*Dq);
    splitw(Wnj,   Wnjh,  Wnjl,  (long)Dq*Dq);
    splitw(Wnode, Wnodeh,Wnodel,(long)Dq*Dq);
    k_wpadsplit<<<(int)(((long)Hq*4096*128)/256), 256>>>(Wrel, Wpadh, Wpadl);
    k_inc<<<1, 32>>>(hts, p_inc);

    // ---- ci = ca @ ctx (batched over B), split output ----
    {
        GemmP g = {};
        for (int z = 0; z < Bq; z++) {
            g.Ah[z] = cah + (long)z*Pq*Lq;  g.Al[z] = cal + (long)z*Pq*Lq;
            g.Bh[z] = ctxh + (long)z*Lq*Dq; g.Bl[z] = ctxl + (long)z*Lq*Dq;
            g.C[z]  = p_ci + (long)z*Pq*Dq;
            g.Chi[z]= cih  + (long)z*Pq*Dq; g.Clo[z]= cil + (long)z*Pq*Dq;
            g.Mz[z] = Pq;
        }
        g.K = Lq; g.ldb = Dq; g.ldc = Dq; g.splitout = 1;
        k_mma<0><<<dim3(6, 5, 4), 256>>>(g);
    }

    // ---- Ebin = ent96 @ W_top ----
    {
        GemmP g = {};
        g.Ah[0] = enth; g.Al[0] = entl; g.Bh[0] = Whbh; g.Bl[0] = Whbl; g.C[0] = p_Ebh; g.Mz[0] = Bq*NEq;
        g.Ah[1] = enth; g.Al[1] = entl; g.Bh[1] = Wtbh; g.Bl[1] = Wtbl; g.C[1] = p_Ebt; g.Mz[1] = Bq*NEq;
        g.K = Dq; g.ldb = Dq; g.ldc = Dq;
        k_mma<0><<<dim3(6, 1, 2), 256>>>(g);
    }

    // ---- bin pair: tanh(ci @ W_bot + Ebin[ent] + bias) ----
    {
        GemmP g = {};
        g.Ah[0] = cih; g.Al[0] = cil; g.Bh[0] = Whbh + (long)Dq*Dq; g.Bl[0] = Whbl + (long)Dq*Dq;
        g.bias[0] = bhb; g.C[0] = p_bh; g.Eadd[0] = p_Ebh; g.Mz[0] = NPq;
        g.Ah[1] = cih; g.Al[1] = cil; g.Bh[1] = Wtbh + (long)Dq*Dq; g.Bl[1] = Wtbl + (long)Dq*Dq;
        g.bias[1] = btb; g.C[1] = p_bt; g.Eadd[1] = p_Ebt; g.Mz[1] = NPq;
        g.hts = hts; g.K = Dq; g.ldb = Dq; g.ldc = Dq; g.act = 1;
        k_mma<4><<<dim3(6, 18, 2), 256>>>(g);
    }
    k_gbl_bin16<<<NPq/16, 256, 2*16*772*4>>>(p_bh, p_bt, Wbin, bbin, outBin, p_mask);

    // ---- EGAT linear layers ----
    {
        GemmP g = {};
        g.Ah[0] = cih;  g.Al[0] = cil;  g.Bh[0] = Wfijh;  g.Bl[0] = Wfijl;  g.C[0] = p_EfW; g.Mz[0] = NPq;
        g.Ah[1] = enth; g.Al[1] = entl; g.Bh[1] = Wnih;   g.Bl[1] = Wnil;   g.C[1] = p_Ni;  g.Mz[1] = Bq*NEq;
        g.Ah[2] = enth; g.Al[2] = entl; g.Bh[2] = Wnjh;   g.Bl[2] = Wnjl;   g.C[2] = p_Nj;  g.Mz[2] = Bq*NEq;
        g.Ah[3] = enth; g.Al[3] = entl; g.Bh[3] = Wnodeh; g.Bl[3] = Wnodel; g.C[3] = p_Hs;  g.Mz[3] = Bq*NEq;
        g.K = Dq; g.ldb = Dq; g.ldc = Dq;
        k_mma<0><<<dim3(6, 18, 4), 256>>>(g);
    }
    k_f<<<Bq*Eq, 256>>>(p_Ni, p_Nj, p_EfW, egat_b, hts, p_f);
    k_score<<<Bq*Eq, 384>>>(p_f, attn_p, p_mask, p_score);
    k_soft<<<Bq*NEq, 384>>>(p_score, p_inc, p_mask, p_alpha);
    k_nodeout<<<Bq*NEq, 256>>>(p_alpha, p_Hs, p_inc, hts, nouth, noutl);

    // ---- relation head ----
    k_newci<<<NPq*Dq/256, 256>>>(p_mask, p_f, p_ci, nch, ncl);
    {
        GemmP g = {};
        g.Ah[0] = nouth; g.Al[0] = noutl; g.Bh[0] = Whh; g.Bl[0] = Whl; g.C[0] = p_Erh; g.Mz[0] = Bq*NEq;
        g.Ah[1] = nouth; g.Al[1] = noutl; g.Bh[1] = Wth; g.Bl[1] = Wtl; g.C[1] = p_Ert; g.Mz[1] = Bq*NEq;
        g.K = Dq; g.ldb = Dq; g.ldc = Dq;
        k_mma<0><<<dim3(6, 1, 2), 256>>>(g);
    }
    {
        GemmP g = {};
        g.Ah[0] = nch; g.Al[0] = ncl; g.Bh[0] = Whh + (long)Dq*Dq; g.Bl[0] = Whl + (long)Dq*Dq;
        g.bias[0] = bh; g.C[0] = p_bh; g.Eadd[0] = p_Erh; g.Mz[0] = NPq;
        g.Ah[1] = nch; g.Al[1] = ncl; g.Bh[1] = Wth + (long)Dq*Dq; g.Bl[1] = Wtl + (long)Dq*Dq;
        g.bias[1] = bt; g.C[1] = p_bt; g.Eadd[1] = p_Ert; g.Mz[1] = NPq;
        g.hts = hts; g.K = Dq; g.ldb = Dq; g.ldc = Dq; g.act = 1;
        k_mma<4><<<dim3(6, 18, 2), 256>>>(g);
    }
    // rel head: 24 = 12 heads x 2 K-splits; each block does K=2048 (64 chunks)
    {
        GemmP g = {};
        g.Bh[0] = Wpadh; g.Bl[0] = Wpadl;
        g.C[0] = p_rpart; g.Mz[0] = NPq;
        g.bhp = p_bh; g.btp = p_bt;
        g.sB = (long)4096*128; g.sC = (long)NPq*128;
        g.K = 2048; g.ldb = 128; g.ldc = 128;
        k_mma<3><<<dim3(1, 18, 24), 256, 2*128*68*4>>>(g);
    }
    k_rel_reduce<<<((long)NPq*Rq + 255)/256, 256>>>(p_rpart, brel, outRel);
}

// round 9
// speedup vs baseline: 2.7365x; 1.0411x over previous
#include <cuda_runtime.h>
#include <cuda_bf16.h>
#include <cuda_fp16.h>
#include <math.h>

#define Bq   4
#define Lq   1024
#define Dq   768
#define Hq   12
#define BSq  64
#define Mq   48
#define NEq  24
#define Pq   552
#define Eq   576
#define Rq   97
#define NPq  2208

typedef __nv_bfloat16 bf16;

// ---------------- scratch ----------------
__device__ float g_cur    [Bq*Hq*NEq*Lq];
__device__ float g_ci     [NPq*Dq];
__device__ float g_bh     [NPq*Dq];
__device__ float g_bt     [NPq*Dq];
__device__ int   g_mask   [NPq];
__device__ float g_Ni     [Bq*NEq*Dq];
__device__ float g_Nj     [Bq*NEq*Dq];
__device__ float g_Hs     [Bq*NEq*Dq];
__device__ float g_EfW    [NPq*Dq];
__device__ float g_f      [Bq*Eq*Dq];
__device__ float g_score  [Bq*Eq*Hq];
__device__ float g_alpha  [Bq*Eq*Hq];
__device__ float g_relpart[(size_t)24*NPq*128];
__device__ int   g_inc    [NEq*23];
__device__ float g_Ebh[96*Dq], g_Ebt[96*Dq], g_Erh[96*Dq], g_Ert[96*Dq];

__device__ bf16 g_enth[Bq*NEq*Dq],   g_entl[Bq*NEq*Dq];
__device__ bf16 g_cah [Bq*Pq*Lq],    g_cal [Bq*Pq*Lq];
__device__ bf16 g_cih [NPq*Dq],      g_cil [NPq*Dq];
__device__ bf16 g_nouth[Bq*NEq*Dq],  g_noutl[Bq*NEq*Dq];
__device__ bf16 g_nch[NPq*Dq],       g_ncl[NPq*Dq];
__device__ bf16 g_ctxh[Bq*Lq*Dq],    g_ctxl[Bq*Lq*Dq];
__device__ bf16 g_Whbh[2*Dq*Dq],     g_Whbl[2*Dq*Dq];
__device__ bf16 g_Wtbh[2*Dq*Dq],     g_Wtbl[2*Dq*Dq];
__device__ bf16 g_Whh [2*Dq*Dq],     g_Whl [2*Dq*Dq];
__device__ bf16 g_Wth [2*Dq*Dq],     g_Wtl [2*Dq*Dq];
__device__ bf16 g_Wfijh[Dq*Dq],      g_Wfijl[Dq*Dq];
__device__ bf16 g_Wnih[Dq*Dq],       g_Wnil[Dq*Dq];
__device__ bf16 g_Wnjh[Dq*Dq],       g_Wnjl[Dq*Dq];
__device__ bf16 g_Wnodeh[Dq*Dq],     g_Wnodel[Dq*Dq];
__device__ __half g_Wpadh[(size_t)Hq*4096*128], g_Wpadl[(size_t)Hq*4096*128];

// ---------------- helpers ----------------
__device__ __forceinline__ void split2(float x, bf16& h, bf16& l) {
    h = __float2bfloat16(x);
    l = __float2bfloat16(x - __bfloat162float(h));
}
__device__ __forceinline__ unsigned su32(const void* p) {
    return (unsigned)__cvta_generic_to_shared(p);
}
__device__ __forceinline__ void ldmx4(unsigned* r, unsigned a) {
    asm volatile("ldmatrix.sync.aligned.m8n8.x4.shared.b16 {%0,%1,%2,%3}, [%4];"
        : "=r"(r[0]), "=r"(r[1]), "=r"(r[2]), "=r"(r[3]) : "r"(a));
}
__device__ __forceinline__ void ldmx4t(unsigned* r, unsigned a) {
    asm volatile("ldmatrix.sync.aligned.m8n8.x4.trans.shared.b16 {%0,%1,%2,%3}, [%4];"
        : "=r"(r[0]), "=r"(r[1]), "=r"(r[2]), "=r"(r[3]) : "r"(a));
}
__device__ __forceinline__ void mma16816(float* c, const unsigned* a, const unsigned* b) {
    asm volatile("mma.sync.aligned.m16n8k16.row.col.f32.bf16.bf16.f32 "
        "{%0,%1,%2,%3}, {%4,%5,%6,%7}, {%8,%9}, {%0,%1,%2,%3};"
        : "+f"(c[0]), "+f"(c[1]), "+f"(c[2]), "+f"(c[3])
        : "r"(a[0]), "r"(a[1]), "r"(a[2]), "r"(a[3]), "r"(b[0]), "r"(b[1]));
}
__device__ __forceinline__ void mma16816f(float* c, const unsigned* a, const unsigned* b) {
    asm volatile("mma.sync.aligned.m16n8k16.row.col.f32.f16.f16.f32 "
        "{%0,%1,%2,%3}, {%4,%5,%6,%7}, {%8,%9}, {%0,%1,%2,%3};"
        : "+f"(c[0]), "+f"(c[1]), "+f"(c[2]), "+f"(c[3])
        : "r"(a[0]), "r"(a[1]), "r"(a[2]), "r"(a[3]), "r"(b[0]), "r"(b[1]));
}
__device__ __forceinline__ uint4 pack8h(const __half* x) {
    uint4 u;
    u.x = ((unsigned)__half_as_ushort(x[1]) << 16) | __half_as_ushort(x[0]);
    u.y = ((unsigned)__half_as_ushort(x[3]) << 16) | __half_as_ushort(x[2]);
    u.z = ((unsigned)__half_as_ushort(x[5]) << 16) | __half_as_ushort(x[4]);
    u.w = ((unsigned)__half_as_ushort(x[7]) << 16) | __half_as_ushort(x[6]);
    return u;
}

// ---------------- small kernels ----------------
__global__ void k_entity(const float* __restrict__ ctx, const int* __restrict__ mm,
                         const float* __restrict__ em,
                         bf16* __restrict__ oh, bf16* __restrict__ ol)
{
    int bn = blockIdx.x; int b = bn / NEq, n = bn % NEq;
    __shared__ float w_s[Mq]; __shared__ int mi_s[Mq];
    if (threadIdx.x < Mq) {
        w_s[threadIdx.x]  = em[(b*NEq + n)*Mq + threadIdx.x];
        mi_s[threadIdx.x] = mm[b*Mq + threadIdx.x];
    }
    __syncthreads();
    for (int d = threadIdx.x; d < Dq; d += blockDim.x) {
        float s = 0.f;
        #pragma unroll 4
        for (int m = 0; m < Mq; m++) {
            float w = w_s[m];
            if (w != 0.f) s += w * expf(ctx[((long)b*Lq + mi_s[m])*Dq + d]);
        }
        float v = logf(s);
        bf16 h, l; split2(v, h, l);
        oh[(long)bn*Dq + d] = h; ol[(long)bn*Dq + d] = l;
    }
}

__global__ void k_cur(const float* __restrict__ att, const int* __restrict__ mm,
                      const float* __restrict__ em, float* __restrict__ cur)
{
    int id = blockIdx.x;
    int n = id % NEq; int h = (id / NEq) % Hq; int b = id / (NEq*Hq);
    __shared__ int   act_m[Mq];
    __shared__ float act_w[Mq];
    __shared__ int   nact;
    __shared__ float invc;
    if (threadIdx.x == 0) {
        int c = 0; float cnt = 0.f;
        for (int m = 0; m < Mq; m++) {
            float w = em[(b*NEq + n)*Mq + m]; cnt += w;
            if (w != 0.f) { act_m[c] = mm[b*Mq + m]; act_w[c] = w; c++; }
        }
        nact = c; invc = 1.f / (cnt + 1e-20f);
    }
    __syncthreads();
    const float* abase = att + ((long)(b*Hq + h))*Lq*Lq;
    float* obase = cur + (long)id*Lq;
    int na = nact; float iv = invc;
    for (int l = threadIdx.x; l < Lq; l += blockDim.x) {
        float s = 0.f;
        for (int a = 0; a < na; a++) s += act_w[a] * abase[(long)act_m[a]*Lq + l];
        obase[l] = s * iv;
    }
}

__global__ void k_ca(const float* __restrict__ cur, const int* __restrict__ hts,
                     bf16* __restrict__ cah, bf16* __restrict__ cal)
{
    int bp = blockIdx.x; int b = bp / Pq, p = bp % Pq;
    int h0 = hts[p], h1 = hts[Pq + p];
    const float* c0 = cur + ((long)b*Hq*NEq + h0)*Lq;
    const float* c1 = cur + ((long)b*Hq*NEq + h1)*Lq;
    float v[4]; float local = 0.f;
    #pragma unroll
    for (int q = 0; q < 4; q++) {
        int l = threadIdx.x + q*256;
        float s = 0.f;
        #pragma unroll
        for (int h = 0; h < Hq; h++)
            s += c0[(long)h*NEq*Lq + l] * c1[(long)h*NEq*Lq + l];
        v[q] = s; local += s;
    }
    __shared__ float red[256];
    red[threadIdx.x] = local; __syncthreads();
    for (int off = 128; off > 0; off >>= 1) {
        if (threadIdx.x < off) red[threadIdx.x] += red[threadIdx.x + off];
        __syncthreads();
    }
    float inv = 1.f / (red[0] + 1e-20f);
    #pragma unroll
    for (int q = 0; q < 4; q++) {
        long o = (long)bp*Lq + threadIdx.x + q*256;
        bf16 h, l; split2(v[q]*inv, h, l);
        cah[o] = h; cal[o] = l;
    }
}

__global__ void k_split(const float* __restrict__ src, bf16* __restrict__ hi,
                        bf16* __restrict__ lo, long n)
{
    long i = (long)blockIdx.x*256 + threadIdx.x;
    if (i >= n) return;
    bf16 h, l; split2(src[i], h, l);
    hi[i] = h; lo[i] = l;
}

// batched 4-way weight split (grid.y selects table entry)
struct SplitP { const float* s[4]; bf16* h[4]; bf16* l[4]; };
__global__ void k_split4(SplitP p, long n)
{
    long i = (long)blockIdx.x*256 + threadIdx.x;
    if (i >= n) return;
    int z = blockIdx.y;
    float v = p.s[z][i];
    bf16 h, l; split2(v, h, l);
    p.h[z][i] = h; p.l[z][i] = l;
}

// Wrel [49152][97] -> padded fp16 split [12][4096][128]
__global__ void k_wpadsplit(const float* __restrict__ W, __half* __restrict__ Wh,
                            __half* __restrict__ Wl)
{
    long idx = (long)blockIdx.x*256 + threadIdx.x;
    int o = (int)(idx & 127);
    long row = idx >> 7;
    float v = (o < Rq) ? W[row*Rq + o] : 0.f;
    __half h = __float2half(v);
    __half l = __float2half(v - __half2float(h));
    Wh[idx] = h; Wl[idx] = l;
}

// ---------------- mma.sync GEMM ----------------
// MODE 0: A from table (bf16 3-term). MODE 3: rel head, fp16 2-term,
//   A generated = fp16(outer(bh,bt)), B = fp16 hi/lo Wrel, z = head*2+ksplit.
// MODE 4: A from table + gathered fp32 epilogue addend.
struct GemmP {
    const bf16 *Ah[4], *Al[4], *Bh[4], *Bl[4];
    const float* bias[4];
    float* C[4];
    bf16 *Chi[4], *Clo[4];
    const float* Eadd[4];
    int Mz[4];
    const int* hts;
    const float *bhp, *btp;
    long sB, sC;
    int K, ldb, ldc, act, splitout;
};

template<int MODE>
__global__ __launch_bounds__(256)
void k_mma(GemmP p)
{
    __shared__ bf16 Ash[128][40], Asl[128][40];
    __shared__ bf16 Bsh[32][136],  Bsl[32][136];
    extern __shared__ float dynf[];     // MODE 3: bhF[128*68], btF[128*68]
    float* bhF = dynf;
    float* btF = dynf + 128*68;

    int z = blockIdx.z;
    const bf16 *pBh, *pBl;
    const float* pbias = 0; float* pC;
    bf16 *pChi = 0, *pClo = 0;
    int M;
    const bf16 *tAh = 0, *tAl = 0;
    int h3 = 0, kcb = 0;
    if (MODE == 3) {
        h3 = z >> 1;
        kcb = (z & 1) * 64;                 // K-split: 64 of 128 32-wide chunks
        pBh = p.Bh[0] + (long)h3*p.sB;  pBl = p.Bl[0] + (long)h3*p.sB;
        pC  = p.C[0]  + (long)z*p.sC;
        M = p.Mz[0];
    } else {
        tAh = p.Ah[z]; tAl = p.Al[z];
        pBh = p.Bh[z]; pBl = p.Bl[z];
        pC  = p.C[z];  pbias = p.bias[z]; M = p.Mz[z];
        if (p.splitout) { pChi = p.Chi[z]; pClo = p.Clo[z]; }
    }
    int row0 = blockIdx.y * 128;
    if (row0 >= M) return;
    int col0 = blockIdx.x * 128;
    int K = p.K, ldb = p.ldb, ldc = p.ldc;
    int t = threadIdx.x;

    int arow = t >> 1;
    int ak   = (t & 1) * 16;
    int grow = row0 + arow;
    int rowc = grow < M ? grow : M - 1;
    const bf16 *srcAh0 = 0, *srcAl0 = 0;
    if (MODE != 3) {
        srcAh0 = tAh + (long)rowc*K;  srcAl0 = tAl + (long)rowc*K;
    }
    int bk = t >> 3;
    int bn = (t & 7) * 16;

    if (MODE == 3) {
        for (int idx = t; idx < 128*16; idx += 256) {
            int r = idx >> 4, q = (idx & 15) * 4;
            int rr = row0 + r; if (rr >= M) rr = M - 1;
            *(float4*)&bhF[r*68 + q] = *(const float4*)(p.bhp + (long)rr*Dq + h3*64 + q);
            *(float4*)&btF[r*68 + q] = *(const float4*)(p.btp + (long)rr*Dq + h3*64 + q);
        }
        __syncthreads();
    }

    uint4 vAh0, vAh1, vAl0, vAl1, vBh0, vBh1, vBl0, vBl1;

    #define LOAD_CHUNK(kc) do {                                                     \
        if (MODE == 3) {                                                            \
            int kk_ = (kc) + kcb;                                                   \
            int i_ = kk_ >> 1, j0_ = (kk_ & 1) * 32;                                \
            float a_ = bhF[arow*68 + i_];                                           \
            __half hh_[16];                                                         \
            _Pragma("unroll")                                                       \
            for (int q = 0; q < 16; q++)                                            \
                hh_[q] = __float2half(a_ * btF[arow*68 + j0_ + ak + q]);            \
            vAh0 = pack8h(hh_); vAh1 = pack8h(hh_ + 8);                             \
        } else {                                                                    \
            const bf16 *sh = srcAh0 + (kc)*32 + ak, *sl = srcAl0 + (kc)*32 + ak;    \
            vAh0 = *(const uint4*)sh;  vAh1 = *(const uint4*)(sh + 8);              \
            vAl0 = *(const uint4*)sl;  vAl1 = *(const uint4*)(sl + 8);              \
        }                                                                           \
        const bf16* bp_ = pBh + (long)(((kc) + kcb)*32 + bk)*ldb + col0 + bn;       \
        const bf16* bq_ = pBl + (long)(((kc) + kcb)*32 + bk)*ldb + col0 + bn;       \
        vBh0 = *(const uint4*)bp_;  vBh1 = *(const uint4*)(bp_ + 8);                \
        vBl0 = *(const uint4*)bq_;  vBl1 = *(const uint4*)(bq_ + 8);                \
    } while (0)

    LOAD_CHUNK(0);

    int w = t >> 5, lane = t & 31;
    // SMSP-balanced warp->tile map: each SMSP (w%4) gets one wn=0 and one wn=1 warp
    int wm = (w >> 1) & 3;
    int wn = (w & 1) ^ ((w >> 2) & 1);
    float acc[2][8][4] = {};

    int KT = K >> 5;
    for (int kc = 0; kc < KT; kc++) {
        *(uint4*)&Ash[arow][ak]     = vAh0;  *(uint4*)&Ash[arow][ak + 8] = vAh1;
        if (MODE != 3) {
            *(uint4*)&Asl[arow][ak] = vAl0;  *(uint4*)&Asl[arow][ak + 8] = vAl1;
        }
        *(uint4*)&Bsh[bk][bn]       = vBh0;  *(uint4*)&Bsh[bk][bn + 8]   = vBh1;
        *(uint4*)&Bsl[bk][bn]       = vBl0;  *(uint4*)&Bsl[bk][bn + 8]   = vBl1;
        __syncthreads();
        if (kc + 1 < KT) LOAD_CHUNK(kc + 1);

        #pragma unroll
        for (int s = 0; s < 2; s++) {
            unsigned ah[2][4], al[2][4];
            int arw = wm*32 + (lane & 15);
            int acl = s*16 + (lane >> 4)*8;
            ldmx4(ah[0], su32(&Ash[arw][acl]));
            ldmx4(ah[1], su32(&Ash[arw + 16][acl]));
            if (MODE != 3) {
                ldmx4(al[0], su32(&Asl[arw][acl]));
                ldmx4(al[1], su32(&Asl[arw + 16][acl]));
            }
            int brow = s*16 + ((lane >> 3) & 1)*8 + (lane & 7);
            int bcol = wn*64 + (lane >> 4)*8;
            #pragma unroll
            for (int g = 0; g < 4; g++) {
                // rel head N-trim: only cols < 104 matter (97 real + pad to 104)
                if (MODE == 3 && wn == 1 && g == 3) continue;
                unsigned bh_[4], bl_[4];
                ldmx4t(bh_, su32(&Bsh[brow][bcol + g*16]));
                ldmx4t(bl_, su32(&Bsl[brow][bcol + g*16]));
                #pragma unroll
                for (int mt = 0; mt < 2; mt++) {
                    if (MODE == 3) {
                        mma16816f(acc[mt][2*g],   ah[mt], bh_);
                        mma16816f(acc[mt][2*g],   ah[mt], bl_);
                        if (!(wn == 1 && g == 2)) {
                            mma16816f(acc[mt][2*g+1], ah[mt], bh_ + 2);
                            mma16816f(acc[mt][2*g+1], ah[mt], bl_ + 2);
                        }
                    } else {
                        mma16816(acc[mt][2*g],   ah[mt], bh_);
                        mma16816(acc[mt][2*g],   ah[mt], bl_);
                        mma16816(acc[mt][2*g],   al[mt], bh_);
                        mma16816(acc[mt][2*g+1], ah[mt], bh_ + 2);
                        mma16816(acc[mt][2*g+1], ah[mt], bl_ + 2);
                        mma16816(acc[mt][2*g+1], al[mt], bh_ + 2);
                    }
                }
            }
        }
        __syncthreads();
    }
    #undef LOAD_CHUNK

    int rg = row0 + wm*32 + (lane >> 2);
    int cb = col0 + wn*64 + (lane & 3)*2;
    const float* ea[2][2] = {};
    if (MODE == 4) {
        #pragma unroll
        for (int mt = 0; mt < 2; mt++)
            #pragma unroll
            for (int hf = 0; hf < 2; hf++) {
                int rr = rg + mt*16 + hf*8;
                if (rr < M) {
                    int b = rr / Pq, pp = rr % Pq;
                    ea[mt][hf] = p.Eadd[z] + ((long)(b*NEq) + p.hts[z*Pq + pp])*Dq;
                }
            }
    }
    #pragma unroll
    for (int mt = 0; mt < 2; mt++) {
        #pragma unroll
        for (int n8 = 0; n8 < 8; n8++) {
            int rr = rg + mt*16;
            int cc = cb + n8*8;
            float v0 = acc[mt][n8][0], v1 = acc[mt][n8][1];
            float v2 = acc[mt][n8][2], v3 = acc[mt][n8][3];
            if (MODE == 4) {
                if (ea[mt][0]) { v0 += ea[mt][0][cc]; v1 += ea[mt][0][cc+1]; }
                if (ea[mt][1]) { v2 += ea[mt][1][cc]; v3 += ea[mt][1][cc+1]; }
            }
            if (pbias) {
                float b0 = pbias[cc], b1 = pbias[cc+1];
                v0 += b0; v1 += b1; v2 += b0; v3 += b1;
            }
            if (p.act) { v0 = tanhf(v0); v1 = tanhf(v1); v2 = tanhf(v2); v3 = tanhf(v3); }
            if (rr < M) {
                *(float2*)(pC + (long)rr*ldc + cc) = make_float2(v0, v1);
                if (pChi) {
                    bf16 h0,l0,h1,l1; split2(v0,h0,l0); split2(v1,h1,l1);
                    *(__nv_bfloat162*)(pChi + (long)rr*ldc + cc) = __nv_bfloat162(h0, h1);
                    *(__nv_bfloat162*)(pClo + (long)rr*ldc + cc) = __nv_bfloat162(l0, l1);
                }
            }
            if (rr + 8 < M) {
                *(float2*)(pC + (long)(rr+8)*ldc + cc) = make_float2(v2, v3);
                if (pChi) {
                    bf16 h0,l0,h1,l1; split2(v2,h0,l0); split2(v3,h1,l1);
                    *(__nv_bfloat162*)(pChi + (long)(rr+8)*ldc + cc) = __nv_bfloat162(h0, h1);
                    *(__nv_bfloat162*)(pClo + (long)(rr+8)*ldc + cc) = __nv_bfloat162(l0, l1);
                }
            }
        }
    }
}

// ---------------- binary head: 16 rows per block ----------------
__global__ void k_gbl_bin16(const float* __restrict__ A, const float* __restrict__ C,
                            const float* __restrict__ W, const float* __restrict__ bias,
                            float* __restrict__ out, int* __restrict__ mask)
{
    extern __shared__ float sm[];
    float* a_s = sm;
    float* c_s = sm + 16*772;
    int n0 = blockIdx.x * 16;
    int t = threadIdx.x;
    for (int idx = t; idx < 16*192; idx += 256) {
        int r = idx / 192, q = (idx % 192) * 4;
        *(float4*)&a_s[r*772 + q] = *(const float4*)(A + (long)(n0 + r)*Dq + q);
        *(float4*)&c_s[r*772 + q] = *(const float4*)(C + (long)(n0 + r)*Dq + q);
    }
    __syncthreads();
    int nl = t & 15, grp = t >> 4;
    float s0 = 0.f, s1 = 0.f;
    for (int s = 0; s < 48; s++) {
        int hi = grp*48 + s;
        float ai = a_s[nl*772 + hi];
        const float2* w2 = (const float2*)(W + (long)hi*BSq*2);
        const float* cc = c_s + nl*772 + (hi & ~63);
        #pragma unroll 8
        for (int j = 0; j < BSq; j++) {
            float v = ai * cc[j];
            float2 ww = w2[j];
            s0 += v*ww.x; s1 += v*ww.y;
        }
    }
    __shared__ float r0[16][17], r1[16][17];
    r0[grp][nl] = s0; r1[grp][nl] = s1;
    __syncthreads();
    if (t < 16) {
        float b0 = bias[0], b1 = bias[1];
        #pragma unroll
        for (int g = 0; g < 16; g++) { b0 += r0[g][t]; b1 += r1[g][t]; }
        int n = n0 + t;
        out[n*2] = b0; out[n*2+1] = b1;
        mask[n] = (b1 > b0) ? 1 : 0;
    }
}

__global__ void k_inc(const int* __restrict__ hts, int* __restrict__ inc)
{
    if (threadIdx.x == 0 && blockIdx.x == 0) {
        int cnt[NEq];
        for (int i = 0; i < NEq; i++) cnt[i] = 0;
        for (int p = 0; p < Pq; p++) {
            int d = hts[Pq + p];
            inc[d*23 + cnt[d]++] = p;
        }
    }
}

__global__ void k_f(const float* __restrict__ Ni, const float* __restrict__ Nj,
                    const float* __restrict__ EfW, const float* __restrict__ eb,
                    const int* __restrict__ hts, float* __restrict__ f)
{
    int be = blockIdx.x; int b = be / Eq, e = be % Eq;
    int src, dst; const float* ef = 0;
    if (e < Pq) { src = hts[e]; dst = hts[Pq + e]; ef = EfW + ((long)b*Pq + e)*Dq; }
    else        { src = dst = e - Pq; }
    const float* ni = Ni + ((long)b*NEq + src)*Dq;
    const float* nj = Nj + ((long)b*NEq + dst)*Dq;
    float* o = f + (long)be*Dq;
    for (int d = threadIdx.x; d < Dq; d += blockDim.x) {
        float v = ni[d] + nj[d] + eb[d];
        if (ef) v += ef[d];
        o[d] = v;
    }
}

__global__ void k_score(const float* __restrict__ f, const float* __restrict__ attn_p,
                        const int* __restrict__ mask, float* __restrict__ score)
{
    int be = blockIdx.x; int b = be / Eq, e = be % Eq;
    int h = threadIdx.x >> 5, lane = threadIdx.x & 31;
    const float* fr = f + (long)be*Dq + h*BSq;
    float s = 0.f;
    #pragma unroll
    for (int i = lane; i < BSq; i += 32) {
        float x = fr[i];
        float lr = x > 0.f ? x : 0.2f*x;
        s += lr * attn_p[h*BSq + i];
    }
    #pragma unroll
    for (int off = 16; off; off >>= 1) s += __shfl_xor_sync(0xffffffffu, s, off);
    if (lane == 0) {
        int m = (e < Pq) ? mask[b*Pq + e] : 1;
        score[(long)be*Hq + h] = m ? s : -1e30f;
    }
}

__global__ void k_soft(const float* __restrict__ score, const int* __restrict__ inc,
                       const int* __restrict__ mask, float* __restrict__ alpha)
{
    int bn = blockIdx.x; int b = bn / NEq, n = bn % NEq;
    int h = threadIdx.x >> 5, lane = threadIdx.x & 31;
    int eid = 0; float sc = -INFINITY; float m = 0.f;
    if (lane < 24) {
        eid = (lane < 23) ? inc[n*23 + lane] : (Pq + n);
        sc  = score[((long)b*Eq + eid)*Hq + h];
        m   = (eid < Pq) ? (float)mask[b*Pq + eid] : 1.f;
    }
    float mx = sc;
    #pragma unroll
    for (int off = 16; off; off >>= 1) mx = fmaxf(mx, __shfl_xor_sync(0xffffffffu, mx, off));
    float ex = (lane < 24) ? expf(sc - mx)*m : 0.f;
    float den = ex;
    #pragma unroll
    for (int off = 16; off; off >>= 1) den += __shfl_xor_sync(0xffffffffu, den, off);
    if (lane < 24) alpha[((long)b*Eq + eid)*Hq + h] = ex / (den + 1e-20f);
}

__global__ void k_nodeout(const float* __restrict__ alpha, const float* __restrict__ Hsrc,
                          const int* __restrict__ inc, const int* __restrict__ hts,
                          bf16* __restrict__ oh, bf16* __restrict__ ol)
{
    int bn = blockIdx.x; int b = bn / NEq, n = bn % NEq;
    __shared__ int   esrc[24];
    __shared__ float eal[24*Hq];
    int t = threadIdx.x;
    if (t < 24) {
        int eid = (t < 23) ? inc[n*23 + t] : (Pq + n);
        esrc[t] = (t < 23) ? hts[eid] : n;
    }
    for (int t2 = t; t2 < 24*Hq; t2 += blockDim.x) {
        int slot = t2 / Hq, hh = t2 % Hq;
        int eid = (slot < 23) ? inc[n*23 + slot] : (Pq + n);
        eal[t2] = alpha[((long)b*Eq + eid)*Hq + hh];
    }
    __syncthreads();
    for (int d = t; d < Dq; d += blockDim.x) {
        int h = d >> 6;
        float s = 0.f;
        #pragma unroll
        for (int slot = 0; slot < 24; slot++)
            s += eal[slot*Hq + h] * Hsrc[((long)b*NEq + esrc[slot])*Dq + d];
        bf16 hh, ll; split2(s, hh, ll);
        oh[(long)bn*Dq + d] = hh; ol[(long)bn*Dq + d] = ll;
    }
}

__global__ void k_newci(const int* __restrict__ mask, const float* __restrict__ f,
                        const float* __restrict__ ci, bf16* __restrict__ oh,
                        bf16* __restrict__ ol)
{
    long idx = (long)blockIdx.x*256 + threadIdx.x;
    int d = (int)(idx % Dq); long n = idx / Dq;
    int b = (int)(n / Pq), p = (int)(n % Pq);
    float v = mask[n] ? f[((long)b*Eq + p)*Dq + d] : ci[idx];
    bf16 h, l; split2(v, h, l);
    oh[idx] = h; ol[idx] = l;
}

__global__ void k_rel_reduce(const float* __restrict__ part, const float* __restrict__ brel,
                             float* __restrict__ out)
{
    long idx = (long)blockIdx.x*256 + threadIdx.x;
    if (idx >= (long)NPq*Rq) return;
    int o = (int)(idx % Rq);
    long n = idx / Rq;
    float s = brel[o];
    #pragma unroll
    for (int h = 0; h < 24; h++) s += part[((long)h*NPq + n)*128 + o];
    out[idx] = s;
}

// ---------------- host ----------------
template <typename T>
static T* sym(const void* s) { void* p = 0; cudaGetSymbolAddress(&p, s); return (T*)p; }

extern "C" void kernel_launch(void* const* d_in, const int* in_sizes, int n_in,
                              void* d_out, int out_size)
{
    const float* ctx    = (const float*)d_in[0];
    const float* att    = (const float*)d_in[1];
    const int*   mm     = (const int*)  d_in[2];
    const float* em     = (const float*)d_in[3];
    const int*   hts    = (const int*)  d_in[4];
    const float* Whb    = (const float*)d_in[5];
    const float* bhb    = (const float*)d_in[6];
    const float* Wtb    = (const float*)d_in[7];
    const float* btb    = (const float*)d_in[8];
    const float* Wbin   = (const float*)d_in[9];
    const float* bbin   = (const float*)d_in[10];
    const float* Wrel   = (const float*)d_in[11];
    const float* brel   = (const float*)d_in[12];
    const float* Wh     = (const float*)d_in[13];
    const float* bh     = (const float*)d_in[14];
    const float* Wt     = (const float*)d_in[15];
    const float* bt     = (const float*)d_in[16];
    const float* Wnode  = (const float*)d_in[17];
    const float* Wni    = (const float*)d_in[18];
    const float* Wfij   = (const float*)d_in[19];
    const float* Wnj    = (const float*)d_in[20];
    const float* attn_p = (const float*)d_in[21];
    const float* egat_b = (const float*)d_in[22];

    float* outBin = (float*)d_out;
    float* outRel = outBin + (long)NPq*2;

    float* p_cur   = sym<float>(g_cur);
    float* p_ci    = sym<float>(g_ci);
    float* p_bh    = sym<float>(g_bh);
    float* p_bt    = sym<float>(g_bt);
    int*   p_mask  = sym<int>(g_mask);
    float* p_Ni    = sym<float>(g_Ni);
    float* p_Nj    = sym<float>(g_Nj);
    float* p_Hs    = sym<float>(g_Hs);
    float* p_EfW   = sym<float>(g_EfW);
    float* p_f     = sym<float>(g_f);
    float* p_score = sym<float>(g_score);
    float* p_alpha = sym<float>(g_alpha);
    float* p_rpart = sym<float>(g_relpart);
    int*   p_inc   = sym<int>(g_inc);
    float* p_Ebh   = sym<float>(g_Ebh);
    float* p_Ebt   = sym<float>(g_Ebt);
    float* p_Erh   = sym<float>(g_Erh);
    float* p_Ert   = sym<float>(g_Ert);

    bf16 *enth = sym<bf16>(g_enth), *entl = sym<bf16>(g_entl);
    bf16 *cah  = sym<bf16>(g_cah),  *cal  = sym<bf16>(g_cal);
    bf16 *cih  = sym<bf16>(g_cih),  *cil  = sym<bf16>(g_cil);
    bf16 *nouth= sym<bf16>(g_nouth),*noutl= sym<bf16>(g_noutl);
    bf16 *nch  = sym<bf16>(g_nch),  *ncl  = sym<bf16>(g_ncl);
    bf16 *ctxh = sym<bf16>(g_ctxh), *ctxl = sym<bf16>(g_ctxl);
    bf16 *Whbh = sym<bf16>(g_Whbh), *Whbl = sym<bf16>(g_Whbl);
    bf16 *Wtbh = sym<bf16>(g_Wtbh), *Wtbl = sym<bf16>(g_Wtbl);
    bf16 *Whh  = sym<bf16>(g_Whh),  *Whl  = sym<bf16>(g_Whl);
    bf16 *Wth  = sym<bf16>(g_Wth),  *Wtl  = sym<bf16>(g_Wtl);
    bf16 *Wfijh= sym<bf16>(g_Wfijh),*Wfijl= sym<bf16>(g_Wfijl);
    bf16 *Wnih = sym<bf16>(g_Wnih), *Wnil = sym<bf16>(g_Wnil);
    bf16 *Wnjh = sym<bf16>(g_Wnjh), *Wnjl = sym<bf16>(g_Wnjl);
    bf16 *Wnodeh=sym<bf16>(g_Wnodeh),*Wnodel=sym<bf16>(g_Wnodel);
    __half *Wpadh = sym<__half>(g_Wpadh), *Wpadl = sym<__half>(g_Wpadl);

    cudaFuncSetAttribute(k_mma<3>, cudaFuncAttributeMaxDynamicSharedMemorySize, 2*128*68*4);
    cudaFuncSetAttribute(k_gbl_bin16, cudaFuncAttributeMaxDynamicSharedMemorySize, 2*16*772*4);

    // ---- pooling + conversions ----
    k_entity<<<Bq*NEq, 256>>>(ctx, mm, em, enth, entl);
    k_cur<<<Bq*Hq*NEq, 256>>>(att, mm, em, p_cur);
    k_ca<<<Bq*Pq, 256>>>(p_cur, hts, cah, cal);
    k_split<<<(int)(((long)Bq*Lq*Dq + 255)/256), 256>>>(ctx, ctxh, ctxl, (long)Bq*Lq*Dq);
    {
        SplitP sp = {};
        sp.s[0] = Whb; sp.h[0] = Whbh; sp.l[0] = Whbl;
        sp.s[1] = Wtb; sp.h[1] = Wtbh; sp.l[1] = Wtbl;
        sp.s[2] = Wh;  sp.h[2] = Whh;  sp.l[2] = Whl;
        sp.s[3] = Wt;  sp.h[3] = Wth;  sp.l[3] = Wtl;
        k_split4<<<dim3((2*Dq*Dq + 255)/256, 4), 256>>>(sp, (long)2*Dq*Dq);
    }
    {
        SplitP sp = {};
        sp.s[0] = Wfij;  sp.h[0] = Wfijh;  sp.l[0] = Wfijl;
        sp.s[1] = Wni;   sp.h[1] = Wnih;   sp.l[1] = Wnil;
        sp.s[2] = Wnj;   sp.h[2] = Wnjh;   sp.l[2] = Wnjl;
        sp.s[3] = Wnode; sp.h[3] = Wnodeh; sp.l[3] = Wnodel;
        k_split4<<<dim3((Dq*Dq + 255)/256, 4), 256>>>(sp, (long)Dq*Dq);
    }
    k_wpadsplit<<<(int)(((long)Hq*4096*128)/256), 256>>>(Wrel, Wpadh, Wpadl);
    k_inc<<<1, 32>>>(hts, p_inc);

    // ---- ci = ca @ ctx (batched over B), split output ----
    {
        GemmP g = {};
        for (int z = 0; z < Bq; z++) {
            g.Ah[z] = cah + (long)z*Pq*Lq;  g.Al[z] = cal + (long)z*Pq*Lq;
            g.Bh[z] = ctxh + (long)z*Lq*Dq; g.Bl[z] = ctxl + (long)z*Lq*Dq;
            g.C[z]  = p_ci + (long)z*Pq*Dq;
            g.Chi[z]= cih  + (long)z*Pq*Dq; g.Clo[z]= cil + (long)z*Pq*Dq;
            g.Mz[z] = Pq;
        }
        g.K = Lq; g.ldb = Dq; g.ldc = Dq; g.splitout = 1;
        k_mma<0><<<dim3(6, 5, 4), 256>>>(g);
    }

    // ---- Ebin = ent96 @ W_top ----
    {
        GemmP g = {};
        g.Ah[0] = enth; g.Al[0] = entl; g.Bh[0] = Whbh; g.Bl[0] = Whbl; g.C[0] = p_Ebh; g.Mz[0] = Bq*NEq;
        g.Ah[1] = enth; g.Al[1] = entl; g.Bh[1] = Wtbh; g.Bl[1] = Wtbl; g.C[1] = p_Ebt; g.Mz[1] = Bq*NEq;
        g.K = Dq; g.ldb = Dq; g.ldc = Dq;
        k_mma<0><<<dim3(6, 1, 2), 256>>>(g);
    }

    // ---- bin pair: tanh(ci @ W_bot + Ebin[ent] + bias) ----
    {
        GemmP g = {};
        g.Ah[0] = cih; g.Al[0] = cil; g.Bh[0] = Whbh + (long)Dq*Dq; g.Bl[0] = Whbl + (long)Dq*Dq;
        g.bias[0] = bhb; g.C[0] = p_bh; g.Eadd[0] = p_Ebh; g.Mz[0] = NPq;
        g.Ah[1] = cih; g.Al[1] = cil; g.Bh[1] = Wtbh + (long)Dq*Dq; g.Bl[1] = Wtbl + (long)Dq*Dq;
        g.bias[1] = btb; g.C[1] = p_bt; g.Eadd[1] = p_Ebt; g.Mz[1] = NPq;
        g.hts = hts; g.K = Dq; g.ldb = Dq; g.ldc = Dq; g.act = 1;
        k_mma<4><<<dim3(6, 18, 2), 256>>>(g);
    }
    k_gbl_bin16<<<NPq/16, 256, 2*16*772*4>>>(p_bh, p_bt, Wbin, bbin, outBin, p_mask);

    // ---- EGAT linear layers ----
    {
        GemmP g = {};
        g.Ah[0] = cih;  g.Al[0] = cil;  g.Bh[0] = Wfijh;  g.Bl[0] = Wfijl;  g.C[0] = p_EfW; g.Mz[0] = NPq;
        g.Ah[1] = enth; g.Al[1] = entl; g.Bh[1] = Wnih;   g.Bl[1] = Wnil;   g.C[1] = p_Ni;  g.Mz[1] = Bq*NEq;
        g.Ah[2] = enth; g.Al[2] = entl; g.Bh[2] = Wnjh;   g.Bl[2] = Wnjl;   g.C[2] = p_Nj;  g.Mz[2] = Bq*NEq;
        g.Ah[3] = enth; g.Al[3] = entl; g.Bh[3] = Wnodeh; g.Bl[3] = Wnodel; g.C[3] = p_Hs;  g.Mz[3] = Bq*NEq;
        g.K = Dq; g.ldb = Dq; g.ldc = Dq;
        k_mma<0><<<dim3(6, 18, 4), 256>>>(g);
    }
    k_f<<<Bq*Eq, 256>>>(p_Ni, p_Nj, p_EfW, egat_b, hts, p_f);
    k_score<<<Bq*Eq, 384>>>(p_f, attn_p, p_mask, p_score);
    k_soft<<<Bq*NEq, 384>>>(p_score, p_inc, p_mask, p_alpha);
    k_nodeout<<<Bq*NEq, 256>>>(p_alpha, p_Hs, p_inc, hts, nouth, noutl);

    // ---- relation head ----
    k_newci<<<NPq*Dq/256, 256>>>(p_mask, p_f, p_ci, nch, ncl);
    {
        GemmP g = {};
        g.Ah[0] = nouth; g.Al[0] = noutl; g.Bh[0] = Whh; g.Bl[0] = Whl; g.C[0] = p_Erh; g.Mz[0] = Bq*NEq;
        g.Ah[1] = nouth; g.Al[1] = noutl; g.Bh[1] = Wth; g.Bl[1] = Wtl; g.C[1] = p_Ert; g.Mz[1] = Bq*NEq;
        g.K = Dq; g.ldb = Dq; g.ldc = Dq;
        k_mma<0><<<dim3(6, 1, 2), 256>>>(g);
    }
    {
        GemmP g = {};
        g.Ah[0] = nch; g.Al[0] = ncl; g.Bh[0] = Whh + (long)Dq*Dq; g.Bl[0] = Whl + (long)Dq*Dq;
        g.bias[0] = bh; g.C[0] = p_bh; g.Eadd[0] = p_Erh; g.Mz[0] = NPq;
        g.Ah[1] = nch; g.Al[1] = ncl; g.Bh[1] = Wth + (long)Dq*Dq; g.Bl[1] = Wtl + (long)Dq*Dq;
        g.bias[1] = bt; g.C[1] = p_bt; g.Eadd[1] = p_Ert; g.Mz[1] = NPq;
        g.hts = hts; g.K = Dq; g.ldb = Dq; g.ldc = Dq; g.act = 1;
        k_mma<4><<<dim3(6, 18, 2), 256>>>(g);
    }
    // rel head: 24 = 12 heads x 2 K-splits; fp16 2-term; each block K=2048
    {
        GemmP g = {};
        g.Bh[0] = (const bf16*)Wpadh; g.Bl[0] = (const bf16*)Wpadl;
        g.C[0] = p_rpart; g.Mz[0] = NPq;
        g.bhp = p_bh; g.btp = p_bt;
        g.sB = (long)4096*128; g.sC = (long)NPq*128;
        g.K = 2048; g.ldb = 128; g.ldc = 128;
        k_mma<3><<<dim3(1, 18, 24), 256, 2*128*68*4>>>(g);
    }
    k_rel_reduce<<<((long)NPq*Rq + 255)/256, 256>>>(p_rpart, brel, outRel);
}